// round 10
// baseline (speedup 1.0000x reference)
#include <cuda_runtime.h>
#include <cuda_bf16.h>
#include <math.h>
#include <stdint.h>

#define S_  2048
#define E_  2048
#define H_  16
#define QR_ 512
#define KVR_ 512
#define DR_ 64
#define DV_ 128
#define DQK_ 192   // DV + DR
#define NDWN 1088  // QR + KVR + DR
#define NQU  3072  // H*DV + H*DR

typedef __nv_bfloat16 bf16;

// ---------------- scratch (device globals) ----------------
__device__ float g_wd [NDWN * E_];          // concat [wq_down; wkv_down; wk_rope]
__device__ float g_wu [NQU * QR_];          // concat [wq_up; wq_rope]
__device__ float g_down[S_ * NDWN];         // [cq | ckv | kr] per row
__device__ float g_qu [S_ * NQU];           // [qc | qr] per row
__device__ float g_kv [S_ * (H_*2*DV_)];
__device__ bf16 g_wo_h[E_*H_*DV_], g_wo_l[E_*H_*DV_];
__device__ bf16 g_q[(size_t)H_ * S_ * DQK_];
__device__ bf16 g_k[(size_t)H_ * S_ * DQK_];
__device__ bf16 g_v[(size_t)H_ * S_ * DV_];
__device__ bf16 g_vT[(size_t)H_ * DV_ * S_];
__device__ bf16 g_logits[(size_t)H_ * S_ * S_];
__device__ bf16 g_probs [(size_t)H_ * S_ * S_];
__device__ bf16 g_attn_bf[(size_t)S_ * H_ * DV_];

// ---------------- helpers ----------------
__device__ __forceinline__ uint32_t f2tf32(float x) {
    uint32_t r;
    asm("cvt.rna.tf32.f32 %0, %1;" : "=r"(r) : "f"(x));
    return r;
}

#define MMA_TF32(c, a, b) \
    asm volatile( \
        "mma.sync.aligned.m16n8k8.row.col.f32.tf32.tf32.f32 " \
        "{%0,%1,%2,%3}, {%4,%5,%6,%7}, {%8,%9}, {%0,%1,%2,%3};" \
        : "+f"((c)[0]), "+f"((c)[1]), "+f"((c)[2]), "+f"((c)[3]) \
        : "r"((a)[0]), "r"((a)[1]), "r"((a)[2]), "r"((a)[3]), \
          "r"((b)[0]), "r"((b)[1]))

#define MMA_BF16(c, a, b) \
    asm volatile( \
        "mma.sync.aligned.m16n8k16.row.col.f32.bf16.bf16.f32 " \
        "{%0,%1,%2,%3}, {%4,%5,%6,%7}, {%8,%9}, {%0,%1,%2,%3};" \
        : "+f"((c)[0]), "+f"((c)[1]), "+f"((c)[2]), "+f"((c)[3]) \
        : "r"((a)[0]), "r"((a)[1]), "r"((a)[2]), "r"((a)[3]), \
          "r"((b)[0]), "r"((b)[1]))

#define CP16(dst, src, nbytes) \
    asm volatile("cp.async.cg.shared.global [%0], [%1], 16, %2;" \
                 :: "r"(dst), "l"(src), "r"(nbytes))
#define CP_COMMIT()  asm volatile("cp.async.commit_group;")
#define CP_WAIT0()   asm volatile("cp.async.wait_group 0;")

__global__ void split_bf_k(const float* __restrict__ src, bf16* __restrict__ hi,
                           bf16* __restrict__ lo, long n)
{
    long i = (long)blockIdx.x * blockDim.x + threadIdx.x;
    long stride = (long)gridDim.x * blockDim.x;
    for (; i < n; i += stride) {
        float v = src[i];
        bf16 h = __float2bfloat16(v);
        hi[i] = h;
        lo[i] = __float2bfloat16(v - __bfloat162float(h));
    }
}

// ============================================================================
// 3xTF32 GEMM, BM=64 tile, 3 CTAs/SM (launch_bounds), chunked-IEEE accumulation.
// Per-output math identical to R7/R9 -> bit-identical results.
// ============================================================================
#define FBM 64
#define FBN 128
#define FBK 16
#define FPAD 20

__global__ __launch_bounds__(256, 3)
void tf32_gemm(const float* __restrict__ A, const float* __restrict__ B,
               float* __restrict__ C, int M, int N, int K,
               long lda, long ldb, long ldc)
{
    constexpr int MT = 2;   // 2 * 16 rows per warp (32)
    constexpr int NT = 4;   // 4 * 8 cols per warp (32)

    __shared__ float sA[2][FBM * FPAD];
    __shared__ float sB[2][FBN * FPAD];

    const int m0 = blockIdx.y * FBM;
    const int n0 = blockIdx.x * FBN;
    const int tid = threadIdx.x;
    const int warp = tid >> 5;
    const int lane = tid & 31;
    const int gid = lane >> 2;
    const int tig = lane & 3;
    const int wm = (warp & 1) * 32;
    const int wn = (warp >> 1) * 32;

    const float* aSrc;
    uint32_t aOff;
    const float* bSrc[2];
    uint32_t bOff[2];
    int bPred[2];
    const uint32_t saBase = (uint32_t)__cvta_generic_to_shared(sA);
    const uint32_t sbBase = (uint32_t)__cvta_generic_to_shared(sB);
    {
        int row = tid >> 2, ch = tid & 3;
        aSrc = A + (long)(m0 + row) * lda + ch * 4;
        aOff = (uint32_t)(row * FPAD + ch * 4) * 4u;
    }
#pragma unroll
    for (int it = 0; it < 2; it++) {
        int idx = tid + it * 256;
        int row = idx >> 2, ch = idx & 3;
        int nrow = n0 + row;
        bPred[it] = (nrow < N) ? 16 : 0;
        if (nrow >= N) nrow = N - 1;
        bSrc[it] = B + (long)nrow * ldb + ch * 4;
        bOff[it] = (uint32_t)(row * FPAD + ch * 4) * 4u;
    }
    const uint32_t ABUF = FBM * FPAD * 4u;
    const uint32_t BBUF = FBN * FPAD * 4u;

    float acc[MT][NT][4];
#pragma unroll
    for (int mt = 0; mt < MT; mt++)
#pragma unroll
        for (int nt = 0; nt < NT; nt++)
#pragma unroll
            for (int r = 0; r < 4; r++) acc[mt][nt][r] = 0.f;

    const int NTILES = K / FBK;

    CP16(saBase + aOff, aSrc, 16);
#pragma unroll
    for (int it = 0; it < 2; it++) CP16(sbBase + bOff[it], bSrc[it], bPred[it]);
    CP_COMMIT();

    for (int t = 0; t < NTILES; t++) {
        const int cur = t & 1;
        CP_WAIT0();
        __syncthreads();

        if (t + 1 < NTILES) {
            const long kk = (long)(t + 1) * FBK;
            CP16(saBase + (cur ^ 1) * ABUF + aOff, aSrc + kk, 16);
#pragma unroll
            for (int it = 0; it < 2; it++)
                CP16(sbBase + (cur ^ 1) * BBUF + bOff[it], bSrc[it] + kk, bPred[it]);
            CP_COMMIT();
        }

        const float* cA = sA[cur];
        const float* cB = sB[cur];

        uint32_t ah[2][MT][4], al[2][MT][4];
#pragma unroll
        for (int ks = 0; ks < 2; ks++)
#pragma unroll
            for (int mt = 0; mt < MT; mt++)
#pragma unroll
                for (int r = 0; r < 4; r++) {
                    int row = wm + mt * 16 + gid + (r & 1) * 8;
                    int col = ks * 8 + tig + (r >> 1) * 4;
                    float v = cA[row * FPAD + col];
                    uint32_t h = f2tf32(v);
                    ah[ks][mt][r] = h;
                    al[ks][mt][r] = f2tf32(v - __uint_as_float(h));
                }

#pragma unroll
        for (int nt = 0; nt < NT; nt++) {
            uint32_t bh[2][2], bl[2][2];
#pragma unroll
            for (int ks = 0; ks < 2; ks++)
#pragma unroll
                for (int r = 0; r < 2; r++) {
                    int n = wn + nt * 8 + gid;
                    int kq = ks * 8 + tig + r * 4;
                    float v = cB[n * FPAD + kq];
                    uint32_t h = f2tf32(v);
                    bh[ks][r] = h;
                    bl[ks][r] = f2tf32(v - __uint_as_float(h));
                }
#pragma unroll
            for (int mt = 0; mt < MT; mt++) {
                float f[4] = {0.f, 0.f, 0.f, 0.f};
#pragma unroll
                for (int ks = 0; ks < 2; ks++) {
                    MMA_TF32(f, ah[ks][mt], bh[ks]);
                    MMA_TF32(f, ah[ks][mt], bl[ks]);
                    MMA_TF32(f, al[ks][mt], bh[ks]);
                }
                float* c = acc[mt][nt];
                c[0] += f[0]; c[1] += f[1]; c[2] += f[2]; c[3] += f[3];
            }
        }
    }

#pragma unroll
    for (int mt = 0; mt < MT; mt++) {
        int row0 = m0 + wm + mt * 16 + gid;
#pragma unroll
        for (int nt = 0; nt < NT; nt++) {
            int n = n0 + wn + nt * 8 + tig * 2;
            if (n >= N) continue;
            float* c = acc[mt][nt];
            C[(long)row0 * ldc + n]         = c[0];
            C[(long)row0 * ldc + n + 1]     = c[1];
            C[(long)(row0+8) * ldc + n]     = c[2];
            C[(long)(row0+8) * ldc + n + 1] = c[3];
        }
    }
}

// ============================================================================
// bf16 tensor-core GEMM (unchanged from R7/R9)
// ============================================================================
#define TBM 128
#define TBN 128
#define TBK 32
#define PADK 40

template <typename TC>
__global__ __launch_bounds__(256)
void bf16_gemm(const bf16* __restrict__ A0, const bf16* __restrict__ A1,
               const bf16* __restrict__ B0, const bf16* __restrict__ B1,
               TC* __restrict__ C, int npass, int M, int N, int K,
               long lda, long ldb, long ldc, long Abat, long Bbat, long Cbat)
{
    __shared__ bf16 sA[2][TBM * PADK];
    __shared__ bf16 sB[2][TBN * PADK];

    const long zo = blockIdx.z;
    C += zo * Cbat;

    const int m0 = blockIdx.y * TBM;
    const int n0 = blockIdx.x * TBN;
    const int tid = threadIdx.x;
    const int warp = tid >> 5;
    const int lane = tid & 31;
    const int gid = lane >> 2;
    const int tig = lane & 3;
    const int wm = (warp >> 1) * 32;
    const int wn = (warp & 1) * 64;

    const uint32_t saBase = (uint32_t)__cvta_generic_to_shared(sA);
    const uint32_t sbBase = (uint32_t)__cvta_generic_to_shared(sB);
    const uint32_t ABUF = TBM * PADK * 2u;

    float acc[2][8][4];
#pragma unroll
    for (int mt = 0; mt < 2; mt++)
#pragma unroll
        for (int nt = 0; nt < 8; nt++)
#pragma unroll
            for (int r = 0; r < 4; r++) acc[mt][nt][r] = 0.f;

    const int NT = K / TBK;

    for (int p = 0; p < npass; p++) {
        const bf16* A = (p ? A1 : A0) + zo * Abat;
        const bf16* B = (p ? B1 : B0) + zo * Bbat;

        const bf16* aSrc[2];
        const bf16* bSrc[2];
        uint32_t sOff[2];
        int bPred[2];
#pragma unroll
        for (int it = 0; it < 2; it++) {
            int idx = tid + it * 256;
            int row = idx >> 2, ch = idx & 3;
            aSrc[it] = A + (long)(m0 + row) * lda + ch * 8;
            int nrow = n0 + row;
            bPred[it] = (nrow < N) ? 16 : 0;
            if (nrow >= N) nrow = N - 1;
            bSrc[it] = B + (long)nrow * ldb + ch * 8;
            sOff[it] = (uint32_t)(row * PADK + ch * 8) * 2u;
        }

        if (p) __syncthreads();

#pragma unroll
        for (int it = 0; it < 2; it++) {
            CP16(saBase + sOff[it], aSrc[it], 16);
            CP16(sbBase + sOff[it], bSrc[it], bPred[it]);
        }
        CP_COMMIT();

        for (int t = 0; t < NT; t++) {
            const int cur = t & 1;
            CP_WAIT0();
            __syncthreads();

            if (t + 1 < NT) {
                const long kk = (long)(t + 1) * TBK;
                const uint32_t bo = (cur ^ 1) * ABUF;
#pragma unroll
                for (int it = 0; it < 2; it++) {
                    CP16(saBase + bo + sOff[it], aSrc[it] + kk, 16);
                    CP16(sbBase + bo + sOff[it], bSrc[it] + kk, bPred[it]);
                }
                CP_COMMIT();
            }

            const bf16* cA = sA[cur];
            const bf16* cB = sB[cur];

            uint32_t a[2][2][4];
#pragma unroll
            for (int ks = 0; ks < 2; ks++)
#pragma unroll
                for (int mt = 0; mt < 2; mt++)
#pragma unroll
                    for (int r = 0; r < 4; r++) {
                        int row = wm + mt * 16 + gid + (r & 1) * 8;
                        int col = ks * 16 + tig * 2 + (r >> 1) * 8;
                        a[ks][mt][r] = *(const uint32_t*)&cA[row * PADK + col];
                    }

#pragma unroll
            for (int nt = 0; nt < 8; nt++) {
                uint32_t b[2][2];
#pragma unroll
                for (int ks = 0; ks < 2; ks++)
#pragma unroll
                    for (int r = 0; r < 2; r++) {
                        int n  = wn + nt * 8 + gid;
                        int kq = ks * 16 + tig * 2 + r * 8;
                        b[ks][r] = *(const uint32_t*)&cB[n * PADK + kq];
                    }
#pragma unroll
                for (int mt = 0; mt < 2; mt++) {
                    float f[4] = {0.f, 0.f, 0.f, 0.f};
                    MMA_BF16(f, a[0][mt], b[0]);
                    MMA_BF16(f, a[1][mt], b[1]);
                    float* c = acc[mt][nt];
                    c[0] += f[0]; c[1] += f[1]; c[2] += f[2]; c[3] += f[3];
                }
            }
        }
    }

#pragma unroll
    for (int mt = 0; mt < 2; mt++) {
        int row0 = m0 + wm + mt * 16 + gid;
#pragma unroll
        for (int nt = 0; nt < 8; nt++) {
            int n = n0 + wn + nt * 8 + tig * 2;
            if (n >= N) continue;
            float* c = acc[mt][nt];
            if (sizeof(TC) == 4) {
                float* Cf = (float*)C;
                Cf[(long)row0 * ldc + n]         = c[0];
                Cf[(long)row0 * ldc + n + 1]     = c[1];
                Cf[(long)(row0+8) * ldc + n]     = c[2];
                Cf[(long)(row0+8) * ldc + n + 1] = c[3];
            } else {
                bf16* Cb = (bf16*)C;
                *(__nv_bfloat162*)&Cb[(long)row0 * ldc + n] =
                    __nv_bfloat162(__float2bfloat16(c[0]), __float2bfloat16(c[1]));
                *(__nv_bfloat162*)&Cb[(long)(row0+8) * ldc + n] =
                    __nv_bfloat162(__float2bfloat16(c[2]), __float2bfloat16(c[3]));
            }
        }
    }
}

// ---------------- pack q/k/v (bf16, head-major) + RoPE ----------------
__global__ void pack_k(const float* __restrict__ qu, const float* __restrict__ kvf,
                       const float* __restrict__ dwn,
                       bf16* __restrict__ q, bf16* __restrict__ k, bf16* __restrict__ v)
{
    const int s = blockIdx.x;
    const int tid = threadIdx.x;  // 256

    __shared__ float ssin[32], scos[32];
    if (tid < 32) {
        double invf_d = pow(10000.0, -((double)(2 * tid)) / 64.0);
        float invf = (float)invf_d;
        float ang = (float)s * invf;
        double a = (double)ang;
        ssin[tid] = (float)sin(a);
        scos[tid] = (float)cos(a);
    }
    __syncthreads();

    for (int idx = tid; idx < H_ * DV_; idx += 256) {
        int h = idx >> 7, d = idx & 127;
        q[((long)h * S_ + s) * DQK_ + d] = __float2bfloat16(qu[(long)s * NQU + idx]);
        k[((long)h * S_ + s) * DQK_ + d] = __float2bfloat16(kvf[(long)s * (H_*2*DV_) + idx]);
        v[((long)h * S_ + s) * DV_ + d]  = __float2bfloat16(kvf[(long)s * (H_*2*DV_) + H_*DV_ + idx]);
    }

    for (int idx = tid; idx < H_ * 32; idx += 256) {
        int h = idx >> 5, j = idx & 31;
        float x1 = qu[(long)s * NQU + 2048 + h * DR_ + j];
        float x2 = qu[(long)s * NQU + 2048 + h * DR_ + 32 + j];
        float sn = ssin[j], cs = scos[j];
        q[((long)h * S_ + s) * DQK_ + DV_ + j]      = __float2bfloat16(x1 * cs - x2 * sn);
        q[((long)h * S_ + s) * DQK_ + DV_ + 32 + j] = __float2bfloat16(x2 * cs + x1 * sn);
    }

    if (tid < 32) {
        int j = tid;
        float x1 = dwn[(long)s * NDWN + 1024 + j];
        float x2 = dwn[(long)s * NDWN + 1024 + 32 + j];
        float sn = ssin[j], cs = scos[j];
        float r1 = x1 * cs - x2 * sn;
        float r2 = x2 * cs + x1 * sn;
#pragma unroll
        for (int h = 0; h < H_; h++) {
            k[((long)h * S_ + s) * DQK_ + DV_ + j]      = __float2bfloat16(r1);
            k[((long)h * S_ + s) * DQK_ + DV_ + 32 + j] = __float2bfloat16(r2);
        }
    }
}

// ---------------- transpose v [h][s][d] -> vT [h][d][s] ----------------
__global__ void transpose_v(const bf16* __restrict__ v, bf16* __restrict__ vT)
{
    __shared__ bf16 t[32][33];
    const int h = blockIdx.z;
    const int s0 = blockIdx.x * 32;
    const int d0 = blockIdx.y * 32;
    const int tx = threadIdx.x, ty = threadIdx.y;  // (32, 8)
#pragma unroll
    for (int j = 0; j < 32; j += 8)
        t[ty + j][tx] = v[((long)h * S_ + s0 + ty + j) * DV_ + d0 + tx];
    __syncthreads();
#pragma unroll
    for (int j = 0; j < 32; j += 8)
        vT[((long)h * DV_ + d0 + ty + j) * S_ + s0 + tx] = t[tx][ty + j];
}

// ---------------- softmax over bf16 logits -> bf16 probs ----------------
__global__ void softmax_k(const bf16* __restrict__ L, bf16* __restrict__ P, float scale)
{
    const int s = blockIdx.x;
    const int h = blockIdx.y;
    const bf16* row = L + ((long)h * S_ + s) * S_;
    bf16* prow = P + ((long)h * S_ + s) * S_;
    const int tid = threadIdx.x;

    float v[8];
    float mx = -1e30f;
#pragma unroll
    for (int i = 0; i < 8; i++) {
        v[i] = __bfloat162float(row[tid + i * 256]) * scale;
        mx = fmaxf(mx, v[i]);
    }
    __shared__ float red[256];
    red[tid] = mx;
    __syncthreads();
    for (int st = 128; st > 0; st >>= 1) {
        if (tid < st) red[tid] = fmaxf(red[tid], red[tid + st]);
        __syncthreads();
    }
    mx = red[0];
    __syncthreads();

    float sum = 0.f;
#pragma unroll
    for (int i = 0; i < 8; i++) {
        v[i] = expf(v[i] - mx);
        sum += v[i];
    }
    red[tid] = sum;
    __syncthreads();
    for (int st = 128; st > 0; st >>= 1) {
        if (tid < st) red[tid] += red[tid + st];
        __syncthreads();
    }
    float tot = red[0];
#pragma unroll
    for (int i = 0; i < 8; i++)
        prow[tid + i * 256] = __float2bfloat16(v[i] / tot);
}

// ---------------- orchestration ----------------
extern "C" void kernel_launch(void* const* d_in, const int* in_sizes, int n_in,
                              void* d_out, int out_size)
{
    (void)in_sizes; (void)n_in; (void)out_size;
    const float* x       = (const float*)d_in[0];
    const float* wq_down = (const float*)d_in[1];
    const float* wq_up   = (const float*)d_in[2];
    const float* wq_rope = (const float*)d_in[3];
    const float* wkv_down= (const float*)d_in[4];
    const float* wkv_up  = (const float*)d_in[5];
    const float* wk_rope = (const float*)d_in[6];
    const float* wo      = (const float*)d_in[7];
    float* out = (float*)d_out;

    float *wd, *wu, *dwn, *qu, *kvf;
    cudaGetSymbolAddress((void**)&wd,  g_wd);
    cudaGetSymbolAddress((void**)&wu,  g_wu);
    cudaGetSymbolAddress((void**)&dwn, g_down);
    cudaGetSymbolAddress((void**)&qu,  g_qu);
    cudaGetSymbolAddress((void**)&kvf, g_kv);

    bf16 *q, *k, *v, *vT, *logits, *probs, *attn_bf, *wo_h, *wo_l;
    cudaGetSymbolAddress((void**)&q, g_q);
    cudaGetSymbolAddress((void**)&k, g_k);
    cudaGetSymbolAddress((void**)&v, g_v);
    cudaGetSymbolAddress((void**)&vT, g_vT);
    cudaGetSymbolAddress((void**)&logits, g_logits);
    cudaGetSymbolAddress((void**)&probs, g_probs);
    cudaGetSymbolAddress((void**)&attn_bf, g_attn_bf);
    cudaGetSymbolAddress((void**)&wo_h, g_wo_h);
    cudaGetSymbolAddress((void**)&wo_l, g_wo_l);

    dim3 blk(256);
    auto fgrid = [](int M, int N) {
        return dim3((N + FBN - 1) / FBN, (M + FBM - 1) / FBM, 1);
    };
    auto bgrid = [](int M, int N, int batch) {
        return dim3((N + TBN - 1) / TBN, (M + TBM - 1) / TBM, batch);
    };

    // 0) concat weights (D2D, graph-capturable) + wo bf16 split
    cudaMemcpyAsync(wd,                 wq_down,  (size_t)QR_ * E_ * 4, cudaMemcpyDeviceToDevice);
    cudaMemcpyAsync(wd + (size_t)QR_*E_, wkv_down, (size_t)KVR_ * E_ * 4, cudaMemcpyDeviceToDevice);
    cudaMemcpyAsync(wd + (size_t)(QR_+KVR_)*E_, wk_rope, (size_t)DR_ * E_ * 4, cudaMemcpyDeviceToDevice);
    cudaMemcpyAsync(wu,                  wq_up,   (size_t)H_*DV_ * QR_ * 4, cudaMemcpyDeviceToDevice);
    cudaMemcpyAsync(wu + (size_t)H_*DV_*QR_, wq_rope, (size_t)H_*DR_ * QR_ * 4, cudaMemcpyDeviceToDevice);
    split_bf_k<<<592, 256>>>(wo, wo_h, wo_l, (long)E_*H_*DV_);

    // 1) fused down projection: [cq|ckv|kr] = x @ wd^T   (N=1088, 9x32=288 CTAs)
    tf32_gemm<<<fgrid(S_, NDWN), blk>>>(x, wd, dwn, S_, NDWN, E_, E_, E_, NDWN);

    // 2) fused q up projection: [qc|qr] = cq @ wu^T  (24x32 = 768 CTAs)
    tf32_gemm<<<fgrid(S_, NQU), blk>>>(dwn, wu, qu, S_, NQU, QR_, NDWN, QR_, NQU);
    // kv up: ckv @ wkv_up^T  (32x32 = 1024 CTAs)
    tf32_gemm<<<fgrid(S_, H_*2*DV_), blk>>>(dwn + QR_, wkv_up, kvf, S_, H_*2*DV_, KVR_,
                                            NDWN, KVR_, H_*2*DV_);

    // 3) pack + rope -> head-major bf16 q/k/v ; transpose v
    pack_k<<<S_, 256>>>(qu, kvf, dwn, q, k, v);
    {
        dim3 tg(S_/32, DV_/32, H_);
        dim3 tb(32, 8);
        transpose_v<<<tg, tb>>>(v, vT);
    }

    // 4) logits[h] = bf16( q[h] @ k[h]^T )
    bf16_gemm<bf16><<<bgrid(S_, S_, H_), blk>>>(
        q, q, k, k, logits, 1, S_, S_, DQK_, DQK_, DQK_, S_,
        (long)S_*DQK_, (long)S_*DQK_, (long)S_*S_);

    // 5) softmax
    {
        dim3 g(S_, H_);
        softmax_k<<<g, 256>>>(logits, probs, 1.0f / sqrtf((float)(DV_ + DR_)));
    }

    // 6) attn[h] = bf16( probs[h] @ v[h] ), stored bf16 interleaved [s][h*DV]
    bf16_gemm<bf16><<<bgrid(S_, DV_, H_), blk>>>(
        probs, probs, vT, vT, attn_bf, 1, S_, DV_, S_, S_, S_, (long)H_*DV_,
        (long)S_*S_, (long)DV_*S_, DV_);

    // 7) out = attn(bf16-exact) @ wo^T : 2-pass bf16 (wo = hi + lo)
    bf16_gemm<float><<<bgrid(S_, E_, 1), blk>>>(
        attn_bf, attn_bf, wo_h, wo_l, out, 2, S_, E_, H_*DV_,
        H_*DV_, H_*DV_, E_, 0, 0, 0);
}

// round 11
// speedup vs baseline: 1.1936x; 1.1936x over previous
#include <cuda_runtime.h>
#include <cuda_bf16.h>
#include <math.h>
#include <stdint.h>

#define S_  2048
#define E_  2048
#define H_  16
#define QR_ 512
#define KVR_ 512
#define DR_ 64
#define DV_ 128
#define DQK_ 192   // DV + DR
#define NDWN 1088  // QR + KVR + DR
#define NQU  3072  // H*DV + H*DR

typedef __nv_bfloat16 bf16;

// ---------------- scratch (device globals) ----------------
__device__ float g_wd [NDWN * E_];
__device__ float g_wu [NQU * QR_];
__device__ float g_down[S_ * NDWN];
__device__ float g_qu [S_ * NQU];
__device__ float g_kv [S_ * (H_*2*DV_)];
__device__ bf16 g_wo_h[E_*H_*DV_], g_wo_l[E_*H_*DV_];
__device__ bf16 g_q[(size_t)H_ * S_ * DQK_];
__device__ bf16 g_k[(size_t)H_ * S_ * DQK_];
__device__ bf16 g_v[(size_t)H_ * S_ * DV_];
__device__ bf16 g_vT[(size_t)H_ * DV_ * S_];
__device__ bf16 g_logits[(size_t)H_ * S_ * S_];
__device__ bf16 g_probs [(size_t)H_ * S_ * S_];
__device__ bf16 g_attn_bf[(size_t)S_ * H_ * DV_];

// ---------------- helpers ----------------
__device__ __forceinline__ uint32_t f2tf32(float x) {
    uint32_t r;
    asm("cvt.rna.tf32.f32 %0, %1;" : "=r"(r) : "f"(x));
    return r;
}

#define MMA_TF32(c, a, b) \
    asm volatile( \
        "mma.sync.aligned.m16n8k8.row.col.f32.tf32.tf32.f32 " \
        "{%0,%1,%2,%3}, {%4,%5,%6,%7}, {%8,%9}, {%0,%1,%2,%3};" \
        : "+f"((c)[0]), "+f"((c)[1]), "+f"((c)[2]), "+f"((c)[3]) \
        : "r"((a)[0]), "r"((a)[1]), "r"((a)[2]), "r"((a)[3]), \
          "r"((b)[0]), "r"((b)[1]))

#define MMA_BF16(c, a, b) \
    asm volatile( \
        "mma.sync.aligned.m16n8k16.row.col.f32.bf16.bf16.f32 " \
        "{%0,%1,%2,%3}, {%4,%5,%6,%7}, {%8,%9}, {%0,%1,%2,%3};" \
        : "+f"((c)[0]), "+f"((c)[1]), "+f"((c)[2]), "+f"((c)[3]) \
        : "r"((a)[0]), "r"((a)[1]), "r"((a)[2]), "r"((a)[3]), \
          "r"((b)[0]), "r"((b)[1]))

#define CP16(dst, src, nbytes) \
    asm volatile("cp.async.cg.shared.global [%0], [%1], 16, %2;" \
                 :: "r"(dst), "l"(src), "r"(nbytes))
#define CP_COMMIT()  asm volatile("cp.async.commit_group;")
#define CP_WAIT0()   asm volatile("cp.async.wait_group 0;")
#define CP_WAIT1()   asm volatile("cp.async.wait_group 1;")

__global__ void split_bf_k(const float* __restrict__ src, bf16* __restrict__ hi,
                           bf16* __restrict__ lo, long n)
{
    long i = (long)blockIdx.x * blockDim.x + threadIdx.x;
    long stride = (long)gridDim.x * blockDim.x;
    for (; i < n; i += stride) {
        float v = src[i];
        bf16 h = __float2bfloat16(v);
        hi[i] = h;
        lo[i] = __float2bfloat16(v - __bfloat162float(h));
    }
}

// ============================================================================
// 3xTF32 GEMM, BMv in {64,128}, 3-stage cp.async pipeline (wait_group 1).
// Chunked-IEEE accumulation; per-output math identical to R9 -> bit-identical.
// ============================================================================
#define FBN 128
#define FBK 16
#define FPAD 20

template <int BMv>
__global__ __launch_bounds__(256)
void tf32_gemm(const float* __restrict__ A, const float* __restrict__ B,
               float* __restrict__ C, int M, int N, int K,
               long lda, long ldb, long ldc)
{
    constexpr int MT = 2;
    constexpr int NT = (BMv == 128) ? 8 : 4;
    constexpr int ACH = BMv * 4 / 256;
    constexpr int ASZ = BMv * FPAD;    // floats
    constexpr int BSZ = FBN * FPAD;

    extern __shared__ float dsm[];     // [3*ASZ | 3*BSZ]
    float* sAbuf = dsm;
    float* sBbuf = dsm + 3 * ASZ;

    const int m0 = blockIdx.y * BMv;
    const int n0 = blockIdx.x * FBN;
    const int tid = threadIdx.x;
    const int warp = tid >> 5;
    const int lane = tid & 31;
    const int gid = lane >> 2;
    const int tig = lane & 3;
    const int wm = (BMv == 128) ? (warp >> 1) * 32 : (warp & 1) * 32;
    const int wn = (BMv == 128) ? (warp & 1) * 64  : (warp >> 1) * 32;

    const float* aSrc[ACH];
    uint32_t aOff[ACH];
    const float* bSrc[2];
    uint32_t bOff[2];
    int bPred[2];
    const uint32_t saBase = (uint32_t)__cvta_generic_to_shared(sAbuf);
    const uint32_t sbBase = (uint32_t)__cvta_generic_to_shared(sBbuf);
#pragma unroll
    for (int it = 0; it < ACH; it++) {
        int idx = tid + it * 256;
        int row = idx >> 2, ch = idx & 3;
        aSrc[it] = A + (long)(m0 + row) * lda + ch * 4;
        aOff[it] = (uint32_t)(row * FPAD + ch * 4) * 4u;
    }
#pragma unroll
    for (int it = 0; it < 2; it++) {
        int idx = tid + it * 256;
        int row = idx >> 2, ch = idx & 3;
        int nrow = n0 + row;
        bPred[it] = (nrow < N) ? 16 : 0;
        if (nrow >= N) nrow = N - 1;
        bSrc[it] = B + (long)nrow * ldb + ch * 4;
        bOff[it] = (uint32_t)(row * FPAD + ch * 4) * 4u;
    }

    float acc[MT][NT][4];
#pragma unroll
    for (int mt = 0; mt < MT; mt++)
#pragma unroll
        for (int nt = 0; nt < NT; nt++)
#pragma unroll
            for (int r = 0; r < 4; r++) acc[mt][nt][r] = 0.f;

    const int NTILES = K / FBK;

    // prologue: tiles 0,1 -> bufs 0,1
#pragma unroll
    for (int s = 0; s < 2; s++) {
        const long kk = (long)s * FBK;
#pragma unroll
        for (int it = 0; it < ACH; it++)
            CP16(saBase + s * ASZ * 4u + aOff[it], aSrc[it] + kk, 16);
#pragma unroll
        for (int it = 0; it < 2; it++)
            CP16(sbBase + s * BSZ * 4u + bOff[it], bSrc[it] + kk, bPred[it]);
        CP_COMMIT();
    }

    int cur = 0, pre = 2;
    for (int t = 0; t < NTILES; t++) {
        if (t + 1 < NTILES) CP_WAIT1(); else CP_WAIT0();
        __syncthreads();

        if (t + 2 < NTILES) {
            const long kk = (long)(t + 2) * FBK;
#pragma unroll
            for (int it = 0; it < ACH; it++)
                CP16(saBase + pre * ASZ * 4u + aOff[it], aSrc[it] + kk, 16);
#pragma unroll
            for (int it = 0; it < 2; it++)
                CP16(sbBase + pre * BSZ * 4u + bOff[it], bSrc[it] + kk, bPred[it]);
            CP_COMMIT();
        }

        const float* cA = sAbuf + cur * ASZ;
        const float* cB = sBbuf + cur * BSZ;

        uint32_t ah[2][MT][4], al[2][MT][4];
#pragma unroll
        for (int ks = 0; ks < 2; ks++)
#pragma unroll
            for (int mt = 0; mt < MT; mt++)
#pragma unroll
                for (int r = 0; r < 4; r++) {
                    int row = wm + mt * 16 + gid + (r & 1) * 8;
                    int col = ks * 8 + tig + (r >> 1) * 4;
                    float v = cA[row * FPAD + col];
                    uint32_t h = f2tf32(v);
                    ah[ks][mt][r] = h;
                    al[ks][mt][r] = f2tf32(v - __uint_as_float(h));
                }

#pragma unroll
        for (int nt = 0; nt < NT; nt++) {
            uint32_t bh[2][2], bl[2][2];
#pragma unroll
            for (int ks = 0; ks < 2; ks++)
#pragma unroll
                for (int r = 0; r < 2; r++) {
                    int n = wn + nt * 8 + gid;
                    int kq = ks * 8 + tig + r * 4;
                    float v = cB[n * FPAD + kq];
                    uint32_t h = f2tf32(v);
                    bh[ks][r] = h;
                    bl[ks][r] = f2tf32(v - __uint_as_float(h));
                }
#pragma unroll
            for (int mt = 0; mt < MT; mt++) {
                float f[4] = {0.f, 0.f, 0.f, 0.f};
#pragma unroll
                for (int ks = 0; ks < 2; ks++) {
                    MMA_TF32(f, ah[ks][mt], bh[ks]);
                    MMA_TF32(f, ah[ks][mt], bl[ks]);
                    MMA_TF32(f, al[ks][mt], bh[ks]);
                }
                float* c = acc[mt][nt];
                c[0] += f[0]; c[1] += f[1]; c[2] += f[2]; c[3] += f[3];
            }
        }

        cur = (cur == 2) ? 0 : cur + 1;
        pre = (pre == 2) ? 0 : pre + 1;
    }

#pragma unroll
    for (int mt = 0; mt < MT; mt++) {
        int row0 = m0 + wm + mt * 16 + gid;
#pragma unroll
        for (int nt = 0; nt < NT; nt++) {
            int n = n0 + wn + nt * 8 + tig * 2;
            if (n >= N) continue;
            float* c = acc[mt][nt];
            C[(long)row0 * ldc + n]         = c[0];
            C[(long)row0 * ldc + n + 1]     = c[1];
            C[(long)(row0+8) * ldc + n]     = c[2];
            C[(long)(row0+8) * ldc + n + 1] = c[3];
        }
    }
}

// ============================================================================
// bf16 tensor-core GEMM, 3-stage cp.async pipeline per pass, chunked-IEEE acc.
// ============================================================================
#define TBM 128
#define TBN 128
#define TBK 32
#define PADK 40

template <typename TC>
__global__ __launch_bounds__(256)
void bf16_gemm(const bf16* __restrict__ A0, const bf16* __restrict__ A1,
               const bf16* __restrict__ B0, const bf16* __restrict__ B1,
               TC* __restrict__ C, int npass, int M, int N, int K,
               long lda, long ldb, long ldc, long Abat, long Bbat, long Cbat)
{
    constexpr int ASZ = TBM * PADK;   // bf16 elems
    constexpr int BSZ = TBN * PADK;

    extern __shared__ bf16 dsmb[];    // [3*ASZ | 3*BSZ]
    bf16* sAbuf = dsmb;
    bf16* sBbuf = dsmb + 3 * ASZ;

    const long zo = blockIdx.z;
    C += zo * Cbat;

    const int m0 = blockIdx.y * TBM;
    const int n0 = blockIdx.x * TBN;
    const int tid = threadIdx.x;
    const int warp = tid >> 5;
    const int lane = tid & 31;
    const int gid = lane >> 2;
    const int tig = lane & 3;
    const int wm = (warp >> 1) * 32;
    const int wn = (warp & 1) * 64;

    const uint32_t saBase = (uint32_t)__cvta_generic_to_shared(sAbuf);
    const uint32_t sbBase = (uint32_t)__cvta_generic_to_shared(sBbuf);

    float acc[2][8][4];
#pragma unroll
    for (int mt = 0; mt < 2; mt++)
#pragma unroll
        for (int nt = 0; nt < 8; nt++)
#pragma unroll
            for (int r = 0; r < 4; r++) acc[mt][nt][r] = 0.f;

    const int NTILES = K / TBK;

    for (int p = 0; p < npass; p++) {
        const bf16* A = (p ? A1 : A0) + zo * Abat;
        const bf16* B = (p ? B1 : B0) + zo * Bbat;

        const bf16* aSrc[2];
        const bf16* bSrc[2];
        uint32_t aOff[2], bOff[2];
        int bPred[2];
#pragma unroll
        for (int it = 0; it < 2; it++) {
            int idx = tid + it * 256;
            int row = idx >> 2, ch = idx & 3;
            aSrc[it] = A + (long)(m0 + row) * lda + ch * 8;
            int nrow = n0 + row;
            bPred[it] = (nrow < N) ? 16 : 0;
            if (nrow >= N) nrow = N - 1;
            bSrc[it] = B + (long)nrow * ldb + ch * 8;
            aOff[it] = (uint32_t)(row * PADK + ch * 8) * 2u;
            bOff[it] = (uint32_t)(row * PADK + ch * 8) * 2u;
        }

        if (p) __syncthreads();   // previous pass fully done before buf reuse

        // prologue: tiles 0,1 -> bufs 0,1
#pragma unroll
        for (int s = 0; s < 2; s++) {
            const long kk = (long)s * TBK;
#pragma unroll
            for (int it = 0; it < 2; it++) {
                CP16(saBase + s * ASZ * 2u + aOff[it], aSrc[it] + kk, 16);
                CP16(sbBase + s * BSZ * 2u + bOff[it], bSrc[it] + kk, bPred[it]);
            }
            CP_COMMIT();
        }

        int cur = 0, pre = 2;
        for (int t = 0; t < NTILES; t++) {
            if (t + 1 < NTILES) CP_WAIT1(); else CP_WAIT0();
            __syncthreads();

            if (t + 2 < NTILES) {
                const long kk = (long)(t + 2) * TBK;
#pragma unroll
                for (int it = 0; it < 2; it++) {
                    CP16(saBase + pre * ASZ * 2u + aOff[it], aSrc[it] + kk, 16);
                    CP16(sbBase + pre * BSZ * 2u + bOff[it], bSrc[it] + kk, bPred[it]);
                }
                CP_COMMIT();
            }

            const bf16* cA = sAbuf + cur * ASZ;
            const bf16* cB = sBbuf + cur * BSZ;

            uint32_t a[2][2][4];
#pragma unroll
            for (int ks = 0; ks < 2; ks++)
#pragma unroll
                for (int mt = 0; mt < 2; mt++)
#pragma unroll
                    for (int r = 0; r < 4; r++) {
                        int row = wm + mt * 16 + gid + (r & 1) * 8;
                        int col = ks * 16 + tig * 2 + (r >> 1) * 8;
                        a[ks][mt][r] = *(const uint32_t*)&cA[row * PADK + col];
                    }

#pragma unroll
            for (int nt = 0; nt < 8; nt++) {
                uint32_t b[2][2];
#pragma unroll
                for (int ks = 0; ks < 2; ks++)
#pragma unroll
                    for (int r = 0; r < 2; r++) {
                        int n  = wn + nt * 8 + gid;
                        int kq = ks * 16 + tig * 2 + r * 8;
                        b[ks][r] = *(const uint32_t*)&cB[n * PADK + kq];
                    }
#pragma unroll
                for (int mt = 0; mt < 2; mt++) {
                    float f[4] = {0.f, 0.f, 0.f, 0.f};
                    MMA_BF16(f, a[0][mt], b[0]);
                    MMA_BF16(f, a[1][mt], b[1]);
                    float* c = acc[mt][nt];
                    c[0] += f[0]; c[1] += f[1]; c[2] += f[2]; c[3] += f[3];
                }
            }

            cur = (cur == 2) ? 0 : cur + 1;
            pre = (pre == 2) ? 0 : pre + 1;
        }
    }

#pragma unroll
    for (int mt = 0; mt < 2; mt++) {
        int row0 = m0 + wm + mt * 16 + gid;
#pragma unroll
        for (int nt = 0; nt < 8; nt++) {
            int n = n0 + wn + nt * 8 + tig * 2;
            if (n >= N) continue;
            float* c = acc[mt][nt];
            if (sizeof(TC) == 4) {
                float* Cf = (float*)C;
                Cf[(long)row0 * ldc + n]         = c[0];
                Cf[(long)row0 * ldc + n + 1]     = c[1];
                Cf[(long)(row0+8) * ldc + n]     = c[2];
                Cf[(long)(row0+8) * ldc + n + 1] = c[3];
            } else {
                bf16* Cb = (bf16*)C;
                *(__nv_bfloat162*)&Cb[(long)row0 * ldc + n] =
                    __nv_bfloat162(__float2bfloat16(c[0]), __float2bfloat16(c[1]));
                *(__nv_bfloat162*)&Cb[(long)(row0+8) * ldc + n] =
                    __nv_bfloat162(__float2bfloat16(c[2]), __float2bfloat16(c[3]));
            }
        }
    }
}

// ---------------- pack q/k/v (bf16, head-major) + RoPE ----------------
__global__ void pack_k(const float* __restrict__ qu, const float* __restrict__ kvf,
                       const float* __restrict__ dwn,
                       bf16* __restrict__ q, bf16* __restrict__ k, bf16* __restrict__ v)
{
    const int s = blockIdx.x;
    const int tid = threadIdx.x;  // 256

    __shared__ float ssin[32], scos[32];
    if (tid < 32) {
        double invf_d = pow(10000.0, -((double)(2 * tid)) / 64.0);
        float invf = (float)invf_d;
        float ang = (float)s * invf;
        double a = (double)ang;
        ssin[tid] = (float)sin(a);
        scos[tid] = (float)cos(a);
    }
    __syncthreads();

    for (int idx = tid; idx < H_ * DV_; idx += 256) {
        int h = idx >> 7, d = idx & 127;
        q[((long)h * S_ + s) * DQK_ + d] = __float2bfloat16(qu[(long)s * NQU + idx]);
        k[((long)h * S_ + s) * DQK_ + d] = __float2bfloat16(kvf[(long)s * (H_*2*DV_) + idx]);
        v[((long)h * S_ + s) * DV_ + d]  = __float2bfloat16(kvf[(long)s * (H_*2*DV_) + H_*DV_ + idx]);
    }

    for (int idx = tid; idx < H_ * 32; idx += 256) {
        int h = idx >> 5, j = idx & 31;
        float x1 = qu[(long)s * NQU + 2048 + h * DR_ + j];
        float x2 = qu[(long)s * NQU + 2048 + h * DR_ + 32 + j];
        float sn = ssin[j], cs = scos[j];
        q[((long)h * S_ + s) * DQK_ + DV_ + j]      = __float2bfloat16(x1 * cs - x2 * sn);
        q[((long)h * S_ + s) * DQK_ + DV_ + 32 + j] = __float2bfloat16(x2 * cs + x1 * sn);
    }

    if (tid < 32) {
        int j = tid;
        float x1 = dwn[(long)s * NDWN + 1024 + j];
        float x2 = dwn[(long)s * NDWN + 1024 + 32 + j];
        float sn = ssin[j], cs = scos[j];
        float r1 = x1 * cs - x2 * sn;
        float r2 = x2 * cs + x1 * sn;
#pragma unroll
        for (int h = 0; h < H_; h++) {
            k[((long)h * S_ + s) * DQK_ + DV_ + j]      = __float2bfloat16(r1);
            k[((long)h * S_ + s) * DQK_ + DV_ + 32 + j] = __float2bfloat16(r2);
        }
    }
}

// ---------------- transpose v [h][s][d] -> vT [h][d][s] ----------------
__global__ void transpose_v(const bf16* __restrict__ v, bf16* __restrict__ vT)
{
    __shared__ bf16 t[32][33];
    const int h = blockIdx.z;
    const int s0 = blockIdx.x * 32;
    const int d0 = blockIdx.y * 32;
    const int tx = threadIdx.x, ty = threadIdx.y;  // (32, 8)
#pragma unroll
    for (int j = 0; j < 32; j += 8)
        t[ty + j][tx] = v[((long)h * S_ + s0 + ty + j) * DV_ + d0 + tx];
    __syncthreads();
#pragma unroll
    for (int j = 0; j < 32; j += 8)
        vT[((long)h * DV_ + d0 + ty + j) * S_ + s0 + tx] = t[tx][ty + j];
}

// ---------------- softmax over bf16 logits -> bf16 probs ----------------
__global__ void softmax_k(const bf16* __restrict__ L, bf16* __restrict__ P, float scale)
{
    const int s = blockIdx.x;
    const int h = blockIdx.y;
    const bf16* row = L + ((long)h * S_ + s) * S_;
    bf16* prow = P + ((long)h * S_ + s) * S_;
    const int tid = threadIdx.x;

    float v[8];
    float mx = -1e30f;
#pragma unroll
    for (int i = 0; i < 8; i++) {
        v[i] = __bfloat162float(row[tid + i * 256]) * scale;
        mx = fmaxf(mx, v[i]);
    }
    __shared__ float red[256];
    red[tid] = mx;
    __syncthreads();
    for (int st = 128; st > 0; st >>= 1) {
        if (tid < st) red[tid] = fmaxf(red[tid], red[tid + st]);
        __syncthreads();
    }
    mx = red[0];
    __syncthreads();

    float sum = 0.f;
#pragma unroll
    for (int i = 0; i < 8; i++) {
        v[i] = expf(v[i] - mx);
        sum += v[i];
    }
    red[tid] = sum;
    __syncthreads();
    for (int st = 128; st > 0; st >>= 1) {
        if (tid < st) red[tid] += red[tid + st];
        __syncthreads();
    }
    float tot = red[0];
#pragma unroll
    for (int i = 0; i < 8; i++)
        prow[tid + i * 256] = __float2bfloat16(v[i] / tot);
}

// ---------------- orchestration ----------------
extern "C" void kernel_launch(void* const* d_in, const int* in_sizes, int n_in,
                              void* d_out, int out_size)
{
    (void)in_sizes; (void)n_in; (void)out_size;
    const float* x       = (const float*)d_in[0];
    const float* wq_down = (const float*)d_in[1];
    const float* wq_up   = (const float*)d_in[2];
    const float* wq_rope = (const float*)d_in[3];
    const float* wkv_down= (const float*)d_in[4];
    const float* wkv_up  = (const float*)d_in[5];
    const float* wk_rope = (const float*)d_in[6];
    const float* wo      = (const float*)d_in[7];
    float* out = (float*)d_out;

    float *wd, *wu, *dwn, *qu, *kvf;
    cudaGetSymbolAddress((void**)&wd,  g_wd);
    cudaGetSymbolAddress((void**)&wu,  g_wu);
    cudaGetSymbolAddress((void**)&dwn, g_down);
    cudaGetSymbolAddress((void**)&qu,  g_qu);
    cudaGetSymbolAddress((void**)&kvf, g_kv);

    bf16 *q, *k, *v, *vT, *logits, *probs, *attn_bf, *wo_h, *wo_l;
    cudaGetSymbolAddress((void**)&q, g_q);
    cudaGetSymbolAddress((void**)&k, g_k);
    cudaGetSymbolAddress((void**)&v, g_v);
    cudaGetSymbolAddress((void**)&vT, g_vT);
    cudaGetSymbolAddress((void**)&logits, g_logits);
    cudaGetSymbolAddress((void**)&probs, g_probs);
    cudaGetSymbolAddress((void**)&attn_bf, g_attn_bf);
    cudaGetSymbolAddress((void**)&wo_h, g_wo_h);
    cudaGetSymbolAddress((void**)&wo_l, g_wo_l);

    // dynamic smem sizes (3-stage)
    const int SM64  = 3 * (64 * FPAD + FBN * FPAD) * 4;    // 46080
    const int SM128 = 3 * (128 * FPAD + FBN * FPAD) * 4;   // 61440
    const int SMBF  = 3 * (TBM * PADK + TBN * PADK) * 2;   // 61440
    cudaFuncSetAttribute(tf32_gemm<64>,  cudaFuncAttributeMaxDynamicSharedMemorySize, SM64);
    cudaFuncSetAttribute(tf32_gemm<128>, cudaFuncAttributeMaxDynamicSharedMemorySize, SM128);
    cudaFuncSetAttribute(bf16_gemm<bf16>,  cudaFuncAttributeMaxDynamicSharedMemorySize, SMBF);
    cudaFuncSetAttribute(bf16_gemm<float>, cudaFuncAttributeMaxDynamicSharedMemorySize, SMBF);

    dim3 blk(256);
    auto bgrid = [](int M, int N, int batch) {
        return dim3((N + TBN - 1) / TBN, (M + TBM - 1) / TBM, batch);
    };

    // 0) concat weights (D2D) + wo bf16 split
    cudaMemcpyAsync(wd,                 wq_down,  (size_t)QR_ * E_ * 4, cudaMemcpyDeviceToDevice);
    cudaMemcpyAsync(wd + (size_t)QR_*E_, wkv_down, (size_t)KVR_ * E_ * 4, cudaMemcpyDeviceToDevice);
    cudaMemcpyAsync(wd + (size_t)(QR_+KVR_)*E_, wk_rope, (size_t)DR_ * E_ * 4, cudaMemcpyDeviceToDevice);
    cudaMemcpyAsync(wu,                  wq_up,   (size_t)H_*DV_ * QR_ * 4, cudaMemcpyDeviceToDevice);
    cudaMemcpyAsync(wu + (size_t)H_*DV_*QR_, wq_rope, (size_t)H_*DR_ * QR_ * 4, cudaMemcpyDeviceToDevice);
    split_bf_k<<<592, 256>>>(wo, wo_h, wo_l, (long)E_*H_*DV_);

    // 1) fused down projection: [cq|ckv|kr] = x @ wd^T  (BM=64: 9x32 = 288 CTAs)
    tf32_gemm<64><<<dim3((NDWN + FBN - 1) / FBN, S_ / 64, 1), blk, SM64>>>(
        x, wd, dwn, S_, NDWN, E_, E_, E_, NDWN);

    // 2) fused q up projection (BM=64: 24x32 = 768 CTAs)
    tf32_gemm<64><<<dim3(NQU / FBN, S_ / 64, 1), blk, SM64>>>(
        dwn, wu, qu, S_, NQU, QR_, NDWN, QR_, NQU);
    // kv up (BM=128: 32x16 = 512 CTAs)
    tf32_gemm<128><<<dim3((H_*2*DV_) / FBN, S_ / 128, 1), blk, SM128>>>(
        dwn + QR_, wkv_up, kvf, S_, H_*2*DV_, KVR_, NDWN, KVR_, H_*2*DV_);

    // 3) pack + rope -> head-major bf16 q/k/v ; transpose v
    pack_k<<<S_, 256>>>(qu, kvf, dwn, q, k, v);
    {
        dim3 tg(S_/32, DV_/32, H_);
        dim3 tb(32, 8);
        transpose_v<<<tg, tb>>>(v, vT);
    }

    // 4) logits[h] = bf16( q[h] @ k[h]^T )
    bf16_gemm<bf16><<<bgrid(S_, S_, H_), blk, SMBF>>>(
        q, q, k, k, logits, 1, S_, S_, DQK_, DQK_, DQK_, S_,
        (long)S_*DQK_, (long)S_*DQK_, (long)S_*S_);

    // 5) softmax
    {
        dim3 g(S_, H_);
        softmax_k<<<g, 256>>>(logits, probs, 1.0f / sqrtf((float)(DV_ + DR_)));
    }

    // 6) attn[h] = bf16( probs[h] @ v[h] ), stored bf16 interleaved [s][h*DV]
    bf16_gemm<bf16><<<bgrid(S_, DV_, H_), blk, SMBF>>>(
        probs, probs, vT, vT, attn_bf, 1, S_, DV_, S_, S_, S_, (long)H_*DV_,
        (long)S_*S_, (long)DV_*S_, DV_);

    // 7) out = attn(bf16-exact) @ wo^T : 2-pass bf16 (wo = hi + lo)
    bf16_gemm<float><<<bgrid(S_, E_, 1), blk, SMBF>>>(
        attn_bf, attn_bf, wo_h, wo_l, out, 2, S_, E_, H_*DV_,
        H_*DV_, H_*DV_, E_, 0, 0, 0);
}

// round 13
// speedup vs baseline: 1.2144x; 1.0174x over previous
#include <cuda_runtime.h>
#include <cuda_bf16.h>
#include <math.h>
#include <stdint.h>

#define S_  2048
#define E_  2048
#define H_  16
#define QR_ 512
#define KVR_ 512
#define DR_ 64
#define DV_ 128
#define DQK_ 192   // DV + DR
#define NDWN 1088  // QR + KVR + DR
#define NQU  3072  // H*DV + H*DR

typedef __nv_bfloat16 bf16;

// ---------------- scratch (device globals) ----------------
__device__ float g_wd [NDWN * E_];
__device__ float g_wu [NQU * QR_];
__device__ float g_down[S_ * NDWN];
__device__ float g_qu [S_ * NQU];
__device__ float g_kv [S_ * (H_*2*DV_)];
__device__ bf16 g_wo_h[E_*H_*DV_], g_wo_l[E_*H_*DV_];
__device__ bf16 g_q[(size_t)H_ * S_ * DQK_];
__device__ bf16 g_k[(size_t)H_ * S_ * DQK_];
__device__ bf16 g_v[(size_t)H_ * S_ * DV_];
__device__ bf16 g_vT[(size_t)H_ * DV_ * S_];
__device__ bf16 g_logits[(size_t)H_ * S_ * S_];
__device__ bf16 g_probs [(size_t)H_ * S_ * S_];
__device__ bf16 g_attn_bf[(size_t)S_ * H_ * DV_];

// ---------------- helpers ----------------
__device__ __forceinline__ uint32_t f2tf32(float x) {
    uint32_t r;
    asm("cvt.rna.tf32.f32 %0, %1;" : "=r"(r) : "f"(x));
    return r;
}

#define MMA_TF32(c, a, b) \
    asm volatile( \
        "mma.sync.aligned.m16n8k8.row.col.f32.tf32.tf32.f32 " \
        "{%0,%1,%2,%3}, {%4,%5,%6,%7}, {%8,%9}, {%0,%1,%2,%3};" \
        : "+f"((c)[0]), "+f"((c)[1]), "+f"((c)[2]), "+f"((c)[3]) \
        : "r"((a)[0]), "r"((a)[1]), "r"((a)[2]), "r"((a)[3]), \
          "r"((b)[0]), "r"((b)[1]))

#define MMA_BF16(c, a, b) \
    asm volatile( \
        "mma.sync.aligned.m16n8k16.row.col.f32.bf16.bf16.f32 " \
        "{%0,%1,%2,%3}, {%4,%5,%6,%7}, {%8,%9}, {%0,%1,%2,%3};" \
        : "+f"((c)[0]), "+f"((c)[1]), "+f"((c)[2]), "+f"((c)[3]) \
        : "r"((a)[0]), "r"((a)[1]), "r"((a)[2]), "r"((a)[3]), \
          "r"((b)[0]), "r"((b)[1]))

#define CP16(dst, src, nbytes) \
    asm volatile("cp.async.cg.shared.global [%0], [%1], 16, %2;" \
                 :: "r"(dst), "l"(src), "r"(nbytes))
#define CP_COMMIT()  asm volatile("cp.async.commit_group;")
#define CP_WAIT0()   asm volatile("cp.async.wait_group 0;")
#define CP_WAIT1()   asm volatile("cp.async.wait_group 1;")

__global__ void split_bf_k(const float* __restrict__ src, bf16* __restrict__ hi,
                           bf16* __restrict__ lo, long n)
{
    long i = (long)blockIdx.x * blockDim.x + threadIdx.x;
    long stride = (long)gridDim.x * blockDim.x;
    for (; i < n; i += stride) {
        float v = src[i];
        bf16 h = __float2bfloat16(v);
        hi[i] = h;
        lo[i] = __float2bfloat16(v - __bfloat162float(h));
    }
}

// ============================================================================
// 3xTF32 GEMM, BMv in {64,128}, 3-stage cp.async pipeline (wait_group 1).
// Chunked-IEEE accumulation; bit-identical to R11.
// ============================================================================
#define FBN 128
#define FBK 16
#define FPAD 20

template <int BMv>
__global__ __launch_bounds__(256)
void tf32_gemm(const float* __restrict__ A, const float* __restrict__ B,
               float* __restrict__ C, int M, int N, int K,
               long lda, long ldb, long ldc)
{
    constexpr int MT = 2;
    constexpr int NT = (BMv == 128) ? 8 : 4;
    constexpr int ACH = BMv * 4 / 256;
    constexpr int ASZ = BMv * FPAD;    // floats
    constexpr int BSZ = FBN * FPAD;

    extern __shared__ float dsm[];     // [3*ASZ | 3*BSZ]
    float* sAbuf = dsm;
    float* sBbuf = dsm + 3 * ASZ;

    const int m0 = blockIdx.y * BMv;
    const int n0 = blockIdx.x * FBN;
    const int tid = threadIdx.x;
    const int warp = tid >> 5;
    const int lane = tid & 31;
    const int gid = lane >> 2;
    const int tig = lane & 3;
    const int wm = (BMv == 128) ? (warp >> 1) * 32 : (warp & 1) * 32;
    const int wn = (BMv == 128) ? (warp & 1) * 64  : (warp >> 1) * 32;

    const float* aSrc[ACH];
    uint32_t aOff[ACH];
    const float* bSrc[2];
    uint32_t bOff[2];
    int bPred[2];
    const uint32_t saBase = (uint32_t)__cvta_generic_to_shared(sAbuf);
    const uint32_t sbBase = (uint32_t)__cvta_generic_to_shared(sBbuf);
#pragma unroll
    for (int it = 0; it < ACH; it++) {
        int idx = tid + it * 256;
        int row = idx >> 2, ch = idx & 3;
        aSrc[it] = A + (long)(m0 + row) * lda + ch * 4;
        aOff[it] = (uint32_t)(row * FPAD + ch * 4) * 4u;
    }
#pragma unroll
    for (int it = 0; it < 2; it++) {
        int idx = tid + it * 256;
        int row = idx >> 2, ch = idx & 3;
        int nrow = n0 + row;
        bPred[it] = (nrow < N) ? 16 : 0;
        if (nrow >= N) nrow = N - 1;
        bSrc[it] = B + (long)nrow * ldb + ch * 4;
        bOff[it] = (uint32_t)(row * FPAD + ch * 4) * 4u;
    }

    float acc[MT][NT][4];
#pragma unroll
    for (int mt = 0; mt < MT; mt++)
#pragma unroll
        for (int nt = 0; nt < NT; nt++)
#pragma unroll
            for (int r = 0; r < 4; r++) acc[mt][nt][r] = 0.f;

    const int NTILES = K / FBK;

#pragma unroll
    for (int s = 0; s < 2; s++) {
        const long kk = (long)s * FBK;
#pragma unroll
        for (int it = 0; it < ACH; it++)
            CP16(saBase + s * ASZ * 4u + aOff[it], aSrc[it] + kk, 16);
#pragma unroll
        for (int it = 0; it < 2; it++)
            CP16(sbBase + s * BSZ * 4u + bOff[it], bSrc[it] + kk, bPred[it]);
        CP_COMMIT();
    }

    int cur = 0, pre = 2;
    for (int t = 0; t < NTILES; t++) {
        if (t + 1 < NTILES) CP_WAIT1(); else CP_WAIT0();
        __syncthreads();

        if (t + 2 < NTILES) {
            const long kk = (long)(t + 2) * FBK;
#pragma unroll
            for (int it = 0; it < ACH; it++)
                CP16(saBase + pre * ASZ * 4u + aOff[it], aSrc[it] + kk, 16);
#pragma unroll
            for (int it = 0; it < 2; it++)
                CP16(sbBase + pre * BSZ * 4u + bOff[it], bSrc[it] + kk, bPred[it]);
            CP_COMMIT();
        }

        const float* cA = sAbuf + cur * ASZ;
        const float* cB = sBbuf + cur * BSZ;

        uint32_t ah[2][MT][4], al[2][MT][4];
#pragma unroll
        for (int ks = 0; ks < 2; ks++)
#pragma unroll
            for (int mt = 0; mt < MT; mt++)
#pragma unroll
                for (int r = 0; r < 4; r++) {
                    int row = wm + mt * 16 + gid + (r & 1) * 8;
                    int col = ks * 8 + tig + (r >> 1) * 4;
                    float v = cA[row * FPAD + col];
                    uint32_t h = f2tf32(v);
                    ah[ks][mt][r] = h;
                    al[ks][mt][r] = f2tf32(v - __uint_as_float(h));
                }

#pragma unroll
        for (int nt = 0; nt < NT; nt++) {
            uint32_t bh[2][2], bl[2][2];
#pragma unroll
            for (int ks = 0; ks < 2; ks++)
#pragma unroll
                for (int r = 0; r < 2; r++) {
                    int n = wn + nt * 8 + gid;
                    int kq = ks * 8 + tig + r * 4;
                    float v = cB[n * FPAD + kq];
                    uint32_t h = f2tf32(v);
                    bh[ks][r] = h;
                    bl[ks][r] = f2tf32(v - __uint_as_float(h));
                }
#pragma unroll
            for (int mt = 0; mt < MT; mt++) {
                float f[4] = {0.f, 0.f, 0.f, 0.f};
#pragma unroll
                for (int ks = 0; ks < 2; ks++) {
                    MMA_TF32(f, ah[ks][mt], bh[ks]);
                    MMA_TF32(f, ah[ks][mt], bl[ks]);
                    MMA_TF32(f, al[ks][mt], bh[ks]);
                }
                float* c = acc[mt][nt];
                c[0] += f[0]; c[1] += f[1]; c[2] += f[2]; c[3] += f[3];
            }
        }

        cur = (cur == 2) ? 0 : cur + 1;
        pre = (pre == 2) ? 0 : pre + 1;
    }

#pragma unroll
    for (int mt = 0; mt < MT; mt++) {
        int row0 = m0 + wm + mt * 16 + gid;
#pragma unroll
        for (int nt = 0; nt < NT; nt++) {
            int n = n0 + wn + nt * 8 + tig * 2;
            if (n >= N) continue;
            float* c = acc[mt][nt];
            C[(long)row0 * ldc + n]         = c[0];
            C[(long)row0 * ldc + n + 1]     = c[1];
            C[(long)(row0+8) * ldc + n]     = c[2];
            C[(long)(row0+8) * ldc + n + 1] = c[3];
        }
    }
}

// ============================================================================
// bf16 tensor-core GEMM, 3-stage cp.async pipeline per pass (as R11).
// ============================================================================
#define TBM 128
#define TBN 128
#define TBK 32
#define PADK 40

template <typename TC>
__global__ __launch_bounds__(256)
void bf16_gemm(const bf16* __restrict__ A0, const bf16* __restrict__ A1,
               const bf16* __restrict__ B0, const bf16* __restrict__ B1,
               TC* __restrict__ C, int npass, int M, int N, int K,
               long lda, long ldb, long ldc, long Abat, long Bbat, long Cbat)
{
    constexpr int ASZ = TBM * PADK;
    constexpr int BSZ = TBN * PADK;

    extern __shared__ bf16 dsmb[];
    bf16* sAbuf = dsmb;
    bf16* sBbuf = dsmb + 3 * ASZ;

    const long zo = blockIdx.z;
    C += zo * Cbat;

    const int m0 = blockIdx.y * TBM;
    const int n0 = blockIdx.x * TBN;
    const int tid = threadIdx.x;
    const int warp = tid >> 5;
    const int lane = tid & 31;
    const int gid = lane >> 2;
    const int tig = lane & 3;
    const int wm = (warp >> 1) * 32;
    const int wn = (warp & 1) * 64;

    const uint32_t saBase = (uint32_t)__cvta_generic_to_shared(sAbuf);
    const uint32_t sbBase = (uint32_t)__cvta_generic_to_shared(sBbuf);

    float acc[2][8][4];
#pragma unroll
    for (int mt = 0; mt < 2; mt++)
#pragma unroll
        for (int nt = 0; nt < 8; nt++)
#pragma unroll
            for (int r = 0; r < 4; r++) acc[mt][nt][r] = 0.f;

    const int NTILES = K / TBK;

    for (int p = 0; p < npass; p++) {
        const bf16* A = (p ? A1 : A0) + zo * Abat;
        const bf16* B = (p ? B1 : B0) + zo * Bbat;

        const bf16* aSrc[2];
        const bf16* bSrc[2];
        uint32_t aOff[2], bOff[2];
        int bPred[2];
#pragma unroll
        for (int it = 0; it < 2; it++) {
            int idx = tid + it * 256;
            int row = idx >> 2, ch = idx & 3;
            aSrc[it] = A + (long)(m0 + row) * lda + ch * 8;
            int nrow = n0 + row;
            bPred[it] = (nrow < N) ? 16 : 0;
            if (nrow >= N) nrow = N - 1;
            bSrc[it] = B + (long)nrow * ldb + ch * 8;
            aOff[it] = (uint32_t)(row * PADK + ch * 8) * 2u;
            bOff[it] = (uint32_t)(row * PADK + ch * 8) * 2u;
        }

        if (p) __syncthreads();

#pragma unroll
        for (int s = 0; s < 2; s++) {
            const long kk = (long)s * TBK;
#pragma unroll
            for (int it = 0; it < 2; it++) {
                CP16(saBase + s * ASZ * 2u + aOff[it], aSrc[it] + kk, 16);
                CP16(sbBase + s * BSZ * 2u + bOff[it], bSrc[it] + kk, bPred[it]);
            }
            CP_COMMIT();
        }

        int cur = 0, pre = 2;
        for (int t = 0; t < NTILES; t++) {
            if (t + 1 < NTILES) CP_WAIT1(); else CP_WAIT0();
            __syncthreads();

            if (t + 2 < NTILES) {
                const long kk = (long)(t + 2) * TBK;
#pragma unroll
                for (int it = 0; it < 2; it++) {
                    CP16(saBase + pre * ASZ * 2u + aOff[it], aSrc[it] + kk, 16);
                    CP16(sbBase + pre * BSZ * 2u + bOff[it], bSrc[it] + kk, bPred[it]);
                }
                CP_COMMIT();
            }

            const bf16* cA = sAbuf + cur * ASZ;
            const bf16* cB = sBbuf + cur * BSZ;

            uint32_t a[2][2][4];
#pragma unroll
            for (int ks = 0; ks < 2; ks++)
#pragma unroll
                for (int mt = 0; mt < 2; mt++)
#pragma unroll
                    for (int r = 0; r < 4; r++) {
                        int row = wm + mt * 16 + gid + (r & 1) * 8;
                        int col = ks * 16 + tig * 2 + (r >> 1) * 8;
                        a[ks][mt][r] = *(const uint32_t*)&cA[row * PADK + col];
                    }

#pragma unroll
            for (int nt = 0; nt < 8; nt++) {
                uint32_t b[2][2];
#pragma unroll
                for (int ks = 0; ks < 2; ks++)
#pragma unroll
                    for (int r = 0; r < 2; r++) {
                        int n  = wn + nt * 8 + gid;
                        int kq = ks * 16 + tig * 2 + r * 8;
                        b[ks][r] = *(const uint32_t*)&cB[n * PADK + kq];
                    }
#pragma unroll
                for (int mt = 0; mt < 2; mt++) {
                    float f[4] = {0.f, 0.f, 0.f, 0.f};
                    MMA_BF16(f, a[0][mt], b[0]);
                    MMA_BF16(f, a[1][mt], b[1]);
                    float* c = acc[mt][nt];
                    c[0] += f[0]; c[1] += f[1]; c[2] += f[2]; c[3] += f[3];
                }
            }

            cur = (cur == 2) ? 0 : cur + 1;
            pre = (pre == 2) ? 0 : pre + 1;
        }
    }

#pragma unroll
    for (int mt = 0; mt < 2; mt++) {
        int row0 = m0 + wm + mt * 16 + gid;
#pragma unroll
        for (int nt = 0; nt < 8; nt++) {
            int n = n0 + wn + nt * 8 + tig * 2;
            if (n >= N) continue;
            float* c = acc[mt][nt];
            if (sizeof(TC) == 4) {
                float* Cf = (float*)C;
                Cf[(long)row0 * ldc + n]         = c[0];
                Cf[(long)row0 * ldc + n + 1]     = c[1];
                Cf[(long)(row0+8) * ldc + n]     = c[2];
                Cf[(long)(row0+8) * ldc + n + 1] = c[3];
            } else {
                bf16* Cb = (bf16*)C;
                *(__nv_bfloat162*)&Cb[(long)row0 * ldc + n] =
                    __nv_bfloat162(__float2bfloat16(c[0]), __float2bfloat16(c[1]));
                *(__nv_bfloat162*)&Cb[(long)(row0+8) * ldc + n] =
                    __nv_bfloat162(__float2bfloat16(c[2]), __float2bfloat16(c[3]));
            }
        }
    }
}

// ============================================================================
// out GEMM: C = A @ (B0 + B1)^T, shared-A dual-B single K-sweep.
// Per 32K tile: zero-init chain on B0, IEEE FADD; zero-init chain on B1, FADD.
// (FADD reordering vs 2-pass only; lands on fp32 output -> ~1e-7 noise.)
// ============================================================================
__global__ __launch_bounds__(256)
void outb_gemm(const bf16* __restrict__ A, const bf16* __restrict__ B0,
               const bf16* __restrict__ B1, float* __restrict__ C,
               int M, int N, int K, long lda, long ldb, long ldc)
{
    constexpr int ASZ = TBM * PADK;
    constexpr int BSZ = TBN * PADK;

    extern __shared__ bf16 dsmb[];    // [3*ASZ | 3*BSZ (B0) | 3*BSZ (B1)]
    bf16* sAbuf  = dsmb;
    bf16* sB0buf = dsmb + 3 * ASZ;
    bf16* sB1buf = dsmb + 3 * ASZ + 3 * BSZ;

    const int m0 = blockIdx.y * TBM;
    const int n0 = blockIdx.x * TBN;
    const int tid = threadIdx.x;
    const int warp = tid >> 5;
    const int lane = tid & 31;
    const int gid = lane >> 2;
    const int tig = lane & 3;
    const int wm = (warp >> 1) * 32;
    const int wn = (warp & 1) * 64;

    const uint32_t saBase  = (uint32_t)__cvta_generic_to_shared(sAbuf);
    const uint32_t sb0Base = (uint32_t)__cvta_generic_to_shared(sB0buf);
    const uint32_t sb1Base = (uint32_t)__cvta_generic_to_shared(sB1buf);

    const bf16 *aSrc[2], *b0Src[2], *b1Src[2];
    uint32_t sOff[2];
#pragma unroll
    for (int it = 0; it < 2; it++) {
        int idx = tid + it * 256;
        int row = idx >> 2, ch = idx & 3;
        aSrc[it]  = A  + (long)(m0 + row) * lda + ch * 8;
        b0Src[it] = B0 + (long)(n0 + row) * ldb + ch * 8;
        b1Src[it] = B1 + (long)(n0 + row) * ldb + ch * 8;
        sOff[it] = (uint32_t)(row * PADK + ch * 8) * 2u;
    }

    float acc[2][8][4];
#pragma unroll
    for (int mt = 0; mt < 2; mt++)
#pragma unroll
        for (int nt = 0; nt < 8; nt++)
#pragma unroll
            for (int r = 0; r < 4; r++) acc[mt][nt][r] = 0.f;

    const int NTILES = K / TBK;

#pragma unroll
    for (int s = 0; s < 2; s++) {
        const long kk = (long)s * TBK;
#pragma unroll
        for (int it = 0; it < 2; it++) {
            CP16(saBase  + s * ASZ * 2u + sOff[it], aSrc[it]  + kk, 16);
            CP16(sb0Base + s * BSZ * 2u + sOff[it], b0Src[it] + kk, 16);
            CP16(sb1Base + s * BSZ * 2u + sOff[it], b1Src[it] + kk, 16);
        }
        CP_COMMIT();
    }

    int cur = 0, pre = 2;
    for (int t = 0; t < NTILES; t++) {
        if (t + 1 < NTILES) CP_WAIT1(); else CP_WAIT0();
        __syncthreads();

        if (t + 2 < NTILES) {
            const long kk = (long)(t + 2) * TBK;
#pragma unroll
            for (int it = 0; it < 2; it++) {
                CP16(saBase  + pre * ASZ * 2u + sOff[it], aSrc[it]  + kk, 16);
                CP16(sb0Base + pre * BSZ * 2u + sOff[it], b0Src[it] + kk, 16);
                CP16(sb1Base + pre * BSZ * 2u + sOff[it], b1Src[it] + kk, 16);
            }
            CP_COMMIT();
        }

        const bf16* cA  = sAbuf  + cur * ASZ;
        const bf16* cB0 = sB0buf + cur * BSZ;
        const bf16* cB1 = sB1buf + cur * BSZ;

        uint32_t a[2][2][4];
#pragma unroll
        for (int ks = 0; ks < 2; ks++)
#pragma unroll
            for (int mt = 0; mt < 2; mt++)
#pragma unroll
                for (int r = 0; r < 4; r++) {
                    int row = wm + mt * 16 + gid + (r & 1) * 8;
                    int col = ks * 16 + tig * 2 + (r >> 1) * 8;
                    a[ks][mt][r] = *(const uint32_t*)&cA[row * PADK + col];
                }

#pragma unroll
        for (int nt = 0; nt < 8; nt++) {
            uint32_t b0[2][2], b1[2][2];
#pragma unroll
            for (int ks = 0; ks < 2; ks++)
#pragma unroll
                for (int r = 0; r < 2; r++) {
                    int n  = wn + nt * 8 + gid;
                    int kq = ks * 16 + tig * 2 + r * 8;
                    b0[ks][r] = *(const uint32_t*)&cB0[n * PADK + kq];
                    b1[ks][r] = *(const uint32_t*)&cB1[n * PADK + kq];
                }
#pragma unroll
            for (int mt = 0; mt < 2; mt++) {
                float* c = acc[mt][nt];
                float f[4] = {0.f, 0.f, 0.f, 0.f};
                MMA_BF16(f, a[0][mt], b0[0]);
                MMA_BF16(f, a[1][mt], b0[1]);
                c[0] += f[0]; c[1] += f[1]; c[2] += f[2]; c[3] += f[3];
                float g[4] = {0.f, 0.f, 0.f, 0.f};
                MMA_BF16(g, a[0][mt], b1[0]);
                MMA_BF16(g, a[1][mt], b1[1]);
                c[0] += g[0]; c[1] += g[1]; c[2] += g[2]; c[3] += g[3];
            }
        }

        cur = (cur == 2) ? 0 : cur + 1;
        pre = (pre == 2) ? 0 : pre + 1;
    }

#pragma unroll
    for (int mt = 0; mt < 2; mt++) {
        int row0 = m0 + wm + mt * 16 + gid;
#pragma unroll
        for (int nt = 0; nt < 8; nt++) {
            int n = n0 + wn + nt * 8 + tig * 2;
            float* c = acc[mt][nt];
            C[(long)row0 * ldc + n]         = c[0];
            C[(long)row0 * ldc + n + 1]     = c[1];
            C[(long)(row0+8) * ldc + n]     = c[2];
            C[(long)(row0+8) * ldc + n + 1] = c[3];
        }
    }
}

// ---------------- pack q/k/v (bf16, head-major) + RoPE ----------------
__global__ void pack_k(const float* __restrict__ qu, const float* __restrict__ kvf,
                       const float* __restrict__ dwn,
                       bf16* __restrict__ q, bf16* __restrict__ k, bf16* __restrict__ v)
{
    const int s = blockIdx.x;
    const int tid = threadIdx.x;  // 256

    __shared__ float ssin[32], scos[32];
    if (tid < 32) {
        double invf_d = pow(10000.0, -((double)(2 * tid)) / 64.0);
        float invf = (float)invf_d;
        float ang = (float)s * invf;
        double a = (double)ang;
        ssin[tid] = (float)sin(a);
        scos[tid] = (float)cos(a);
    }
    __syncthreads();

    for (int idx = tid; idx < H_ * DV_; idx += 256) {
        int h = idx >> 7, d = idx & 127;
        q[((long)h * S_ + s) * DQK_ + d] = __float2bfloat16(qu[(long)s * NQU + idx]);
        k[((long)h * S_ + s) * DQK_ + d] = __float2bfloat16(kvf[(long)s * (H_*2*DV_) + idx]);
        v[((long)h * S_ + s) * DV_ + d]  = __float2bfloat16(kvf[(long)s * (H_*2*DV_) + H_*DV_ + idx]);
    }

    for (int idx = tid; idx < H_ * 32; idx += 256) {
        int h = idx >> 5, j = idx & 31;
        float x1 = qu[(long)s * NQU + 2048 + h * DR_ + j];
        float x2 = qu[(long)s * NQU + 2048 + h * DR_ + 32 + j];
        float sn = ssin[j], cs = scos[j];
        q[((long)h * S_ + s) * DQK_ + DV_ + j]      = __float2bfloat16(x1 * cs - x2 * sn);
        q[((long)h * S_ + s) * DQK_ + DV_ + 32 + j] = __float2bfloat16(x2 * cs + x1 * sn);
    }

    if (tid < 32) {
        int j = tid;
        float x1 = dwn[(long)s * NDWN + 1024 + j];
        float x2 = dwn[(long)s * NDWN + 1024 + 32 + j];
        float sn = ssin[j], cs = scos[j];
        float r1 = x1 * cs - x2 * sn;
        float r2 = x2 * cs + x1 * sn;
#pragma unroll
        for (int h = 0; h < H_; h++) {
            k[((long)h * S_ + s) * DQK_ + DV_ + j]      = __float2bfloat16(r1);
            k[((long)h * S_ + s) * DQK_ + DV_ + 32 + j] = __float2bfloat16(r2);
        }
    }
}

// ---------------- transpose v [h][s][d] -> vT [h][d][s] ----------------
__global__ void transpose_v(const bf16* __restrict__ v, bf16* __restrict__ vT)
{
    __shared__ bf16 t[32][33];
    const int h = blockIdx.z;
    const int s0 = blockIdx.x * 32;
    const int d0 = blockIdx.y * 32;
    const int tx = threadIdx.x, ty = threadIdx.y;  // (32, 8)
#pragma unroll
    for (int j = 0; j < 32; j += 8)
        t[ty + j][tx] = v[((long)h * S_ + s0 + ty + j) * DV_ + d0 + tx];
    __syncthreads();
#pragma unroll
    for (int j = 0; j < 32; j += 8)
        vT[((long)h * DV_ + d0 + ty + j) * S_ + s0 + tx] = t[tx][ty + j];
}

// ---------------- softmax over bf16 logits -> bf16 probs ----------------
__global__ void softmax_k(const bf16* __restrict__ L, bf16* __restrict__ P, float scale)
{
    const int s = blockIdx.x;
    const int h = blockIdx.y;
    const bf16* row = L + ((long)h * S_ + s) * S_;
    bf16* prow = P + ((long)h * S_ + s) * S_;
    const int tid = threadIdx.x;

    float v[8];
    float mx = -1e30f;
#pragma unroll
    for (int i = 0; i < 8; i++) {
        v[i] = __bfloat162float(row[tid + i * 256]) * scale;
        mx = fmaxf(mx, v[i]);
    }
    __shared__ float red[256];
    red[tid] = mx;
    __syncthreads();
    for (int st = 128; st > 0; st >>= 1) {
        if (tid < st) red[tid] = fmaxf(red[tid], red[tid + st]);
        __syncthreads();
    }
    mx = red[0];
    __syncthreads();

    float sum = 0.f;
#pragma unroll
    for (int i = 0; i < 8; i++) {
        v[i] = expf(v[i] - mx);
        sum += v[i];
    }
    red[tid] = sum;
    __syncthreads();
    for (int st = 128; st > 0; st >>= 1) {
        if (tid < st) red[tid] += red[tid + st];
        __syncthreads();
    }
    float tot = red[0];
#pragma unroll
    for (int i = 0; i < 8; i++)
        prow[tid + i * 256] = __float2bfloat16(v[i] / tot);
}

// ---------------- orchestration ----------------
extern "C" void kernel_launch(void* const* d_in, const int* in_sizes, int n_in,
                              void* d_out, int out_size)
{
    (void)in_sizes; (void)n_in; (void)out_size;
    const float* x       = (const float*)d_in[0];
    const float* wq_down = (const float*)d_in[1];
    const float* wq_up   = (const float*)d_in[2];
    const float* wq_rope = (const float*)d_in[3];
    const float* wkv_down= (const float*)d_in[4];
    const float* wkv_up  = (const float*)d_in[5];
    const float* wk_rope = (const float*)d_in[6];
    const float* wo      = (const float*)d_in[7];
    float* out = (float*)d_out;

    float *wd, *wu, *dwn, *qu, *kvf;
    cudaGetSymbolAddress((void**)&wd,  g_wd);
    cudaGetSymbolAddress((void**)&wu,  g_wu);
    cudaGetSymbolAddress((void**)&dwn, g_down);
    cudaGetSymbolAddress((void**)&qu,  g_qu);
    cudaGetSymbolAddress((void**)&kvf, g_kv);

    bf16 *q, *k, *v, *vT, *logits, *probs, *attn_bf, *wo_h, *wo_l;
    cudaGetSymbolAddress((void**)&q, g_q);
    cudaGetSymbolAddress((void**)&k, g_k);
    cudaGetSymbolAddress((void**)&v, g_v);
    cudaGetSymbolAddress((void**)&vT, g_vT);
    cudaGetSymbolAddress((void**)&logits, g_logits);
    cudaGetSymbolAddress((void**)&probs, g_probs);
    cudaGetSymbolAddress((void**)&attn_bf, g_attn_bf);
    cudaGetSymbolAddress((void**)&wo_h, g_wo_h);
    cudaGetSymbolAddress((void**)&wo_l, g_wo_l);

    // dynamic smem sizes (3-stage)
    const int SM64  = 3 * (64 * FPAD + FBN * FPAD) * 4;        // 46080
    const int SM128 = 3 * (128 * FPAD + FBN * FPAD) * 4;       // 61440
    const int SMBF  = 3 * (TBM * PADK + TBN * PADK) * 2;       // 61440
    const int SMOUT = 3 * (TBM * PADK + 2 * TBN * PADK) * 2;   // 92160
    cudaFuncSetAttribute(tf32_gemm<64>,  cudaFuncAttributeMaxDynamicSharedMemorySize, SM64);
    cudaFuncSetAttribute(tf32_gemm<128>, cudaFuncAttributeMaxDynamicSharedMemorySize, SM128);
    cudaFuncSetAttribute(bf16_gemm<bf16>,  cudaFuncAttributeMaxDynamicSharedMemorySize, SMBF);
    cudaFuncSetAttribute(bf16_gemm<float>, cudaFuncAttributeMaxDynamicSharedMemorySize, SMBF);
    cudaFuncSetAttribute(outb_gemm, cudaFuncAttributeMaxDynamicSharedMemorySize, SMOUT);

    dim3 blk(256);
    auto bgrid = [](int M, int N, int batch) {
        return dim3((N + TBN - 1) / TBN, (M + TBM - 1) / TBM, batch);
    };

    // 0) concat weights (D2D) + wo bf16 split
    cudaMemcpyAsync(wd,                 wq_down,  (size_t)QR_ * E_ * 4, cudaMemcpyDeviceToDevice);
    cudaMemcpyAsync(wd + (size_t)QR_*E_, wkv_down, (size_t)KVR_ * E_ * 4, cudaMemcpyDeviceToDevice);
    cudaMemcpyAsync(wd + (size_t)(QR_+KVR_)*E_, wk_rope, (size_t)DR_ * E_ * 4, cudaMemcpyDeviceToDevice);
    cudaMemcpyAsync(wu,                  wq_up,   (size_t)H_*DV_ * QR_ * 4, cudaMemcpyDeviceToDevice);
    cudaMemcpyAsync(wu + (size_t)H_*DV_*QR_, wq_rope, (size_t)H_*DR_ * QR_ * 4, cudaMemcpyDeviceToDevice);
    split_bf_k<<<592, 256>>>(wo, wo_h, wo_l, (long)E_*H_*DV_);

    // 1) fused down projection: [cq|ckv|kr] = x @ wd^T  (BM=64: 9x32 = 288 CTAs)
    tf32_gemm<64><<<dim3((NDWN + FBN - 1) / FBN, S_ / 64, 1), blk, SM64>>>(
        x, wd, dwn, S_, NDWN, E_, E_, E_, NDWN);

    // 2) fused q up projection (BM=64: 24x32 = 768 CTAs)
    tf32_gemm<64><<<dim3(NQU / FBN, S_ / 64, 1), blk, SM64>>>(
        dwn, wu, qu, S_, NQU, QR_, NDWN, QR_, NQU);
    // kv up (BM=128: 32x16 = 512 CTAs)
    tf32_gemm<128><<<dim3((H_*2*DV_) / FBN, S_ / 128, 1), blk, SM128>>>(
        dwn + QR_, wkv_up, kvf, S_, H_*2*DV_, KVR_, NDWN, KVR_, H_*2*DV_);

    // 3) pack + rope -> head-major bf16 q/k/v ; transpose v
    pack_k<<<S_, 256>>>(qu, kvf, dwn, q, k, v);
    {
        dim3 tg(S_/32, DV_/32, H_);
        dim3 tb(32, 8);
        transpose_v<<<tg, tb>>>(v, vT);
    }

    // 4) logits[h] = bf16( q[h] @ k[h]^T )
    bf16_gemm<bf16><<<bgrid(S_, S_, H_), blk, SMBF>>>(
        q, q, k, k, logits, 1, S_, S_, DQK_, DQK_, DQK_, S_,
        (long)S_*DQK_, (long)S_*DQK_, (long)S_*S_);

    // 5) softmax
    {
        dim3 g(S_, H_);
        softmax_k<<<g, 256>>>(logits, probs, 1.0f / sqrtf((float)(DV_ + DR_)));
    }

    // 6) attn[h] = bf16( probs[h] @ v[h] ), stored bf16 interleaved [s][h*DV]
    bf16_gemm<bf16><<<bgrid(S_, DV_, H_), blk, SMBF>>>(
        probs, probs, vT, vT, attn_bf, 1, S_, DV_, S_, S_, S_, (long)H_*DV_,
        (long)S_*S_, (long)DV_*S_, DV_);

    // 7) out = attn @ (wo_h + wo_l)^T : shared-A dual-B single sweep
    outb_gemm<<<bgrid(S_, E_, 1), blk, SMOUT>>>(
        attn_bf, wo_h, wo_l, out, S_, E_, H_*DV_, H_*DV_, H_*DV_, E_);
}

// round 14
// speedup vs baseline: 1.2642x; 1.0410x over previous
#include <cuda_runtime.h>
#include <cuda_bf16.h>
#include <math.h>
#include <stdint.h>

#define S_  2048
#define E_  2048
#define H_  16
#define QR_ 512
#define KVR_ 512
#define DR_ 64
#define DV_ 128
#define DQK_ 192   // DV + DR
#define NDWN 1088  // QR + KVR + DR
#define NQU  3072  // H*DV + H*DR

typedef __nv_bfloat16 bf16;

// ---------------- scratch (device globals) ----------------
__device__ float g_wd [NDWN * E_];
__device__ float g_wu [NQU * QR_];
__device__ float g_down[S_ * NDWN];
__device__ float g_qu [S_ * NQU];
__device__ float g_kv [S_ * (H_*2*DV_)];
__device__ bf16 g_wo_h[E_*H_*DV_], g_wo_l[E_*H_*DV_];
__device__ bf16 g_q[(size_t)H_ * S_ * DQK_];
__device__ bf16 g_k[(size_t)H_ * S_ * DQK_];
__device__ bf16 g_v[(size_t)H_ * S_ * DV_];
__device__ bf16 g_vT[(size_t)H_ * DV_ * S_];
__device__ bf16 g_logits[(size_t)H_ * S_ * S_];
__device__ bf16 g_probs [(size_t)H_ * S_ * S_];
__device__ bf16 g_attn_bf[(size_t)S_ * H_ * DV_];

// ---------------- helpers ----------------
__device__ __forceinline__ uint32_t f2tf32(float x) {
    uint32_t r;
    asm("cvt.rna.tf32.f32 %0, %1;" : "=r"(r) : "f"(x));
    return r;
}

#define MMA_TF32(c, a, b) \
    asm volatile( \
        "mma.sync.aligned.m16n8k8.row.col.f32.tf32.tf32.f32 " \
        "{%0,%1,%2,%3}, {%4,%5,%6,%7}, {%8,%9}, {%0,%1,%2,%3};" \
        : "+f"((c)[0]), "+f"((c)[1]), "+f"((c)[2]), "+f"((c)[3]) \
        : "r"((a)[0]), "r"((a)[1]), "r"((a)[2]), "r"((a)[3]), \
          "r"((b)[0]), "r"((b)[1]))

#define MMA_BF16(c, a, b) \
    asm volatile( \
        "mma.sync.aligned.m16n8k16.row.col.f32.bf16.bf16.f32 " \
        "{%0,%1,%2,%3}, {%4,%5,%6,%7}, {%8,%9}, {%0,%1,%2,%3};" \
        : "+f"((c)[0]), "+f"((c)[1]), "+f"((c)[2]), "+f"((c)[3]) \
        : "r"((a)[0]), "r"((a)[1]), "r"((a)[2]), "r"((a)[3]), \
          "r"((b)[0]), "r"((b)[1]))

#define CP16(dst, src, nbytes) \
    asm volatile("cp.async.cg.shared.global [%0], [%1], 16, %2;" \
                 :: "r"(dst), "l"(src), "r"(nbytes))
#define CP_COMMIT()  asm volatile("cp.async.commit_group;")
#define CP_WAIT0()   asm volatile("cp.async.wait_group 0;")
#define CP_WAIT1()   asm volatile("cp.async.wait_group 1;")

__global__ void split_bf_k(const float* __restrict__ src, bf16* __restrict__ hi,
                           bf16* __restrict__ lo, long n)
{
    long i = (long)blockIdx.x * blockDim.x + threadIdx.x;
    long stride = (long)gridDim.x * blockDim.x;
    for (; i < n; i += stride) {
        float v = src[i];
        bf16 h = __float2bfloat16(v);
        hi[i] = h;
        lo[i] = __float2bfloat16(v - __bfloat162float(h));
    }
}

// ============================================================================
// 3xTF32 GEMM, BMv in {64,128}, 3-stage cp.async pipeline (wait_group 1).
// Chunked-IEEE accumulation; bit-identical per-output math.
// ============================================================================
#define FBN 128
#define FBK 16
#define FPAD 20

template <int BMv>
__global__ __launch_bounds__(256)
void tf32_gemm(const float* __restrict__ A, const float* __restrict__ B,
               float* __restrict__ C, int M, int N, int K,
               long lda, long ldb, long ldc)
{
    constexpr int MT = 2;
    constexpr int NT = (BMv == 128) ? 8 : 4;
    constexpr int ACH = BMv * 4 / 256;
    constexpr int ASZ = BMv * FPAD;
    constexpr int BSZ = FBN * FPAD;

    extern __shared__ float dsm[];
    float* sAbuf = dsm;
    float* sBbuf = dsm + 3 * ASZ;

    const int m0 = blockIdx.y * BMv;
    const int n0 = blockIdx.x * FBN;
    const int tid = threadIdx.x;
    const int warp = tid >> 5;
    const int lane = tid & 31;
    const int gid = lane >> 2;
    const int tig = lane & 3;
    const int wm = (BMv == 128) ? (warp >> 1) * 32 : (warp & 1) * 32;
    const int wn = (BMv == 128) ? (warp & 1) * 64  : (warp >> 1) * 32;

    const float* aSrc[ACH];
    uint32_t aOff[ACH];
    const float* bSrc[2];
    uint32_t bOff[2];
    int bPred[2];
    const uint32_t saBase = (uint32_t)__cvta_generic_to_shared(sAbuf);
    const uint32_t sbBase = (uint32_t)__cvta_generic_to_shared(sBbuf);
#pragma unroll
    for (int it = 0; it < ACH; it++) {
        int idx = tid + it * 256;
        int row = idx >> 2, ch = idx & 3;
        aSrc[it] = A + (long)(m0 + row) * lda + ch * 4;
        aOff[it] = (uint32_t)(row * FPAD + ch * 4) * 4u;
    }
#pragma unroll
    for (int it = 0; it < 2; it++) {
        int idx = tid + it * 256;
        int row = idx >> 2, ch = idx & 3;
        int nrow = n0 + row;
        bPred[it] = (nrow < N) ? 16 : 0;
        if (nrow >= N) nrow = N - 1;
        bSrc[it] = B + (long)nrow * ldb + ch * 4;
        bOff[it] = (uint32_t)(row * FPAD + ch * 4) * 4u;
    }

    float acc[MT][NT][4];
#pragma unroll
    for (int mt = 0; mt < MT; mt++)
#pragma unroll
        for (int nt = 0; nt < NT; nt++)
#pragma unroll
            for (int r = 0; r < 4; r++) acc[mt][nt][r] = 0.f;

    const int NTILES = K / FBK;

#pragma unroll
    for (int s = 0; s < 2; s++) {
        const long kk = (long)s * FBK;
#pragma unroll
        for (int it = 0; it < ACH; it++)
            CP16(saBase + s * ASZ * 4u + aOff[it], aSrc[it] + kk, 16);
#pragma unroll
        for (int it = 0; it < 2; it++)
            CP16(sbBase + s * BSZ * 4u + bOff[it], bSrc[it] + kk, bPred[it]);
        CP_COMMIT();
    }

    int cur = 0, pre = 2;
    for (int t = 0; t < NTILES; t++) {
        if (t + 1 < NTILES) CP_WAIT1(); else CP_WAIT0();
        __syncthreads();

        if (t + 2 < NTILES) {
            const long kk = (long)(t + 2) * FBK;
#pragma unroll
            for (int it = 0; it < ACH; it++)
                CP16(saBase + pre * ASZ * 4u + aOff[it], aSrc[it] + kk, 16);
#pragma unroll
            for (int it = 0; it < 2; it++)
                CP16(sbBase + pre * BSZ * 4u + bOff[it], bSrc[it] + kk, bPred[it]);
            CP_COMMIT();
        }

        const float* cA = sAbuf + cur * ASZ;
        const float* cB = sBbuf + cur * BSZ;

        uint32_t ah[2][MT][4], al[2][MT][4];
#pragma unroll
        for (int ks = 0; ks < 2; ks++)
#pragma unroll
            for (int mt = 0; mt < MT; mt++)
#pragma unroll
                for (int r = 0; r < 4; r++) {
                    int row = wm + mt * 16 + gid + (r & 1) * 8;
                    int col = ks * 8 + tig + (r >> 1) * 4;
                    float v = cA[row * FPAD + col];
                    uint32_t h = f2tf32(v);
                    ah[ks][mt][r] = h;
                    al[ks][mt][r] = f2tf32(v - __uint_as_float(h));
                }

#pragma unroll
        for (int nt = 0; nt < NT; nt++) {
            uint32_t bh[2][2], bl[2][2];
#pragma unroll
            for (int ks = 0; ks < 2; ks++)
#pragma unroll
                for (int r = 0; r < 2; r++) {
                    int n = wn + nt * 8 + gid;
                    int kq = ks * 8 + tig + r * 4;
                    float v = cB[n * FPAD + kq];
                    uint32_t h = f2tf32(v);
                    bh[ks][r] = h;
                    bl[ks][r] = f2tf32(v - __uint_as_float(h));
                }
#pragma unroll
            for (int mt = 0; mt < MT; mt++) {
                float f[4] = {0.f, 0.f, 0.f, 0.f};
#pragma unroll
                for (int ks = 0; ks < 2; ks++) {
                    MMA_TF32(f, ah[ks][mt], bh[ks]);
                    MMA_TF32(f, ah[ks][mt], bl[ks]);
                    MMA_TF32(f, al[ks][mt], bh[ks]);
                }
                float* c = acc[mt][nt];
                c[0] += f[0]; c[1] += f[1]; c[2] += f[2]; c[3] += f[3];
            }
        }

        cur = (cur == 2) ? 0 : cur + 1;
        pre = (pre == 2) ? 0 : pre + 1;
    }

#pragma unroll
    for (int mt = 0; mt < MT; mt++) {
        int row0 = m0 + wm + mt * 16 + gid;
#pragma unroll
        for (int nt = 0; nt < NT; nt++) {
            int n = n0 + wn + nt * 8 + tig * 2;
            if (n >= N) continue;
            float* c = acc[mt][nt];
            C[(long)row0 * ldc + n]         = c[0];
            C[(long)row0 * ldc + n + 1]     = c[1];
            C[(long)(row0+8) * ldc + n]     = c[2];
            C[(long)(row0+8) * ldc + n + 1] = c[3];
        }
    }
}

// ============================================================================
// Fused qu-up + kv-up: one flattened launch, BM=128 both.
//   blocks [0,384):  C0 = A0 @ B0^T  (M=2048, N=3072, 16x24 tiles)
//   blocks [384,896): C1 = A1 @ B1^T (M=2048, N=4096, 16x32 tiles)
// K=512, lda=NDWN, ldb=QR_ for both. N multiples of 128 -> no predication.
// Same per-output math as tf32_gemm<128> -> bit-identical results.
// ============================================================================
__global__ __launch_bounds__(256)
void tf32_dual(const float* __restrict__ A0, const float* __restrict__ B0, float* __restrict__ C0,
               const float* __restrict__ A1, const float* __restrict__ B1, float* __restrict__ C1,
               int K, long lda, long ldb)
{
    constexpr int ASZ = 128 * FPAD;
    constexpr int BSZ = FBN * FPAD;

    extern __shared__ float dsm[];
    float* sAbuf = dsm;
    float* sBbuf = dsm + 3 * ASZ;

    const int bid = blockIdx.x;
    const float *A, *B;
    float* C;
    int m0, n0;
    long ldc;
    if (bid < 384) {
        A = A0; B = B0; C = C0; ldc = NQU;
        m0 = (bid / 24) * 128;  n0 = (bid % 24) * 128;
    } else {
        int b = bid - 384;
        A = A1; B = B1; C = C1; ldc = H_*2*DV_;
        m0 = (b / 32) * 128;  n0 = (b % 32) * 128;
    }

    const int tid = threadIdx.x;
    const int warp = tid >> 5;
    const int lane = tid & 31;
    const int gid = lane >> 2;
    const int tig = lane & 3;
    const int wm = (warp >> 1) * 32;
    const int wn = (warp & 1) * 64;

    const float* aSrc[2];
    const float* bSrc[2];
    uint32_t sOff[2];
    const uint32_t saBase = (uint32_t)__cvta_generic_to_shared(sAbuf);
    const uint32_t sbBase = (uint32_t)__cvta_generic_to_shared(sBbuf);
#pragma unroll
    for (int it = 0; it < 2; it++) {
        int idx = tid + it * 256;
        int row = idx >> 2, ch = idx & 3;
        aSrc[it] = A + (long)(m0 + row) * lda + ch * 4;
        bSrc[it] = B + (long)(n0 + row) * ldb + ch * 4;
        sOff[it] = (uint32_t)(row * FPAD + ch * 4) * 4u;
    }

    float acc[2][8][4];
#pragma unroll
    for (int mt = 0; mt < 2; mt++)
#pragma unroll
        for (int nt = 0; nt < 8; nt++)
#pragma unroll
            for (int r = 0; r < 4; r++) acc[mt][nt][r] = 0.f;

    const int NTILES = K / FBK;

#pragma unroll
    for (int s = 0; s < 2; s++) {
        const long kk = (long)s * FBK;
#pragma unroll
        for (int it = 0; it < 2; it++) {
            CP16(saBase + s * ASZ * 4u + sOff[it], aSrc[it] + kk, 16);
            CP16(sbBase + s * BSZ * 4u + sOff[it], bSrc[it] + kk, 16);
        }
        CP_COMMIT();
    }

    int cur = 0, pre = 2;
    for (int t = 0; t < NTILES; t++) {
        if (t + 1 < NTILES) CP_WAIT1(); else CP_WAIT0();
        __syncthreads();

        if (t + 2 < NTILES) {
            const long kk = (long)(t + 2) * FBK;
#pragma unroll
            for (int it = 0; it < 2; it++) {
                CP16(saBase + pre * ASZ * 4u + sOff[it], aSrc[it] + kk, 16);
                CP16(sbBase + pre * BSZ * 4u + sOff[it], bSrc[it] + kk, 16);
            }
            CP_COMMIT();
        }

        const float* cA = sAbuf + cur * ASZ;
        const float* cB = sBbuf + cur * BSZ;

        uint32_t ah[2][2][4], al[2][2][4];
#pragma unroll
        for (int ks = 0; ks < 2; ks++)
#pragma unroll
            for (int mt = 0; mt < 2; mt++)
#pragma unroll
                for (int r = 0; r < 4; r++) {
                    int row = wm + mt * 16 + gid + (r & 1) * 8;
                    int col = ks * 8 + tig + (r >> 1) * 4;
                    float v = cA[row * FPAD + col];
                    uint32_t h = f2tf32(v);
                    ah[ks][mt][r] = h;
                    al[ks][mt][r] = f2tf32(v - __uint_as_float(h));
                }

#pragma unroll
        for (int nt = 0; nt < 8; nt++) {
            uint32_t bh[2][2], bl[2][2];
#pragma unroll
            for (int ks = 0; ks < 2; ks++)
#pragma unroll
                for (int r = 0; r < 2; r++) {
                    int n = wn + nt * 8 + gid;
                    int kq = ks * 8 + tig + r * 4;
                    float v = cB[n * FPAD + kq];
                    uint32_t h = f2tf32(v);
                    bh[ks][r] = h;
                    bl[ks][r] = f2tf32(v - __uint_as_float(h));
                }
#pragma unroll
            for (int mt = 0; mt < 2; mt++) {
                float f[4] = {0.f, 0.f, 0.f, 0.f};
#pragma unroll
                for (int ks = 0; ks < 2; ks++) {
                    MMA_TF32(f, ah[ks][mt], bh[ks]);
                    MMA_TF32(f, ah[ks][mt], bl[ks]);
                    MMA_TF32(f, al[ks][mt], bh[ks]);
                }
                float* c = acc[mt][nt];
                c[0] += f[0]; c[1] += f[1]; c[2] += f[2]; c[3] += f[3];
            }
        }

        cur = (cur == 2) ? 0 : cur + 1;
        pre = (pre == 2) ? 0 : pre + 1;
    }

#pragma unroll
    for (int mt = 0; mt < 2; mt++) {
        int row0 = m0 + wm + mt * 16 + gid;
#pragma unroll
        for (int nt = 0; nt < 8; nt++) {
            int n = n0 + wn + nt * 8 + tig * 2;
            float* c = acc[mt][nt];
            C[(long)row0 * ldc + n]         = c[0];
            C[(long)row0 * ldc + n + 1]     = c[1];
            C[(long)(row0+8) * ldc + n]     = c[2];
            C[(long)(row0+8) * ldc + n + 1] = c[3];
        }
    }
}

// ============================================================================
// bf16 tensor-core GEMM, 3-stage cp.async pipeline per pass (as R11/R13).
// ============================================================================
#define TBM 128
#define TBN 128
#define TBK 32
#define PADK 40

template <typename TC>
__global__ __launch_bounds__(256)
void bf16_gemm(const bf16* __restrict__ A0, const bf16* __restrict__ A1,
               const bf16* __restrict__ B0, const bf16* __restrict__ B1,
               TC* __restrict__ C, int npass, int M, int N, int K,
               long lda, long ldb, long ldc, long Abat, long Bbat, long Cbat)
{
    constexpr int ASZ = TBM * PADK;
    constexpr int BSZ = TBN * PADK;

    extern __shared__ bf16 dsmb[];
    bf16* sAbuf = dsmb;
    bf16* sBbuf = dsmb + 3 * ASZ;

    const long zo = blockIdx.z;
    C += zo * Cbat;

    const int m0 = blockIdx.y * TBM;
    const int n0 = blockIdx.x * TBN;
    const int tid = threadIdx.x;
    const int warp = tid >> 5;
    const int lane = tid & 31;
    const int gid = lane >> 2;
    const int tig = lane & 3;
    const int wm = (warp >> 1) * 32;
    const int wn = (warp & 1) * 64;

    const uint32_t saBase = (uint32_t)__cvta_generic_to_shared(sAbuf);
    const uint32_t sbBase = (uint32_t)__cvta_generic_to_shared(sBbuf);

    float acc[2][8][4];
#pragma unroll
    for (int mt = 0; mt < 2; mt++)
#pragma unroll
        for (int nt = 0; nt < 8; nt++)
#pragma unroll
            for (int r = 0; r < 4; r++) acc[mt][nt][r] = 0.f;

    const int NTILES = K / TBK;

    for (int p = 0; p < npass; p++) {
        const bf16* A = (p ? A1 : A0) + zo * Abat;
        const bf16* B = (p ? B1 : B0) + zo * Bbat;

        const bf16* aSrc[2];
        const bf16* bSrc[2];
        uint32_t aOff[2], bOff[2];
        int bPred[2];
#pragma unroll
        for (int it = 0; it < 2; it++) {
            int idx = tid + it * 256;
            int row = idx >> 2, ch = idx & 3;
            aSrc[it] = A + (long)(m0 + row) * lda + ch * 8;
            int nrow = n0 + row;
            bPred[it] = (nrow < N) ? 16 : 0;
            if (nrow >= N) nrow = N - 1;
            bSrc[it] = B + (long)nrow * ldb + ch * 8;
            aOff[it] = (uint32_t)(row * PADK + ch * 8) * 2u;
            bOff[it] = (uint32_t)(row * PADK + ch * 8) * 2u;
        }

        if (p) __syncthreads();

#pragma unroll
        for (int s = 0; s < 2; s++) {
            const long kk = (long)s * TBK;
#pragma unroll
            for (int it = 0; it < 2; it++) {
                CP16(saBase + s * ASZ * 2u + aOff[it], aSrc[it] + kk, 16);
                CP16(sbBase + s * BSZ * 2u + bOff[it], bSrc[it] + kk, bPred[it]);
            }
            CP_COMMIT();
        }

        int cur = 0, pre = 2;
        for (int t = 0; t < NTILES; t++) {
            if (t + 1 < NTILES) CP_WAIT1(); else CP_WAIT0();
            __syncthreads();

            if (t + 2 < NTILES) {
                const long kk = (long)(t + 2) * TBK;
#pragma unroll
                for (int it = 0; it < 2; it++) {
                    CP16(saBase + pre * ASZ * 2u + aOff[it], aSrc[it] + kk, 16);
                    CP16(sbBase + pre * BSZ * 2u + bOff[it], bSrc[it] + kk, bPred[it]);
                }
                CP_COMMIT();
            }

            const bf16* cA = sAbuf + cur * ASZ;
            const bf16* cB = sBbuf + cur * BSZ;

            uint32_t a[2][2][4];
#pragma unroll
            for (int ks = 0; ks < 2; ks++)
#pragma unroll
                for (int mt = 0; mt < 2; mt++)
#pragma unroll
                    for (int r = 0; r < 4; r++) {
                        int row = wm + mt * 16 + gid + (r & 1) * 8;
                        int col = ks * 16 + tig * 2 + (r >> 1) * 8;
                        a[ks][mt][r] = *(const uint32_t*)&cA[row * PADK + col];
                    }

#pragma unroll
            for (int nt = 0; nt < 8; nt++) {
                uint32_t b[2][2];
#pragma unroll
                for (int ks = 0; ks < 2; ks++)
#pragma unroll
                    for (int r = 0; r < 2; r++) {
                        int n  = wn + nt * 8 + gid;
                        int kq = ks * 16 + tig * 2 + r * 8;
                        b[ks][r] = *(const uint32_t*)&cB[n * PADK + kq];
                    }
#pragma unroll
                for (int mt = 0; mt < 2; mt++) {
                    float f[4] = {0.f, 0.f, 0.f, 0.f};
                    MMA_BF16(f, a[0][mt], b[0]);
                    MMA_BF16(f, a[1][mt], b[1]);
                    float* c = acc[mt][nt];
                    c[0] += f[0]; c[1] += f[1]; c[2] += f[2]; c[3] += f[3];
                }
            }

            cur = (cur == 2) ? 0 : cur + 1;
            pre = (pre == 2) ? 0 : pre + 1;
        }
    }

#pragma unroll
    for (int mt = 0; mt < 2; mt++) {
        int row0 = m0 + wm + mt * 16 + gid;
#pragma unroll
        for (int nt = 0; nt < 8; nt++) {
            int n = n0 + wn + nt * 8 + tig * 2;
            if (n >= N) continue;
            float* c = acc[mt][nt];
            if (sizeof(TC) == 4) {
                float* Cf = (float*)C;
                Cf[(long)row0 * ldc + n]         = c[0];
                Cf[(long)row0 * ldc + n + 1]     = c[1];
                Cf[(long)(row0+8) * ldc + n]     = c[2];
                Cf[(long)(row0+8) * ldc + n + 1] = c[3];
            } else {
                bf16* Cb = (bf16*)C;
                *(__nv_bfloat162*)&Cb[(long)row0 * ldc + n] =
                    __nv_bfloat162(__float2bfloat16(c[0]), __float2bfloat16(c[1]));
                *(__nv_bfloat162*)&Cb[(long)(row0+8) * ldc + n] =
                    __nv_bfloat162(__float2bfloat16(c[2]), __float2bfloat16(c[3]));
            }
        }
    }
}

// ============================================================================
// out GEMM: C = A @ (B0 + B1)^T, shared-A dual-B single K-sweep (as R13).
// ============================================================================
__global__ __launch_bounds__(256)
void outb_gemm(const bf16* __restrict__ A, const bf16* __restrict__ B0,
               const bf16* __restrict__ B1, float* __restrict__ C,
               int M, int N, int K, long lda, long ldb, long ldc)
{
    constexpr int ASZ = TBM * PADK;
    constexpr int BSZ = TBN * PADK;

    extern __shared__ bf16 dsmb[];
    bf16* sAbuf  = dsmb;
    bf16* sB0buf = dsmb + 3 * ASZ;
    bf16* sB1buf = dsmb + 3 * ASZ + 3 * BSZ;

    const int m0 = blockIdx.y * TBM;
    const int n0 = blockIdx.x * TBN;
    const int tid = threadIdx.x;
    const int warp = tid >> 5;
    const int lane = tid & 31;
    const int gid = lane >> 2;
    const int tig = lane & 3;
    const int wm = (warp >> 1) * 32;
    const int wn = (warp & 1) * 64;

    const uint32_t saBase  = (uint32_t)__cvta_generic_to_shared(sAbuf);
    const uint32_t sb0Base = (uint32_t)__cvta_generic_to_shared(sB0buf);
    const uint32_t sb1Base = (uint32_t)__cvta_generic_to_shared(sB1buf);

    const bf16 *aSrc[2], *b0Src[2], *b1Src[2];
    uint32_t sOff[2];
#pragma unroll
    for (int it = 0; it < 2; it++) {
        int idx = tid + it * 256;
        int row = idx >> 2, ch = idx & 3;
        aSrc[it]  = A  + (long)(m0 + row) * lda + ch * 8;
        b0Src[it] = B0 + (long)(n0 + row) * ldb + ch * 8;
        b1Src[it] = B1 + (long)(n0 + row) * ldb + ch * 8;
        sOff[it] = (uint32_t)(row * PADK + ch * 8) * 2u;
    }

    float acc[2][8][4];
#pragma unroll
    for (int mt = 0; mt < 2; mt++)
#pragma unroll
        for (int nt = 0; nt < 8; nt++)
#pragma unroll
            for (int r = 0; r < 4; r++) acc[mt][nt][r] = 0.f;

    const int NTILES = K / TBK;

#pragma unroll
    for (int s = 0; s < 2; s++) {
        const long kk = (long)s * TBK;
#pragma unroll
        for (int it = 0; it < 2; it++) {
            CP16(saBase  + s * ASZ * 2u + sOff[it], aSrc[it]  + kk, 16);
            CP16(sb0Base + s * BSZ * 2u + sOff[it], b0Src[it] + kk, 16);
            CP16(sb1Base + s * BSZ * 2u + sOff[it], b1Src[it] + kk, 16);
        }
        CP_COMMIT();
    }

    int cur = 0, pre = 2;
    for (int t = 0; t < NTILES; t++) {
        if (t + 1 < NTILES) CP_WAIT1(); else CP_WAIT0();
        __syncthreads();

        if (t + 2 < NTILES) {
            const long kk = (long)(t + 2) * TBK;
#pragma unroll
            for (int it = 0; it < 2; it++) {
                CP16(saBase  + pre * ASZ * 2u + sOff[it], aSrc[it]  + kk, 16);
                CP16(sb0Base + pre * BSZ * 2u + sOff[it], b0Src[it] + kk, 16);
                CP16(sb1Base + pre * BSZ * 2u + sOff[it], b1Src[it] + kk, 16);
            }
            CP_COMMIT();
        }

        const bf16* cA  = sAbuf  + cur * ASZ;
        const bf16* cB0 = sB0buf + cur * BSZ;
        const bf16* cB1 = sB1buf + cur * BSZ;

        uint32_t a[2][2][4];
#pragma unroll
        for (int ks = 0; ks < 2; ks++)
#pragma unroll
            for (int mt = 0; mt < 2; mt++)
#pragma unroll
                for (int r = 0; r < 4; r++) {
                    int row = wm + mt * 16 + gid + (r & 1) * 8;
                    int col = ks * 16 + tig * 2 + (r >> 1) * 8;
                    a[ks][mt][r] = *(const uint32_t*)&cA[row * PADK + col];
                }

#pragma unroll
        for (int nt = 0; nt < 8; nt++) {
            uint32_t b0[2][2], b1[2][2];
#pragma unroll
            for (int ks = 0; ks < 2; ks++)
#pragma unroll
                for (int r = 0; r < 2; r++) {
                    int n  = wn + nt * 8 + gid;
                    int kq = ks * 16 + tig * 2 + r * 8;
                    b0[ks][r] = *(const uint32_t*)&cB0[n * PADK + kq];
                    b1[ks][r] = *(const uint32_t*)&cB1[n * PADK + kq];
                }
#pragma unroll
            for (int mt = 0; mt < 2; mt++) {
                float* c = acc[mt][nt];
                float f[4] = {0.f, 0.f, 0.f, 0.f};
                MMA_BF16(f, a[0][mt], b0[0]);
                MMA_BF16(f, a[1][mt], b0[1]);
                c[0] += f[0]; c[1] += f[1]; c[2] += f[2]; c[3] += f[3];
                float g[4] = {0.f, 0.f, 0.f, 0.f};
                MMA_BF16(g, a[0][mt], b1[0]);
                MMA_BF16(g, a[1][mt], b1[1]);
                c[0] += g[0]; c[1] += g[1]; c[2] += g[2]; c[3] += g[3];
            }
        }

        cur = (cur == 2) ? 0 : cur + 1;
        pre = (pre == 2) ? 0 : pre + 1;
    }

#pragma unroll
    for (int mt = 0; mt < 2; mt++) {
        int row0 = m0 + wm + mt * 16 + gid;
#pragma unroll
        for (int nt = 0; nt < 8; nt++) {
            int n = n0 + wn + nt * 8 + tig * 2;
            float* c = acc[mt][nt];
            C[(long)row0 * ldc + n]         = c[0];
            C[(long)row0 * ldc + n + 1]     = c[1];
            C[(long)(row0+8) * ldc + n]     = c[2];
            C[(long)(row0+8) * ldc + n + 1] = c[3];
        }
    }
}

// ---------------- pack q/k/v (bf16, head-major) + RoPE ----------------
__global__ void pack_k(const float* __restrict__ qu, const float* __restrict__ kvf,
                       const float* __restrict__ dwn,
                       bf16* __restrict__ q, bf16* __restrict__ k, bf16* __restrict__ v)
{
    const int s = blockIdx.x;
    const int tid = threadIdx.x;  // 256

    __shared__ float ssin[32], scos[32];
    if (tid < 32) {
        double invf_d = pow(10000.0, -((double)(2 * tid)) / 64.0);
        float invf = (float)invf_d;
        float ang = (float)s * invf;
        double a = (double)ang;
        ssin[tid] = (float)sin(a);
        scos[tid] = (float)cos(a);
    }
    __syncthreads();

    for (int idx = tid; idx < H_ * DV_; idx += 256) {
        int h = idx >> 7, d = idx & 127;
        q[((long)h * S_ + s) * DQK_ + d] = __float2bfloat16(qu[(long)s * NQU + idx]);
        k[((long)h * S_ + s) * DQK_ + d] = __float2bfloat16(kvf[(long)s * (H_*2*DV_) + idx]);
        v[((long)h * S_ + s) * DV_ + d]  = __float2bfloat16(kvf[(long)s * (H_*2*DV_) + H_*DV_ + idx]);
    }

    for (int idx = tid; idx < H_ * 32; idx += 256) {
        int h = idx >> 5, j = idx & 31;
        float x1 = qu[(long)s * NQU + 2048 + h * DR_ + j];
        float x2 = qu[(long)s * NQU + 2048 + h * DR_ + 32 + j];
        float sn = ssin[j], cs = scos[j];
        q[((long)h * S_ + s) * DQK_ + DV_ + j]      = __float2bfloat16(x1 * cs - x2 * sn);
        q[((long)h * S_ + s) * DQK_ + DV_ + 32 + j] = __float2bfloat16(x2 * cs + x1 * sn);
    }

    if (tid < 32) {
        int j = tid;
        float x1 = dwn[(long)s * NDWN + 1024 + j];
        float x2 = dwn[(long)s * NDWN + 1024 + 32 + j];
        float sn = ssin[j], cs = scos[j];
        float r1 = x1 * cs - x2 * sn;
        float r2 = x2 * cs + x1 * sn;
#pragma unroll
        for (int h = 0; h < H_; h++) {
            k[((long)h * S_ + s) * DQK_ + DV_ + j]      = __float2bfloat16(r1);
            k[((long)h * S_ + s) * DQK_ + DV_ + 32 + j] = __float2bfloat16(r2);
        }
    }
}

// ---------------- transpose v [h][s][d] -> vT [h][d][s] ----------------
__global__ void transpose_v(const bf16* __restrict__ v, bf16* __restrict__ vT)
{
    __shared__ bf16 t[32][33];
    const int h = blockIdx.z;
    const int s0 = blockIdx.x * 32;
    const int d0 = blockIdx.y * 32;
    const int tx = threadIdx.x, ty = threadIdx.y;  // (32, 8)
#pragma unroll
    for (int j = 0; j < 32; j += 8)
        t[ty + j][tx] = v[((long)h * S_ + s0 + ty + j) * DV_ + d0 + tx];
    __syncthreads();
#pragma unroll
    for (int j = 0; j < 32; j += 8)
        vT[((long)h * DV_ + d0 + ty + j) * S_ + s0 + tx] = t[tx][ty + j];
}

// ---------------- softmax over bf16 logits -> bf16 probs ----------------
__global__ void softmax_k(const bf16* __restrict__ L, bf16* __restrict__ P, float scale)
{
    const int s = blockIdx.x;
    const int h = blockIdx.y;
    const bf16* row = L + ((long)h * S_ + s) * S_;
    bf16* prow = P + ((long)h * S_ + s) * S_;
    const int tid = threadIdx.x;

    float v[8];
    float mx = -1e30f;
#pragma unroll
    for (int i = 0; i < 8; i++) {
        v[i] = __bfloat162float(row[tid + i * 256]) * scale;
        mx = fmaxf(mx, v[i]);
    }
    __shared__ float red[256];
    red[tid] = mx;
    __syncthreads();
    for (int st = 128; st > 0; st >>= 1) {
        if (tid < st) red[tid] = fmaxf(red[tid], red[tid + st]);
        __syncthreads();
    }
    mx = red[0];
    __syncthreads();

    float sum = 0.f;
#pragma unroll
    for (int i = 0; i < 8; i++) {
        v[i] = expf(v[i] - mx);
        sum += v[i];
    }
    red[tid] = sum;
    __syncthreads();
    for (int st = 128; st > 0; st >>= 1) {
        if (tid < st) red[tid] += red[tid + st];
        __syncthreads();
    }
    float tot = red[0];
#pragma unroll
    for (int i = 0; i < 8; i++)
        prow[tid + i * 256] = __float2bfloat16(v[i] / tot);
}

// ---------------- orchestration ----------------
extern "C" void kernel_launch(void* const* d_in, const int* in_sizes, int n_in,
                              void* d_out, int out_size)
{
    (void)in_sizes; (void)n_in; (void)out_size;
    const float* x       = (const float*)d_in[0];
    const float* wq_down = (const float*)d_in[1];
    const float* wq_up   = (const float*)d_in[2];
    const float* wq_rope = (const float*)d_in[3];
    const float* wkv_down= (const float*)d_in[4];
    const float* wkv_up  = (const float*)d_in[5];
    const float* wk_rope = (const float*)d_in[6];
    const float* wo      = (const float*)d_in[7];
    float* out = (float*)d_out;

    float *wd, *wu, *dwn, *qu, *kvf;
    cudaGetSymbolAddress((void**)&wd,  g_wd);
    cudaGetSymbolAddress((void**)&wu,  g_wu);
    cudaGetSymbolAddress((void**)&dwn, g_down);
    cudaGetSymbolAddress((void**)&qu,  g_qu);
    cudaGetSymbolAddress((void**)&kvf, g_kv);

    bf16 *q, *k, *v, *vT, *logits, *probs, *attn_bf, *wo_h, *wo_l;
    cudaGetSymbolAddress((void**)&q, g_q);
    cudaGetSymbolAddress((void**)&k, g_k);
    cudaGetSymbolAddress((void**)&v, g_v);
    cudaGetSymbolAddress((void**)&vT, g_vT);
    cudaGetSymbolAddress((void**)&logits, g_logits);
    cudaGetSymbolAddress((void**)&probs, g_probs);
    cudaGetSymbolAddress((void**)&attn_bf, g_attn_bf);
    cudaGetSymbolAddress((void**)&wo_h, g_wo_h);
    cudaGetSymbolAddress((void**)&wo_l, g_wo_l);

    // dynamic smem sizes (3-stage)
    const int SM64  = 3 * (64 * FPAD + FBN * FPAD) * 4;        // 46080
    const int SM128 = 3 * (128 * FPAD + FBN * FPAD) * 4;       // 61440
    const int SMBF  = 3 * (TBM * PADK + TBN * PADK) * 2;       // 61440
    const int SMOUT = 3 * (TBM * PADK + 2 * TBN * PADK) * 2;   // 92160
    cudaFuncSetAttribute(tf32_gemm<64>,  cudaFuncAttributeMaxDynamicSharedMemorySize, SM64);
    cudaFuncSetAttribute(tf32_dual, cudaFuncAttributeMaxDynamicSharedMemorySize, SM128);
    cudaFuncSetAttribute(bf16_gemm<bf16>,  cudaFuncAttributeMaxDynamicSharedMemorySize, SMBF);
    cudaFuncSetAttribute(bf16_gemm<float>, cudaFuncAttributeMaxDynamicSharedMemorySize, SMBF);
    cudaFuncSetAttribute(outb_gemm, cudaFuncAttributeMaxDynamicSharedMemorySize, SMOUT);

    dim3 blk(256);
    auto bgrid = [](int M, int N, int batch) {
        return dim3((N + TBN - 1) / TBN, (M + TBM - 1) / TBM, batch);
    };

    // 0) concat weights (D2D) + wo bf16 split
    cudaMemcpyAsync(wd,                 wq_down,  (size_t)QR_ * E_ * 4, cudaMemcpyDeviceToDevice);
    cudaMemcpyAsync(wd + (size_t)QR_*E_, wkv_down, (size_t)KVR_ * E_ * 4, cudaMemcpyDeviceToDevice);
    cudaMemcpyAsync(wd + (size_t)(QR_+KVR_)*E_, wk_rope, (size_t)DR_ * E_ * 4, cudaMemcpyDeviceToDevice);
    cudaMemcpyAsync(wu,                  wq_up,   (size_t)H_*DV_ * QR_ * 4, cudaMemcpyDeviceToDevice);
    cudaMemcpyAsync(wu + (size_t)H_*DV_*QR_, wq_rope, (size_t)H_*DR_ * QR_ * 4, cudaMemcpyDeviceToDevice);
    split_bf_k<<<592, 256>>>(wo, wo_h, wo_l, (long)E_*H_*DV_);

    // 1) fused down projection: [cq|ckv|kr] = x @ wd^T  (BM=64: 9x32 = 288 CTAs)
    tf32_gemm<64><<<dim3((NDWN + FBN - 1) / FBN, S_ / 64, 1), blk, SM64>>>(
        x, wd, dwn, S_, NDWN, E_, E_, E_, NDWN);

    // 2) fused qu-up + kv-up in ONE launch (384 + 512 = 896 CTAs, 3.03 waves)
    tf32_dual<<<896, blk, SM128>>>(
        dwn, wu, qu,                 // qu: [qc|qr] = cq @ wu^T
        dwn + QR_, wkv_up, kvf,      // kv: ckv @ wkv_up^T
        QR_, NDWN, QR_);

    // 3) pack + rope -> head-major bf16 q/k/v ; transpose v
    pack_k<<<S_, 256>>>(qu, kvf, dwn, q, k, v);
    {
        dim3 tg(S_/32, DV_/32, H_);
        dim3 tb(32, 8);
        transpose_v<<<tg, tb>>>(v, vT);
    }

    // 4) logits[h] = bf16( q[h] @ k[h]^T )
    bf16_gemm<bf16><<<bgrid(S_, S_, H_), blk, SMBF>>>(
        q, q, k, k, logits, 1, S_, S_, DQK_, DQK_, DQK_, S_,
        (long)S_*DQK_, (long)S_*DQK_, (long)S_*S_);

    // 5) softmax
    {
        dim3 g(S_, H_);
        softmax_k<<<g, 256>>>(logits, probs, 1.0f / sqrtf((float)(DV_ + DR_)));
    }

    // 6) attn[h] = bf16( probs[h] @ v[h] ), stored bf16 interleaved [s][h*DV]
    bf16_gemm<bf16><<<bgrid(S_, DV_, H_), blk, SMBF>>>(
        probs, probs, vT, vT, attn_bf, 1, S_, DV_, S_, S_, S_, (long)H_*DV_,
        (long)S_*S_, (long)DV_*S_, DV_);

    // 7) out = attn @ (wo_h + wo_l)^T : shared-A dual-B single sweep
    outb_gemm<<<bgrid(S_, E_, 1), blk, SMOUT>>>(
        attn_bf, wo_h, wo_l, out, S_, E_, H_*DV_, H_*DV_, H_*DV_, E_);
}

// round 15
// speedup vs baseline: 1.2967x; 1.0257x over previous
#include <cuda_runtime.h>
#include <cuda_bf16.h>
#include <math.h>
#include <stdint.h>

#define S_  2048
#define E_  2048
#define H_  16
#define QR_ 512
#define KVR_ 512
#define DR_ 64
#define DV_ 128
#define DQK_ 192   // DV + DR
#define NDWN 1088  // QR + KVR + DR
#define NQU  3072  // H*DV + H*DR

typedef __nv_bfloat16 bf16;

// ---------------- scratch (device globals) ----------------
__device__ float g_wd [NDWN * E_];
__device__ float g_wu [NQU * QR_];
__device__ float g_down[S_ * NDWN];
__device__ float g_qu [S_ * NQU];
__device__ float g_kv [S_ * (H_*2*DV_)];
__device__ bf16 g_wo_h[E_*H_*DV_], g_wo_l[E_*H_*DV_];
__device__ bf16 g_q[(size_t)H_ * S_ * DQK_];
__device__ bf16 g_k[(size_t)H_ * S_ * DQK_];
__device__ bf16 g_v[(size_t)H_ * S_ * DV_];
__device__ bf16 g_vT[(size_t)H_ * DV_ * S_];
__device__ bf16 g_logits[(size_t)H_ * S_ * S_];
__device__ bf16 g_probs [(size_t)H_ * S_ * S_];
__device__ bf16 g_attn_bf[(size_t)S_ * H_ * DV_];

// ---------------- helpers ----------------
__device__ __forceinline__ uint32_t f2tf32(float x) {
    uint32_t r;
    asm("cvt.rna.tf32.f32 %0, %1;" : "=r"(r) : "f"(x));
    return r;
}

#define MMA_TF32(c, a, b) \
    asm volatile( \
        "mma.sync.aligned.m16n8k8.row.col.f32.tf32.tf32.f32 " \
        "{%0,%1,%2,%3}, {%4,%5,%6,%7}, {%8,%9}, {%0,%1,%2,%3};" \
        : "+f"((c)[0]), "+f"((c)[1]), "+f"((c)[2]), "+f"((c)[3]) \
        : "r"((a)[0]), "r"((a)[1]), "r"((a)[2]), "r"((a)[3]), \
          "r"((b)[0]), "r"((b)[1]))

#define MMA_BF16(c, a, b) \
    asm volatile( \
        "mma.sync.aligned.m16n8k16.row.col.f32.bf16.bf16.f32 " \
        "{%0,%1,%2,%3}, {%4,%5,%6,%7}, {%8,%9}, {%0,%1,%2,%3};" \
        : "+f"((c)[0]), "+f"((c)[1]), "+f"((c)[2]), "+f"((c)[3]) \
        : "r"((a)[0]), "r"((a)[1]), "r"((a)[2]), "r"((a)[3]), \
          "r"((b)[0]), "r"((b)[1]))

#define CP16(dst, src, nbytes) \
    asm volatile("cp.async.cg.shared.global [%0], [%1], 16, %2;" \
                 :: "r"(dst), "l"(src), "r"(nbytes))
#define CP_COMMIT()  asm volatile("cp.async.commit_group;")
#define CP_WAIT0()   asm volatile("cp.async.wait_group 0;")
#define CP_WAIT1()   asm volatile("cp.async.wait_group 1;")

__device__ __forceinline__ __nv_bfloat162 f2bf2(float a, float b) {
    return __nv_bfloat162(__float2bfloat16(a), __float2bfloat16(b));
}

__global__ void split_bf_k(const float* __restrict__ src, bf16* __restrict__ hi,
                           bf16* __restrict__ lo, long n)
{
    long i = (long)blockIdx.x * blockDim.x + threadIdx.x;
    long stride = (long)gridDim.x * blockDim.x;
    for (; i < n; i += stride) {
        float v = src[i];
        bf16 h = __float2bfloat16(v);
        hi[i] = h;
        lo[i] = __float2bfloat16(v - __bfloat162float(h));
    }
}

// ============================================================================
// 3xTF32 GEMM, BMv in {64,128}, 3-stage cp.async pipeline (wait_group 1).
// ============================================================================
#define FBN 128
#define FBK 16
#define FPAD 20

template <int BMv>
__global__ __launch_bounds__(256)
void tf32_gemm(const float* __restrict__ A, const float* __restrict__ B,
               float* __restrict__ C, int M, int N, int K,
               long lda, long ldb, long ldc)
{
    constexpr int MT = 2;
    constexpr int NT = (BMv == 128) ? 8 : 4;
    constexpr int ACH = BMv * 4 / 256;
    constexpr int ASZ = BMv * FPAD;
    constexpr int BSZ = FBN * FPAD;

    extern __shared__ float dsm[];
    float* sAbuf = dsm;
    float* sBbuf = dsm + 3 * ASZ;

    const int m0 = blockIdx.y * BMv;
    const int n0 = blockIdx.x * FBN;
    const int tid = threadIdx.x;
    const int warp = tid >> 5;
    const int lane = tid & 31;
    const int gid = lane >> 2;
    const int tig = lane & 3;
    const int wm = (BMv == 128) ? (warp >> 1) * 32 : (warp & 1) * 32;
    const int wn = (BMv == 128) ? (warp & 1) * 64  : (warp >> 1) * 32;

    const float* aSrc[ACH];
    uint32_t aOff[ACH];
    const float* bSrc[2];
    uint32_t bOff[2];
    int bPred[2];
    const uint32_t saBase = (uint32_t)__cvta_generic_to_shared(sAbuf);
    const uint32_t sbBase = (uint32_t)__cvta_generic_to_shared(sBbuf);
#pragma unroll
    for (int it = 0; it < ACH; it++) {
        int idx = tid + it * 256;
        int row = idx >> 2, ch = idx & 3;
        aSrc[it] = A + (long)(m0 + row) * lda + ch * 4;
        aOff[it] = (uint32_t)(row * FPAD + ch * 4) * 4u;
    }
#pragma unroll
    for (int it = 0; it < 2; it++) {
        int idx = tid + it * 256;
        int row = idx >> 2, ch = idx & 3;
        int nrow = n0 + row;
        bPred[it] = (nrow < N) ? 16 : 0;
        if (nrow >= N) nrow = N - 1;
        bSrc[it] = B + (long)nrow * ldb + ch * 4;
        bOff[it] = (uint32_t)(row * FPAD + ch * 4) * 4u;
    }

    float acc[MT][NT][4];
#pragma unroll
    for (int mt = 0; mt < MT; mt++)
#pragma unroll
        for (int nt = 0; nt < NT; nt++)
#pragma unroll
            for (int r = 0; r < 4; r++) acc[mt][nt][r] = 0.f;

    const int NTILES = K / FBK;

#pragma unroll
    for (int s = 0; s < 2; s++) {
        const long kk = (long)s * FBK;
#pragma unroll
        for (int it = 0; it < ACH; it++)
            CP16(saBase + s * ASZ * 4u + aOff[it], aSrc[it] + kk, 16);
#pragma unroll
        for (int it = 0; it < 2; it++)
            CP16(sbBase + s * BSZ * 4u + bOff[it], bSrc[it] + kk, bPred[it]);
        CP_COMMIT();
    }

    int cur = 0, pre = 2;
    for (int t = 0; t < NTILES; t++) {
        if (t + 1 < NTILES) CP_WAIT1(); else CP_WAIT0();
        __syncthreads();

        if (t + 2 < NTILES) {
            const long kk = (long)(t + 2) * FBK;
#pragma unroll
            for (int it = 0; it < ACH; it++)
                CP16(saBase + pre * ASZ * 4u + aOff[it], aSrc[it] + kk, 16);
#pragma unroll
            for (int it = 0; it < 2; it++)
                CP16(sbBase + pre * BSZ * 4u + bOff[it], bSrc[it] + kk, bPred[it]);
            CP_COMMIT();
        }

        const float* cA = sAbuf + cur * ASZ;
        const float* cB = sBbuf + cur * BSZ;

        uint32_t ah[2][MT][4], al[2][MT][4];
#pragma unroll
        for (int ks = 0; ks < 2; ks++)
#pragma unroll
            for (int mt = 0; mt < MT; mt++)
#pragma unroll
                for (int r = 0; r < 4; r++) {
                    int row = wm + mt * 16 + gid + (r & 1) * 8;
                    int col = ks * 8 + tig + (r >> 1) * 4;
                    float v = cA[row * FPAD + col];
                    uint32_t h = f2tf32(v);
                    ah[ks][mt][r] = h;
                    al[ks][mt][r] = f2tf32(v - __uint_as_float(h));
                }

#pragma unroll
        for (int nt = 0; nt < NT; nt++) {
            uint32_t bh[2][2], bl[2][2];
#pragma unroll
            for (int ks = 0; ks < 2; ks++)
#pragma unroll
                for (int r = 0; r < 2; r++) {
                    int n = wn + nt * 8 + gid;
                    int kq = ks * 8 + tig + r * 4;
                    float v = cB[n * FPAD + kq];
                    uint32_t h = f2tf32(v);
                    bh[ks][r] = h;
                    bl[ks][r] = f2tf32(v - __uint_as_float(h));
                }
#pragma unroll
            for (int mt = 0; mt < MT; mt++) {
                float f[4] = {0.f, 0.f, 0.f, 0.f};
#pragma unroll
                for (int ks = 0; ks < 2; ks++) {
                    MMA_TF32(f, ah[ks][mt], bh[ks]);
                    MMA_TF32(f, ah[ks][mt], bl[ks]);
                    MMA_TF32(f, al[ks][mt], bh[ks]);
                }
                float* c = acc[mt][nt];
                c[0] += f[0]; c[1] += f[1]; c[2] += f[2]; c[3] += f[3];
            }
        }

        cur = (cur == 2) ? 0 : cur + 1;
        pre = (pre == 2) ? 0 : pre + 1;
    }

#pragma unroll
    for (int mt = 0; mt < MT; mt++) {
        int row0 = m0 + wm + mt * 16 + gid;
#pragma unroll
        for (int nt = 0; nt < NT; nt++) {
            int n = n0 + wn + nt * 8 + tig * 2;
            if (n >= N) continue;
            float* c = acc[mt][nt];
            C[(long)row0 * ldc + n]         = c[0];
            C[(long)row0 * ldc + n + 1]     = c[1];
            C[(long)(row0+8) * ldc + n]     = c[2];
            C[(long)(row0+8) * ldc + n + 1] = c[3];
        }
    }
}

// ============================================================================
// Fused qu-up + kv-up (one flattened launch, BM=128 both) — as R14.
// ============================================================================
__global__ __launch_bounds__(256)
void tf32_dual(const float* __restrict__ A0, const float* __restrict__ B0, float* __restrict__ C0,
               const float* __restrict__ A1, const float* __restrict__ B1, float* __restrict__ C1,
               int K, long lda, long ldb)
{
    constexpr int ASZ = 128 * FPAD;
    constexpr int BSZ = FBN * FPAD;

    extern __shared__ float dsm[];
    float* sAbuf = dsm;
    float* sBbuf = dsm + 3 * ASZ;

    const int bid = blockIdx.x;
    const float *A, *B;
    float* C;
    int m0, n0;
    long ldc;
    if (bid < 384) {
        A = A0; B = B0; C = C0; ldc = NQU;
        m0 = (bid / 24) * 128;  n0 = (bid % 24) * 128;
    } else {
        int b = bid - 384;
        A = A1; B = B1; C = C1; ldc = H_*2*DV_;
        m0 = (b / 32) * 128;  n0 = (b % 32) * 128;
    }

    const int tid = threadIdx.x;
    const int warp = tid >> 5;
    const int lane = tid & 31;
    const int gid = lane >> 2;
    const int tig = lane & 3;
    const int wm = (warp >> 1) * 32;
    const int wn = (warp & 1) * 64;

    const float* aSrc[2];
    const float* bSrc[2];
    uint32_t sOff[2];
    const uint32_t saBase = (uint32_t)__cvta_generic_to_shared(sAbuf);
    const uint32_t sbBase = (uint32_t)__cvta_generic_to_shared(sBbuf);
#pragma unroll
    for (int it = 0; it < 2; it++) {
        int idx = tid + it * 256;
        int row = idx >> 2, ch = idx & 3;
        aSrc[it] = A + (long)(m0 + row) * lda + ch * 4;
        bSrc[it] = B + (long)(n0 + row) * ldb + ch * 4;
        sOff[it] = (uint32_t)(row * FPAD + ch * 4) * 4u;
    }

    float acc[2][8][4];
#pragma unroll
    for (int mt = 0; mt < 2; mt++)
#pragma unroll
        for (int nt = 0; nt < 8; nt++)
#pragma unroll
            for (int r = 0; r < 4; r++) acc[mt][nt][r] = 0.f;

    const int NTILES = K / FBK;

#pragma unroll
    for (int s = 0; s < 2; s++) {
        const long kk = (long)s * FBK;
#pragma unroll
        for (int it = 0; it < 2; it++) {
            CP16(saBase + s * ASZ * 4u + sOff[it], aSrc[it] + kk, 16);
            CP16(sbBase + s * BSZ * 4u + sOff[it], bSrc[it] + kk, 16);
        }
        CP_COMMIT();
    }

    int cur = 0, pre = 2;
    for (int t = 0; t < NTILES; t++) {
        if (t + 1 < NTILES) CP_WAIT1(); else CP_WAIT0();
        __syncthreads();

        if (t + 2 < NTILES) {
            const long kk = (long)(t + 2) * FBK;
#pragma unroll
            for (int it = 0; it < 2; it++) {
                CP16(saBase + pre * ASZ * 4u + sOff[it], aSrc[it] + kk, 16);
                CP16(sbBase + pre * BSZ * 4u + sOff[it], bSrc[it] + kk, 16);
            }
            CP_COMMIT();
        }

        const float* cA = sAbuf + cur * ASZ;
        const float* cB = sBbuf + cur * BSZ;

        uint32_t ah[2][2][4], al[2][2][4];
#pragma unroll
        for (int ks = 0; ks < 2; ks++)
#pragma unroll
            for (int mt = 0; mt < 2; mt++)
#pragma unroll
                for (int r = 0; r < 4; r++) {
                    int row = wm + mt * 16 + gid + (r & 1) * 8;
                    int col = ks * 8 + tig + (r >> 1) * 4;
                    float v = cA[row * FPAD + col];
                    uint32_t h = f2tf32(v);
                    ah[ks][mt][r] = h;
                    al[ks][mt][r] = f2tf32(v - __uint_as_float(h));
                }

#pragma unroll
        for (int nt = 0; nt < 8; nt++) {
            uint32_t bh[2][2], bl[2][2];
#pragma unroll
            for (int ks = 0; ks < 2; ks++)
#pragma unroll
                for (int r = 0; r < 2; r++) {
                    int n = wn + nt * 8 + gid;
                    int kq = ks * 8 + tig + r * 4;
                    float v = cB[n * FPAD + kq];
                    uint32_t h = f2tf32(v);
                    bh[ks][r] = h;
                    bl[ks][r] = f2tf32(v - __uint_as_float(h));
                }
#pragma unroll
            for (int mt = 0; mt < 2; mt++) {
                float f[4] = {0.f, 0.f, 0.f, 0.f};
#pragma unroll
                for (int ks = 0; ks < 2; ks++) {
                    MMA_TF32(f, ah[ks][mt], bh[ks]);
                    MMA_TF32(f, ah[ks][mt], bl[ks]);
                    MMA_TF32(f, al[ks][mt], bh[ks]);
                }
                float* c = acc[mt][nt];
                c[0] += f[0]; c[1] += f[1]; c[2] += f[2]; c[3] += f[3];
            }
        }

        cur = (cur == 2) ? 0 : cur + 1;
        pre = (pre == 2) ? 0 : pre + 1;
    }

#pragma unroll
    for (int mt = 0; mt < 2; mt++) {
        int row0 = m0 + wm + mt * 16 + gid;
#pragma unroll
        for (int nt = 0; nt < 8; nt++) {
            int n = n0 + wn + nt * 8 + tig * 2;
            float* c = acc[mt][nt];
            C[(long)row0 * ldc + n]         = c[0];
            C[(long)row0 * ldc + n + 1]     = c[1];
            C[(long)(row0+8) * ldc + n]     = c[2];
            C[(long)(row0+8) * ldc + n + 1] = c[3];
        }
    }
}

// ============================================================================
// bf16 tensor-core GEMM, 3-stage cp.async pipeline per pass (as R13/R14).
// ============================================================================
#define TBM 128
#define TBN 128
#define TBK 32
#define PADK 40

template <typename TC>
__global__ __launch_bounds__(256)
void bf16_gemm(const bf16* __restrict__ A0, const bf16* __restrict__ A1,
               const bf16* __restrict__ B0, const bf16* __restrict__ B1,
               TC* __restrict__ C, int npass, int M, int N, int K,
               long lda, long ldb, long ldc, long Abat, long Bbat, long Cbat)
{
    constexpr int ASZ = TBM * PADK;
    constexpr int BSZ = TBN * PADK;

    extern __shared__ bf16 dsmb[];
    bf16* sAbuf = dsmb;
    bf16* sBbuf = dsmb + 3 * ASZ;

    const long zo = blockIdx.z;
    C += zo * Cbat;

    const int m0 = blockIdx.y * TBM;
    const int n0 = blockIdx.x * TBN;
    const int tid = threadIdx.x;
    const int warp = tid >> 5;
    const int lane = tid & 31;
    const int gid = lane >> 2;
    const int tig = lane & 3;
    const int wm = (warp >> 1) * 32;
    const int wn = (warp & 1) * 64;

    const uint32_t saBase = (uint32_t)__cvta_generic_to_shared(sAbuf);
    const uint32_t sbBase = (uint32_t)__cvta_generic_to_shared(sBbuf);

    float acc[2][8][4];
#pragma unroll
    for (int mt = 0; mt < 2; mt++)
#pragma unroll
        for (int nt = 0; nt < 8; nt++)
#pragma unroll
            for (int r = 0; r < 4; r++) acc[mt][nt][r] = 0.f;

    const int NTILES = K / TBK;

    for (int p = 0; p < npass; p++) {
        const bf16* A = (p ? A1 : A0) + zo * Abat;
        const bf16* B = (p ? B1 : B0) + zo * Bbat;

        const bf16* aSrc[2];
        const bf16* bSrc[2];
        uint32_t aOff[2], bOff[2];
        int bPred[2];
#pragma unroll
        for (int it = 0; it < 2; it++) {
            int idx = tid + it * 256;
            int row = idx >> 2, ch = idx & 3;
            aSrc[it] = A + (long)(m0 + row) * lda + ch * 8;
            int nrow = n0 + row;
            bPred[it] = (nrow < N) ? 16 : 0;
            if (nrow >= N) nrow = N - 1;
            bSrc[it] = B + (long)nrow * ldb + ch * 8;
            aOff[it] = (uint32_t)(row * PADK + ch * 8) * 2u;
            bOff[it] = (uint32_t)(row * PADK + ch * 8) * 2u;
        }

        if (p) __syncthreads();

#pragma unroll
        for (int s = 0; s < 2; s++) {
            const long kk = (long)s * TBK;
#pragma unroll
            for (int it = 0; it < 2; it++) {
                CP16(saBase + s * ASZ * 2u + aOff[it], aSrc[it] + kk, 16);
                CP16(sbBase + s * BSZ * 2u + bOff[it], bSrc[it] + kk, bPred[it]);
            }
            CP_COMMIT();
        }

        int cur = 0, pre = 2;
        for (int t = 0; t < NTILES; t++) {
            if (t + 1 < NTILES) CP_WAIT1(); else CP_WAIT0();
            __syncthreads();

            if (t + 2 < NTILES) {
                const long kk = (long)(t + 2) * TBK;
#pragma unroll
                for (int it = 0; it < 2; it++) {
                    CP16(saBase + pre * ASZ * 2u + aOff[it], aSrc[it] + kk, 16);
                    CP16(sbBase + pre * BSZ * 2u + bOff[it], bSrc[it] + kk, bPred[it]);
                }
                CP_COMMIT();
            }

            const bf16* cA = sAbuf + cur * ASZ;
            const bf16* cB = sBbuf + cur * BSZ;

            uint32_t a[2][2][4];
#pragma unroll
            for (int ks = 0; ks < 2; ks++)
#pragma unroll
                for (int mt = 0; mt < 2; mt++)
#pragma unroll
                    for (int r = 0; r < 4; r++) {
                        int row = wm + mt * 16 + gid + (r & 1) * 8;
                        int col = ks * 16 + tig * 2 + (r >> 1) * 8;
                        a[ks][mt][r] = *(const uint32_t*)&cA[row * PADK + col];
                    }

#pragma unroll
            for (int nt = 0; nt < 8; nt++) {
                uint32_t b[2][2];
#pragma unroll
                for (int ks = 0; ks < 2; ks++)
#pragma unroll
                    for (int r = 0; r < 2; r++) {
                        int n  = wn + nt * 8 + gid;
                        int kq = ks * 16 + tig * 2 + r * 8;
                        b[ks][r] = *(const uint32_t*)&cB[n * PADK + kq];
                    }
#pragma unroll
                for (int mt = 0; mt < 2; mt++) {
                    float f[4] = {0.f, 0.f, 0.f, 0.f};
                    MMA_BF16(f, a[0][mt], b[0]);
                    MMA_BF16(f, a[1][mt], b[1]);
                    float* c = acc[mt][nt];
                    c[0] += f[0]; c[1] += f[1]; c[2] += f[2]; c[3] += f[3];
                }
            }

            cur = (cur == 2) ? 0 : cur + 1;
            pre = (pre == 2) ? 0 : pre + 1;
        }
    }

#pragma unroll
    for (int mt = 0; mt < 2; mt++) {
        int row0 = m0 + wm + mt * 16 + gid;
#pragma unroll
        for (int nt = 0; nt < 8; nt++) {
            int n = n0 + wn + nt * 8 + tig * 2;
            if (n >= N) continue;
            float* c = acc[mt][nt];
            if (sizeof(TC) == 4) {
                float* Cf = (float*)C;
                Cf[(long)row0 * ldc + n]         = c[0];
                Cf[(long)row0 * ldc + n + 1]     = c[1];
                Cf[(long)(row0+8) * ldc + n]     = c[2];
                Cf[(long)(row0+8) * ldc + n + 1] = c[3];
            } else {
                bf16* Cb = (bf16*)C;
                *(__nv_bfloat162*)&Cb[(long)row0 * ldc + n] =
                    __nv_bfloat162(__float2bfloat16(c[0]), __float2bfloat16(c[1]));
                *(__nv_bfloat162*)&Cb[(long)(row0+8) * ldc + n] =
                    __nv_bfloat162(__float2bfloat16(c[2]), __float2bfloat16(c[3]));
            }
        }
    }
}

// ============================================================================
// out GEMM: C = A @ (B0 + B1)^T, shared-A dual-B single K-sweep (as R13/R14).
// ============================================================================
__global__ __launch_bounds__(256)
void outb_gemm(const bf16* __restrict__ A, const bf16* __restrict__ B0,
               const bf16* __restrict__ B1, float* __restrict__ C,
               int M, int N, int K, long lda, long ldb, long ldc)
{
    constexpr int ASZ = TBM * PADK;
    constexpr int BSZ = TBN * PADK;

    extern __shared__ bf16 dsmb[];
    bf16* sAbuf  = dsmb;
    bf16* sB0buf = dsmb + 3 * ASZ;
    bf16* sB1buf = dsmb + 3 * ASZ + 3 * BSZ;

    const int m0 = blockIdx.y * TBM;
    const int n0 = blockIdx.x * TBN;
    const int tid = threadIdx.x;
    const int warp = tid >> 5;
    const int lane = tid & 31;
    const int gid = lane >> 2;
    const int tig = lane & 3;
    const int wm = (warp >> 1) * 32;
    const int wn = (warp & 1) * 64;

    const uint32_t saBase  = (uint32_t)__cvta_generic_to_shared(sAbuf);
    const uint32_t sb0Base = (uint32_t)__cvta_generic_to_shared(sB0buf);
    const uint32_t sb1Base = (uint32_t)__cvta_generic_to_shared(sB1buf);

    const bf16 *aSrc[2], *b0Src[2], *b1Src[2];
    uint32_t sOff[2];
#pragma unroll
    for (int it = 0; it < 2; it++) {
        int idx = tid + it * 256;
        int row = idx >> 2, ch = idx & 3;
        aSrc[it]  = A  + (long)(m0 + row) * lda + ch * 8;
        b0Src[it] = B0 + (long)(n0 + row) * ldb + ch * 8;
        b1Src[it] = B1 + (long)(n0 + row) * ldb + ch * 8;
        sOff[it] = (uint32_t)(row * PADK + ch * 8) * 2u;
    }

    float acc[2][8][4];
#pragma unroll
    for (int mt = 0; mt < 2; mt++)
#pragma unroll
        for (int nt = 0; nt < 8; nt++)
#pragma unroll
            for (int r = 0; r < 4; r++) acc[mt][nt][r] = 0.f;

    const int NTILES = K / TBK;

#pragma unroll
    for (int s = 0; s < 2; s++) {
        const long kk = (long)s * TBK;
#pragma unroll
        for (int it = 0; it < 2; it++) {
            CP16(saBase  + s * ASZ * 2u + sOff[it], aSrc[it]  + kk, 16);
            CP16(sb0Base + s * BSZ * 2u + sOff[it], b0Src[it] + kk, 16);
            CP16(sb1Base + s * BSZ * 2u + sOff[it], b1Src[it] + kk, 16);
        }
        CP_COMMIT();
    }

    int cur = 0, pre = 2;
    for (int t = 0; t < NTILES; t++) {
        if (t + 1 < NTILES) CP_WAIT1(); else CP_WAIT0();
        __syncthreads();

        if (t + 2 < NTILES) {
            const long kk = (long)(t + 2) * TBK;
#pragma unroll
            for (int it = 0; it < 2; it++) {
                CP16(saBase  + pre * ASZ * 2u + sOff[it], aSrc[it]  + kk, 16);
                CP16(sb0Base + pre * BSZ * 2u + sOff[it], b0Src[it] + kk, 16);
                CP16(sb1Base + pre * BSZ * 2u + sOff[it], b1Src[it] + kk, 16);
            }
            CP_COMMIT();
        }

        const bf16* cA  = sAbuf  + cur * ASZ;
        const bf16* cB0 = sB0buf + cur * BSZ;
        const bf16* cB1 = sB1buf + cur * BSZ;

        uint32_t a[2][2][4];
#pragma unroll
        for (int ks = 0; ks < 2; ks++)
#pragma unroll
            for (int mt = 0; mt < 2; mt++)
#pragma unroll
                for (int r = 0; r < 4; r++) {
                    int row = wm + mt * 16 + gid + (r & 1) * 8;
                    int col = ks * 16 + tig * 2 + (r >> 1) * 8;
                    a[ks][mt][r] = *(const uint32_t*)&cA[row * PADK + col];
                }

#pragma unroll
        for (int nt = 0; nt < 8; nt++) {
            uint32_t b0[2][2], b1[2][2];
#pragma unroll
            for (int ks = 0; ks < 2; ks++)
#pragma unroll
                for (int r = 0; r < 2; r++) {
                    int n  = wn + nt * 8 + gid;
                    int kq = ks * 16 + tig * 2 + r * 8;
                    b0[ks][r] = *(const uint32_t*)&cB0[n * PADK + kq];
                    b1[ks][r] = *(const uint32_t*)&cB1[n * PADK + kq];
                }
#pragma unroll
            for (int mt = 0; mt < 2; mt++) {
                float* c = acc[mt][nt];
                float f[4] = {0.f, 0.f, 0.f, 0.f};
                MMA_BF16(f, a[0][mt], b0[0]);
                MMA_BF16(f, a[1][mt], b0[1]);
                c[0] += f[0]; c[1] += f[1]; c[2] += f[2]; c[3] += f[3];
                float g[4] = {0.f, 0.f, 0.f, 0.f};
                MMA_BF16(g, a[0][mt], b1[0]);
                MMA_BF16(g, a[1][mt], b1[1]);
                c[0] += g[0]; c[1] += g[1]; c[2] += g[2]; c[3] += g[3];
            }
        }

        cur = (cur == 2) ? 0 : cur + 1;
        pre = (pre == 2) ? 0 : pre + 1;
    }

#pragma unroll
    for (int mt = 0; mt < 2; mt++) {
        int row0 = m0 + wm + mt * 16 + gid;
#pragma unroll
        for (int nt = 0; nt < 8; nt++) {
            int n = n0 + wn + nt * 8 + tig * 2;
            float* c = acc[mt][nt];
            C[(long)row0 * ldc + n]         = c[0];
            C[(long)row0 * ldc + n + 1]     = c[1];
            C[(long)(row0+8) * ldc + n]     = c[2];
            C[(long)(row0+8) * ldc + n + 1] = c[3];
        }
    }
}

// ---------------- pack q/k/v (bf16, head-major) + RoPE, VECTORIZED ----------
__global__ void pack_k(const float* __restrict__ qu, const float* __restrict__ kvf,
                       const float* __restrict__ dwn,
                       bf16* __restrict__ q, bf16* __restrict__ k, bf16* __restrict__ v)
{
    const int s = blockIdx.x;
    const int tid = threadIdx.x;  // 256

    __shared__ float ssin[32], scos[32];
    if (tid < 32) {
        double invf_d = pow(10000.0, -((double)(2 * tid)) / 64.0);
        float invf = (float)invf_d;
        float ang = (float)s * invf;
        double a = (double)ang;
        ssin[tid] = (float)sin(a);
        scos[tid] = (float)cos(a);
    }
    __syncthreads();

    // content + v: H_*DV_/2 = 1024 bf162 pairs, 4 iters of 256 threads
#pragma unroll
    for (int it = 0; it < 4; it++) {
        int idx = tid + it * 256;              // 0..1023
        int h = idx >> 6, dp = idx & 63;       // dp: pair index 0..63
        int d = dp * 2;
        float2 a = *(const float2*)&qu[(long)s * NQU + h * DV_ + d];
        *(__nv_bfloat162*)&q[((long)h * S_ + s) * DQK_ + d] = f2bf2(a.x, a.y);
        float2 b = *(const float2*)&kvf[(long)s * (H_*2*DV_) + h * DV_ + d];
        *(__nv_bfloat162*)&k[((long)h * S_ + s) * DQK_ + d] = f2bf2(b.x, b.y);
        float2 c = *(const float2*)&kvf[(long)s * (H_*2*DV_) + H_*DV_ + h * DV_ + d];
        *(__nv_bfloat162*)&v[((long)h * S_ + s) * DV_ + d] = f2bf2(c.x, c.y);
    }

    // q rope: H_*16 = 256 pair-tasks, exactly one iteration
    {
        int h = tid >> 4, jp = tid & 15;
        int j = jp * 2;
        const float* base = &qu[(long)s * NQU + 2048 + h * DR_];
        float x1a = base[j],      x1b = base[j + 1];
        float x2a = base[32 + j], x2b = base[33 + j];
        float sna = ssin[j], csa = scos[j];
        float snb = ssin[j + 1], csb = scos[j + 1];
        bf16* qd = &q[((long)h * S_ + s) * DQK_ + DV_];
        *(__nv_bfloat162*)&qd[j]      = f2bf2(x1a * csa - x2a * sna, x1b * csb - x2b * snb);
        *(__nv_bfloat162*)&qd[32 + j] = f2bf2(x2a * csa + x1a * sna, x2b * csb + x1b * snb);
    }

    // k rope (shared across heads): 16 threads, pair j
    if (tid < 16) {
        int j = tid * 2;
        float x1a = dwn[(long)s * NDWN + 1024 + j];
        float x1b = dwn[(long)s * NDWN + 1024 + j + 1];
        float x2a = dwn[(long)s * NDWN + 1024 + 32 + j];
        float x2b = dwn[(long)s * NDWN + 1024 + 33 + j];
        float sna = ssin[j], csa = scos[j];
        float snb = ssin[j + 1], csb = scos[j + 1];
        __nv_bfloat162 r1 = f2bf2(x1a * csa - x2a * sna, x1b * csb - x2b * snb);
        __nv_bfloat162 r2 = f2bf2(x2a * csa + x1a * sna, x2b * csb + x1b * snb);
#pragma unroll
        for (int h = 0; h < H_; h++) {
            bf16* kd = &k[((long)h * S_ + s) * DQK_ + DV_];
            *(__nv_bfloat162*)&kd[j]      = r1;
            *(__nv_bfloat162*)&kd[32 + j] = r2;
        }
    }
}

// ---------------- transpose v [h][s][d] -> vT [h][d][s] ----------------
__global__ void transpose_v(const bf16* __restrict__ v, bf16* __restrict__ vT)
{
    __shared__ bf16 t[32][33];
    const int h = blockIdx.z;
    const int s0 = blockIdx.x * 32;
    const int d0 = blockIdx.y * 32;
    const int tx = threadIdx.x, ty = threadIdx.y;  // (32, 8)
#pragma unroll
    for (int j = 0; j < 32; j += 8)
        t[ty + j][tx] = v[((long)h * S_ + s0 + ty + j) * DV_ + d0 + tx];
    __syncthreads();
#pragma unroll
    for (int j = 0; j < 32; j += 8)
        vT[((long)h * DV_ + d0 + ty + j) * S_ + s0 + tx] = t[tx][ty + j];
}

// ---------------- softmax over bf16 logits -> bf16 probs, VECTORIZED -------
__global__ void softmax_k(const bf16* __restrict__ L, bf16* __restrict__ P, float scale)
{
    const int s = blockIdx.x;
    const int h = blockIdx.y;
    const bf16* row = L + ((long)h * S_ + s) * S_;
    bf16* prow = P + ((long)h * S_ + s) * S_;
    const int tid = threadIdx.x;   // 256 threads, 8 contiguous elems each

    uint4 pkt = ((const uint4*)row)[tid];
    bf16 e[8];
    *(uint4*)e = pkt;

    float v[8];
    float mx = -1e30f;
#pragma unroll
    for (int i = 0; i < 8; i++) {
        v[i] = __bfloat162float(e[i]) * scale;
        mx = fmaxf(mx, v[i]);
    }
    __shared__ float red[256];
    red[tid] = mx;
    __syncthreads();
    for (int st = 128; st > 0; st >>= 1) {
        if (tid < st) red[tid] = fmaxf(red[tid], red[tid + st]);
        __syncthreads();
    }
    mx = red[0];
    __syncthreads();

    float sum = 0.f;
#pragma unroll
    for (int i = 0; i < 8; i++) {
        v[i] = expf(v[i] - mx);
        sum += v[i];
    }
    red[tid] = sum;
    __syncthreads();
    for (int st = 128; st > 0; st >>= 1) {
        if (tid < st) red[tid] += red[tid + st];
        __syncthreads();
    }
    float tot = red[0];

    bf16 o[8];
#pragma unroll
    for (int i = 0; i < 8; i++) o[i] = __float2bfloat16(v[i] / tot);
    ((uint4*)prow)[tid] = *(const uint4*)o;
}

// ---------------- orchestration ----------------
extern "C" void kernel_launch(void* const* d_in, const int* in_sizes, int n_in,
                              void* d_out, int out_size)
{
    (void)in_sizes; (void)n_in; (void)out_size;
    const float* x       = (const float*)d_in[0];
    const float* wq_down = (const float*)d_in[1];
    const float* wq_up   = (const float*)d_in[2];
    const float* wq_rope = (const float*)d_in[3];
    const float* wkv_down= (const float*)d_in[4];
    const float* wkv_up  = (const float*)d_in[5];
    const float* wk_rope = (const float*)d_in[6];
    const float* wo      = (const float*)d_in[7];
    float* out = (float*)d_out;

    float *wd, *wu, *dwn, *qu, *kvf;
    cudaGetSymbolAddress((void**)&wd,  g_wd);
    cudaGetSymbolAddress((void**)&wu,  g_wu);
    cudaGetSymbolAddress((void**)&dwn, g_down);
    cudaGetSymbolAddress((void**)&qu,  g_qu);
    cudaGetSymbolAddress((void**)&kvf, g_kv);

    bf16 *q, *k, *v, *vT, *logits, *probs, *attn_bf, *wo_h, *wo_l;
    cudaGetSymbolAddress((void**)&q, g_q);
    cudaGetSymbolAddress((void**)&k, g_k);
    cudaGetSymbolAddress((void**)&v, g_v);
    cudaGetSymbolAddress((void**)&vT, g_vT);
    cudaGetSymbolAddress((void**)&logits, g_logits);
    cudaGetSymbolAddress((void**)&probs, g_probs);
    cudaGetSymbolAddress((void**)&attn_bf, g_attn_bf);
    cudaGetSymbolAddress((void**)&wo_h, g_wo_h);
    cudaGetSymbolAddress((void**)&wo_l, g_wo_l);

    // dynamic smem sizes (3-stage)
    const int SM64  = 3 * (64 * FPAD + FBN * FPAD) * 4;        // 46080
    const int SM128 = 3 * (128 * FPAD + FBN * FPAD) * 4;       // 61440
    const int SMBF  = 3 * (TBM * PADK + TBN * PADK) * 2;       // 61440
    const int SMOUT = 3 * (TBM * PADK + 2 * TBN * PADK) * 2;   // 92160
    cudaFuncSetAttribute(tf32_gemm<64>,  cudaFuncAttributeMaxDynamicSharedMemorySize, SM64);
    cudaFuncSetAttribute(tf32_dual, cudaFuncAttributeMaxDynamicSharedMemorySize, SM128);
    cudaFuncSetAttribute(bf16_gemm<bf16>,  cudaFuncAttributeMaxDynamicSharedMemorySize, SMBF);
    cudaFuncSetAttribute(bf16_gemm<float>, cudaFuncAttributeMaxDynamicSharedMemorySize, SMBF);
    cudaFuncSetAttribute(outb_gemm, cudaFuncAttributeMaxDynamicSharedMemorySize, SMOUT);

    dim3 blk(256);
    auto bgrid = [](int M, int N, int batch) {
        return dim3((N + TBN - 1) / TBN, (M + TBM - 1) / TBM, batch);
    };

    // 0) concat weights (D2D) + wo bf16 split
    cudaMemcpyAsync(wd,                 wq_down,  (size_t)QR_ * E_ * 4, cudaMemcpyDeviceToDevice);
    cudaMemcpyAsync(wd + (size_t)QR_*E_, wkv_down, (size_t)KVR_ * E_ * 4, cudaMemcpyDeviceToDevice);
    cudaMemcpyAsync(wd + (size_t)(QR_+KVR_)*E_, wk_rope, (size_t)DR_ * E_ * 4, cudaMemcpyDeviceToDevice);
    cudaMemcpyAsync(wu,                  wq_up,   (size_t)H_*DV_ * QR_ * 4, cudaMemcpyDeviceToDevice);
    cudaMemcpyAsync(wu + (size_t)H_*DV_*QR_, wq_rope, (size_t)H_*DR_ * QR_ * 4, cudaMemcpyDeviceToDevice);
    split_bf_k<<<592, 256>>>(wo, wo_h, wo_l, (long)E_*H_*DV_);

    // 1) fused down projection: [cq|ckv|kr] = x @ wd^T  (BM=64: 9x32 = 288 CTAs)
    tf32_gemm<64><<<dim3((NDWN + FBN - 1) / FBN, S_ / 64, 1), blk, SM64>>>(
        x, wd, dwn, S_, NDWN, E_, E_, E_, NDWN);

    // 2) fused qu-up + kv-up in ONE launch (896 CTAs)
    tf32_dual<<<896, blk, SM128>>>(
        dwn, wu, qu,
        dwn + QR_, wkv_up, kvf,
        QR_, NDWN, QR_);

    // 3) pack + rope -> head-major bf16 q/k/v ; transpose v
    pack_k<<<S_, 256>>>(qu, kvf, dwn, q, k, v);
    {
        dim3 tg(S_/32, DV_/32, H_);
        dim3 tb(32, 8);
        transpose_v<<<tg, tb>>>(v, vT);
    }

    // 4) logits[h] = bf16( q[h] @ k[h]^T )
    bf16_gemm<bf16><<<bgrid(S_, S_, H_), blk, SMBF>>>(
        q, q, k, k, logits, 1, S_, S_, DQK_, DQK_, DQK_, S_,
        (long)S_*DQK_, (long)S_*DQK_, (long)S_*S_);

    // 5) softmax
    {
        dim3 g(S_, H_);
        softmax_k<<<g, 256>>>(logits, probs, 1.0f / sqrtf((float)(DV_ + DR_)));
    }

    // 6) attn[h] = bf16( probs[h] @ v[h] ), stored bf16 interleaved [s][h*DV]
    bf16_gemm<bf16><<<bgrid(S_, DV_, H_), blk, SMBF>>>(
        probs, probs, vT, vT, attn_bf, 1, S_, DV_, S_, S_, S_, (long)H_*DV_,
        (long)S_*S_, (long)DV_*S_, DV_);

    // 7) out = attn @ (wo_h + wo_l)^T : shared-A dual-B single sweep
    outb_gemm<<<bgrid(S_, E_, 1), blk, SMOUT>>>(
        attn_bf, wo_h, wo_l, out, S_, E_, H_*DV_, H_*DV_, H_*DV_, E_);
}

// round 16
// speedup vs baseline: 1.3070x; 1.0079x over previous
#include <cuda_runtime.h>
#include <cuda_bf16.h>
#include <math.h>
#include <stdint.h>

#define S_  2048
#define E_  2048
#define H_  16
#define QR_ 512
#define KVR_ 512
#define DR_ 64
#define DV_ 128
#define DQK_ 192   // DV + DR
#define NDWN 1088  // QR + KVR + DR
#define NQU  3072  // H*DV + H*DR

typedef __nv_bfloat16 bf16;

// ---------------- scratch (device globals) ----------------
__device__ float g_wd [NDWN * E_];
__device__ float g_wu [NQU * QR_];
__device__ float g_down[S_ * NDWN];
__device__ float g_qu [S_ * NQU];
__device__ float g_kv [S_ * (H_*2*DV_)];
__device__ bf16 g_wo_h[E_*H_*DV_], g_wo_l[E_*H_*DV_];
__device__ bf16 g_q[(size_t)H_ * S_ * DQK_];
__device__ bf16 g_k[(size_t)H_ * S_ * DQK_];
__device__ bf16 g_vT[(size_t)H_ * DV_ * S_];
__device__ bf16 g_logits[(size_t)H_ * S_ * S_];
__device__ bf16 g_probs [(size_t)H_ * S_ * S_];
__device__ bf16 g_attn_bf[(size_t)S_ * H_ * DV_];

// ---------------- helpers ----------------
__device__ __forceinline__ uint32_t f2tf32(float x) {
    uint32_t r;
    asm("cvt.rna.tf32.f32 %0, %1;" : "=r"(r) : "f"(x));
    return r;
}

#define MMA_TF32(c, a, b) \
    asm volatile( \
        "mma.sync.aligned.m16n8k8.row.col.f32.tf32.tf32.f32 " \
        "{%0,%1,%2,%3}, {%4,%5,%6,%7}, {%8,%9}, {%0,%1,%2,%3};" \
        : "+f"((c)[0]), "+f"((c)[1]), "+f"((c)[2]), "+f"((c)[3]) \
        : "r"((a)[0]), "r"((a)[1]), "r"((a)[2]), "r"((a)[3]), \
          "r"((b)[0]), "r"((b)[1]))

#define MMA_BF16(c, a, b) \
    asm volatile( \
        "mma.sync.aligned.m16n8k16.row.col.f32.bf16.bf16.f32 " \
        "{%0,%1,%2,%3}, {%4,%5,%6,%7}, {%8,%9}, {%0,%1,%2,%3};" \
        : "+f"((c)[0]), "+f"((c)[1]), "+f"((c)[2]), "+f"((c)[3]) \
        : "r"((a)[0]), "r"((a)[1]), "r"((a)[2]), "r"((a)[3]), \
          "r"((b)[0]), "r"((b)[1]))

#define CP16(dst, src, nbytes) \
    asm volatile("cp.async.cg.shared.global [%0], [%1], 16, %2;" \
                 :: "r"(dst), "l"(src), "r"(nbytes))
#define CP_COMMIT()  asm volatile("cp.async.commit_group;")
#define CP_WAIT0()   asm volatile("cp.async.wait_group 0;")
#define CP_WAIT1()   asm volatile("cp.async.wait_group 1;")

__device__ __forceinline__ __nv_bfloat162 f2bf2(float a, float b) {
    return __nv_bfloat162(__float2bfloat16(a), __float2bfloat16(b));
}

__global__ void split_bf_k(const float* __restrict__ src, bf16* __restrict__ hi,
                           bf16* __restrict__ lo, long n)
{
    long i = (long)blockIdx.x * blockDim.x + threadIdx.x;
    long stride = (long)gridDim.x * blockDim.x;
    for (; i < n; i += stride) {
        float v = src[i];
        bf16 h = __float2bfloat16(v);
        hi[i] = h;
        lo[i] = __float2bfloat16(v - __bfloat162float(h));
    }
}

// ============================================================================
// 3xTF32 GEMM, BMv in {64,128}, 3-stage cp.async pipeline (wait_group 1).
// ============================================================================
#define FBN 128
#define FBK 16
#define FPAD 20

template <int BMv>
__global__ __launch_bounds__(256)
void tf32_gemm(const float* __restrict__ A, const float* __restrict__ B,
               float* __restrict__ C, int M, int N, int K,
               long lda, long ldb, long ldc)
{
    constexpr int MT = 2;
    constexpr int NT = (BMv == 128) ? 8 : 4;
    constexpr int ACH = BMv * 4 / 256;
    constexpr int ASZ = BMv * FPAD;
    constexpr int BSZ = FBN * FPAD;

    extern __shared__ float dsm[];
    float* sAbuf = dsm;
    float* sBbuf = dsm + 3 * ASZ;

    const int m0 = blockIdx.y * BMv;
    const int n0 = blockIdx.x * FBN;
    const int tid = threadIdx.x;
    const int warp = tid >> 5;
    const int lane = tid & 31;
    const int gid = lane >> 2;
    const int tig = lane & 3;
    const int wm = (BMv == 128) ? (warp >> 1) * 32 : (warp & 1) * 32;
    const int wn = (BMv == 128) ? (warp & 1) * 64  : (warp >> 1) * 32;

    const float* aSrc[ACH];
    uint32_t aOff[ACH];
    const float* bSrc[2];
    uint32_t bOff[2];
    int bPred[2];
    const uint32_t saBase = (uint32_t)__cvta_generic_to_shared(sAbuf);
    const uint32_t sbBase = (uint32_t)__cvta_generic_to_shared(sBbuf);
#pragma unroll
    for (int it = 0; it < ACH; it++) {
        int idx = tid + it * 256;
        int row = idx >> 2, ch = idx & 3;
        aSrc[it] = A + (long)(m0 + row) * lda + ch * 4;
        aOff[it] = (uint32_t)(row * FPAD + ch * 4) * 4u;
    }
#pragma unroll
    for (int it = 0; it < 2; it++) {
        int idx = tid + it * 256;
        int row = idx >> 2, ch = idx & 3;
        int nrow = n0 + row;
        bPred[it] = (nrow < N) ? 16 : 0;
        if (nrow >= N) nrow = N - 1;
        bSrc[it] = B + (long)nrow * ldb + ch * 4;
        bOff[it] = (uint32_t)(row * FPAD + ch * 4) * 4u;
    }

    float acc[MT][NT][4];
#pragma unroll
    for (int mt = 0; mt < MT; mt++)
#pragma unroll
        for (int nt = 0; nt < NT; nt++)
#pragma unroll
            for (int r = 0; r < 4; r++) acc[mt][nt][r] = 0.f;

    const int NTILES = K / FBK;

#pragma unroll
    for (int s = 0; s < 2; s++) {
        const long kk = (long)s * FBK;
#pragma unroll
        for (int it = 0; it < ACH; it++)
            CP16(saBase + s * ASZ * 4u + aOff[it], aSrc[it] + kk, 16);
#pragma unroll
        for (int it = 0; it < 2; it++)
            CP16(sbBase + s * BSZ * 4u + bOff[it], bSrc[it] + kk, bPred[it]);
        CP_COMMIT();
    }

    int cur = 0, pre = 2;
    for (int t = 0; t < NTILES; t++) {
        if (t + 1 < NTILES) CP_WAIT1(); else CP_WAIT0();
        __syncthreads();

        if (t + 2 < NTILES) {
            const long kk = (long)(t + 2) * FBK;
#pragma unroll
            for (int it = 0; it < ACH; it++)
                CP16(saBase + pre * ASZ * 4u + aOff[it], aSrc[it] + kk, 16);
#pragma unroll
            for (int it = 0; it < 2; it++)
                CP16(sbBase + pre * BSZ * 4u + bOff[it], bSrc[it] + kk, bPred[it]);
            CP_COMMIT();
        }

        const float* cA = sAbuf + cur * ASZ;
        const float* cB = sBbuf + cur * BSZ;

        uint32_t ah[2][MT][4], al[2][MT][4];
#pragma unroll
        for (int ks = 0; ks < 2; ks++)
#pragma unroll
            for (int mt = 0; mt < MT; mt++)
#pragma unroll
                for (int r = 0; r < 4; r++) {
                    int row = wm + mt * 16 + gid + (r & 1) * 8;
                    int col = ks * 8 + tig + (r >> 1) * 4;
                    float v = cA[row * FPAD + col];
                    uint32_t h = f2tf32(v);
                    ah[ks][mt][r] = h;
                    al[ks][mt][r] = f2tf32(v - __uint_as_float(h));
                }

#pragma unroll
        for (int nt = 0; nt < NT; nt++) {
            uint32_t bh[2][2], bl[2][2];
#pragma unroll
            for (int ks = 0; ks < 2; ks++)
#pragma unroll
                for (int r = 0; r < 2; r++) {
                    int n = wn + nt * 8 + gid;
                    int kq = ks * 8 + tig + r * 4;
                    float v = cB[n * FPAD + kq];
                    uint32_t h = f2tf32(v);
                    bh[ks][r] = h;
                    bl[ks][r] = f2tf32(v - __uint_as_float(h));
                }
#pragma unroll
            for (int mt = 0; mt < MT; mt++) {
                float f[4] = {0.f, 0.f, 0.f, 0.f};
#pragma unroll
                for (int ks = 0; ks < 2; ks++) {
                    MMA_TF32(f, ah[ks][mt], bh[ks]);
                    MMA_TF32(f, ah[ks][mt], bl[ks]);
                    MMA_TF32(f, al[ks][mt], bh[ks]);
                }
                float* c = acc[mt][nt];
                c[0] += f[0]; c[1] += f[1]; c[2] += f[2]; c[3] += f[3];
            }
        }

        cur = (cur == 2) ? 0 : cur + 1;
        pre = (pre == 2) ? 0 : pre + 1;
    }

#pragma unroll
    for (int mt = 0; mt < MT; mt++) {
        int row0 = m0 + wm + mt * 16 + gid;
#pragma unroll
        for (int nt = 0; nt < NT; nt++) {
            int n = n0 + wn + nt * 8 + tig * 2;
            if (n >= N) continue;
            float* c = acc[mt][nt];
            C[(long)row0 * ldc + n]         = c[0];
            C[(long)row0 * ldc + n + 1]     = c[1];
            C[(long)(row0+8) * ldc + n]     = c[2];
            C[(long)(row0+8) * ldc + n + 1] = c[3];
        }
    }
}

// ============================================================================
// Fused qu-up + kv-up (one flattened launch, BM=128 both) — as R14/R15.
// ============================================================================
__global__ __launch_bounds__(256)
void tf32_dual(const float* __restrict__ A0, const float* __restrict__ B0, float* __restrict__ C0,
               const float* __restrict__ A1, const float* __restrict__ B1, float* __restrict__ C1,
               int K, long lda, long ldb)
{
    constexpr int ASZ = 128 * FPAD;
    constexpr int BSZ = FBN * FPAD;

    extern __shared__ float dsm[];
    float* sAbuf = dsm;
    float* sBbuf = dsm + 3 * ASZ;

    const int bid = blockIdx.x;
    const float *A, *B;
    float* C;
    int m0, n0;
    long ldc;
    if (bid < 384) {
        A = A0; B = B0; C = C0; ldc = NQU;
        m0 = (bid / 24) * 128;  n0 = (bid % 24) * 128;
    } else {
        int b = bid - 384;
        A = A1; B = B1; C = C1; ldc = H_*2*DV_;
        m0 = (b / 32) * 128;  n0 = (b % 32) * 128;
    }

    const int tid = threadIdx.x;
    const int warp = tid >> 5;
    const int lane = tid & 31;
    const int gid = lane >> 2;
    const int tig = lane & 3;
    const int wm = (warp >> 1) * 32;
    const int wn = (warp & 1) * 64;

    const float* aSrc[2];
    const float* bSrc[2];
    uint32_t sOff[2];
    const uint32_t saBase = (uint32_t)__cvta_generic_to_shared(sAbuf);
    const uint32_t sbBase = (uint32_t)__cvta_generic_to_shared(sBbuf);
#pragma unroll
    for (int it = 0; it < 2; it++) {
        int idx = tid + it * 256;
        int row = idx >> 2, ch = idx & 3;
        aSrc[it] = A + (long)(m0 + row) * lda + ch * 4;
        bSrc[it] = B + (long)(n0 + row) * ldb + ch * 4;
        sOff[it] = (uint32_t)(row * FPAD + ch * 4) * 4u;
    }

    float acc[2][8][4];
#pragma unroll
    for (int mt = 0; mt < 2; mt++)
#pragma unroll
        for (int nt = 0; nt < 8; nt++)
#pragma unroll
            for (int r = 0; r < 4; r++) acc[mt][nt][r] = 0.f;

    const int NTILES = K / FBK;

#pragma unroll
    for (int s = 0; s < 2; s++) {
        const long kk = (long)s * FBK;
#pragma unroll
        for (int it = 0; it < 2; it++) {
            CP16(saBase + s * ASZ * 4u + sOff[it], aSrc[it] + kk, 16);
            CP16(sbBase + s * BSZ * 4u + sOff[it], bSrc[it] + kk, 16);
        }
        CP_COMMIT();
    }

    int cur = 0, pre = 2;
    for (int t = 0; t < NTILES; t++) {
        if (t + 1 < NTILES) CP_WAIT1(); else CP_WAIT0();
        __syncthreads();

        if (t + 2 < NTILES) {
            const long kk = (long)(t + 2) * FBK;
#pragma unroll
            for (int it = 0; it < 2; it++) {
                CP16(saBase + pre * ASZ * 4u + sOff[it], aSrc[it] + kk, 16);
                CP16(sbBase + pre * BSZ * 4u + sOff[it], bSrc[it] + kk, 16);
            }
            CP_COMMIT();
        }

        const float* cA = sAbuf + cur * ASZ;
        const float* cB = sBbuf + cur * BSZ;

        uint32_t ah[2][2][4], al[2][2][4];
#pragma unroll
        for (int ks = 0; ks < 2; ks++)
#pragma unroll
            for (int mt = 0; mt < 2; mt++)
#pragma unroll
                for (int r = 0; r < 4; r++) {
                    int row = wm + mt * 16 + gid + (r & 1) * 8;
                    int col = ks * 8 + tig + (r >> 1) * 4;
                    float v = cA[row * FPAD + col];
                    uint32_t h = f2tf32(v);
                    ah[ks][mt][r] = h;
                    al[ks][mt][r] = f2tf32(v - __uint_as_float(h));
                }

#pragma unroll
        for (int nt = 0; nt < 8; nt++) {
            uint32_t bh[2][2], bl[2][2];
#pragma unroll
            for (int ks = 0; ks < 2; ks++)
#pragma unroll
                for (int r = 0; r < 2; r++) {
                    int n = wn + nt * 8 + gid;
                    int kq = ks * 8 + tig + r * 4;
                    float v = cB[n * FPAD + kq];
                    uint32_t h = f2tf32(v);
                    bh[ks][r] = h;
                    bl[ks][r] = f2tf32(v - __uint_as_float(h));
                }
#pragma unroll
            for (int mt = 0; mt < 2; mt++) {
                float f[4] = {0.f, 0.f, 0.f, 0.f};
#pragma unroll
                for (int ks = 0; ks < 2; ks++) {
                    MMA_TF32(f, ah[ks][mt], bh[ks]);
                    MMA_TF32(f, ah[ks][mt], bl[ks]);
                    MMA_TF32(f, al[ks][mt], bh[ks]);
                }
                float* c = acc[mt][nt];
                c[0] += f[0]; c[1] += f[1]; c[2] += f[2]; c[3] += f[3];
            }
        }

        cur = (cur == 2) ? 0 : cur + 1;
        pre = (pre == 2) ? 0 : pre + 1;
    }

#pragma unroll
    for (int mt = 0; mt < 2; mt++) {
        int row0 = m0 + wm + mt * 16 + gid;
#pragma unroll
        for (int nt = 0; nt < 8; nt++) {
            int n = n0 + wn + nt * 8 + tig * 2;
            float* c = acc[mt][nt];
            C[(long)row0 * ldc + n]         = c[0];
            C[(long)row0 * ldc + n + 1]     = c[1];
            C[(long)(row0+8) * ldc + n]     = c[2];
            C[(long)(row0+8) * ldc + n + 1] = c[3];
        }
    }
}

// ============================================================================
// bf16 tensor-core GEMM, 3-stage cp.async pipeline per pass (as R13-R15).
// ============================================================================
#define TBM 128
#define TBN 128
#define TBK 32
#define PADK 40

template <typename TC>
__global__ __launch_bounds__(256)
void bf16_gemm(const bf16* __restrict__ A0, const bf16* __restrict__ A1,
               const bf16* __restrict__ B0, const bf16* __restrict__ B1,
               TC* __restrict__ C, int npass, int M, int N, int K,
               long lda, long ldb, long ldc, long Abat, long Bbat, long Cbat)
{
    constexpr int ASZ = TBM * PADK;
    constexpr int BSZ = TBN * PADK;

    extern __shared__ bf16 dsmb[];
    bf16* sAbuf = dsmb;
    bf16* sBbuf = dsmb + 3 * ASZ;

    const long zo = blockIdx.z;
    C += zo * Cbat;

    const int m0 = blockIdx.y * TBM;
    const int n0 = blockIdx.x * TBN;
    const int tid = threadIdx.x;
    const int warp = tid >> 5;
    const int lane = tid & 31;
    const int gid = lane >> 2;
    const int tig = lane & 3;
    const int wm = (warp >> 1) * 32;
    const int wn = (warp & 1) * 64;

    const uint32_t saBase = (uint32_t)__cvta_generic_to_shared(sAbuf);
    const uint32_t sbBase = (uint32_t)__cvta_generic_to_shared(sBbuf);

    float acc[2][8][4];
#pragma unroll
    for (int mt = 0; mt < 2; mt++)
#pragma unroll
        for (int nt = 0; nt < 8; nt++)
#pragma unroll
            for (int r = 0; r < 4; r++) acc[mt][nt][r] = 0.f;

    const int NTILES = K / TBK;

    for (int p = 0; p < npass; p++) {
        const bf16* A = (p ? A1 : A0) + zo * Abat;
        const bf16* B = (p ? B1 : B0) + zo * Bbat;

        const bf16* aSrc[2];
        const bf16* bSrc[2];
        uint32_t aOff[2], bOff[2];
        int bPred[2];
#pragma unroll
        for (int it = 0; it < 2; it++) {
            int idx = tid + it * 256;
            int row = idx >> 2, ch = idx & 3;
            aSrc[it] = A + (long)(m0 + row) * lda + ch * 8;
            int nrow = n0 + row;
            bPred[it] = (nrow < N) ? 16 : 0;
            if (nrow >= N) nrow = N - 1;
            bSrc[it] = B + (long)nrow * ldb + ch * 8;
            aOff[it] = (uint32_t)(row * PADK + ch * 8) * 2u;
            bOff[it] = (uint32_t)(row * PADK + ch * 8) * 2u;
        }

        if (p) __syncthreads();

#pragma unroll
        for (int s = 0; s < 2; s++) {
            const long kk = (long)s * TBK;
#pragma unroll
            for (int it = 0; it < 2; it++) {
                CP16(saBase + s * ASZ * 2u + aOff[it], aSrc[it] + kk, 16);
                CP16(sbBase + s * BSZ * 2u + bOff[it], bSrc[it] + kk, bPred[it]);
            }
            CP_COMMIT();
        }

        int cur = 0, pre = 2;
        for (int t = 0; t < NTILES; t++) {
            if (t + 1 < NTILES) CP_WAIT1(); else CP_WAIT0();
            __syncthreads();

            if (t + 2 < NTILES) {
                const long kk = (long)(t + 2) * TBK;
#pragma unroll
                for (int it = 0; it < 2; it++) {
                    CP16(saBase + pre * ASZ * 2u + aOff[it], aSrc[it] + kk, 16);
                    CP16(sbBase + pre * BSZ * 2u + bOff[it], bSrc[it] + kk, bPred[it]);
                }
                CP_COMMIT();
            }

            const bf16* cA = sAbuf + cur * ASZ;
            const bf16* cB = sBbuf + cur * BSZ;

            uint32_t a[2][2][4];
#pragma unroll
            for (int ks = 0; ks < 2; ks++)
#pragma unroll
                for (int mt = 0; mt < 2; mt++)
#pragma unroll
                    for (int r = 0; r < 4; r++) {
                        int row = wm + mt * 16 + gid + (r & 1) * 8;
                        int col = ks * 16 + tig * 2 + (r >> 1) * 8;
                        a[ks][mt][r] = *(const uint32_t*)&cA[row * PADK + col];
                    }

#pragma unroll
            for (int nt = 0; nt < 8; nt++) {
                uint32_t b[2][2];
#pragma unroll
                for (int ks = 0; ks < 2; ks++)
#pragma unroll
                    for (int r = 0; r < 2; r++) {
                        int n  = wn + nt * 8 + gid;
                        int kq = ks * 16 + tig * 2 + r * 8;
                        b[ks][r] = *(const uint32_t*)&cB[n * PADK + kq];
                    }
#pragma unroll
                for (int mt = 0; mt < 2; mt++) {
                    float f[4] = {0.f, 0.f, 0.f, 0.f};
                    MMA_BF16(f, a[0][mt], b[0]);
                    MMA_BF16(f, a[1][mt], b[1]);
                    float* c = acc[mt][nt];
                    c[0] += f[0]; c[1] += f[1]; c[2] += f[2]; c[3] += f[3];
                }
            }

            cur = (cur == 2) ? 0 : cur + 1;
            pre = (pre == 2) ? 0 : pre + 1;
        }
    }

#pragma unroll
    for (int mt = 0; mt < 2; mt++) {
        int row0 = m0 + wm + mt * 16 + gid;
#pragma unroll
        for (int nt = 0; nt < 8; nt++) {
            int n = n0 + wn + nt * 8 + tig * 2;
            if (n >= N) continue;
            float* c = acc[mt][nt];
            if (sizeof(TC) == 4) {
                float* Cf = (float*)C;
                Cf[(long)row0 * ldc + n]         = c[0];
                Cf[(long)row0 * ldc + n + 1]     = c[1];
                Cf[(long)(row0+8) * ldc + n]     = c[2];
                Cf[(long)(row0+8) * ldc + n + 1] = c[3];
            } else {
                bf16* Cb = (bf16*)C;
                *(__nv_bfloat162*)&Cb[(long)row0 * ldc + n] =
                    __nv_bfloat162(__float2bfloat16(c[0]), __float2bfloat16(c[1]));
                *(__nv_bfloat162*)&Cb[(long)(row0+8) * ldc + n] =
                    __nv_bfloat162(__float2bfloat16(c[2]), __float2bfloat16(c[3]));
            }
        }
    }
}

// ============================================================================
// out GEMM: C = A @ (B0 + B1)^T, shared-A dual-B single K-sweep (as R13-R15).
// ============================================================================
__global__ __launch_bounds__(256)
void outb_gemm(const bf16* __restrict__ A, const bf16* __restrict__ B0,
               const bf16* __restrict__ B1, float* __restrict__ C,
               int M, int N, int K, long lda, long ldb, long ldc)
{
    constexpr int ASZ = TBM * PADK;
    constexpr int BSZ = TBN * PADK;

    extern __shared__ bf16 dsmb[];
    bf16* sAbuf  = dsmb;
    bf16* sB0buf = dsmb + 3 * ASZ;
    bf16* sB1buf = dsmb + 3 * ASZ + 3 * BSZ;

    const int m0 = blockIdx.y * TBM;
    const int n0 = blockIdx.x * TBN;
    const int tid = threadIdx.x;
    const int warp = tid >> 5;
    const int lane = tid & 31;
    const int gid = lane >> 2;
    const int tig = lane & 3;
    const int wm = (warp >> 1) * 32;
    const int wn = (warp & 1) * 64;

    const uint32_t saBase  = (uint32_t)__cvta_generic_to_shared(sAbuf);
    const uint32_t sb0Base = (uint32_t)__cvta_generic_to_shared(sB0buf);
    const uint32_t sb1Base = (uint32_t)__cvta_generic_to_shared(sB1buf);

    const bf16 *aSrc[2], *b0Src[2], *b1Src[2];
    uint32_t sOff[2];
#pragma unroll
    for (int it = 0; it < 2; it++) {
        int idx = tid + it * 256;
        int row = idx >> 2, ch = idx & 3;
        aSrc[it]  = A  + (long)(m0 + row) * lda + ch * 8;
        b0Src[it] = B0 + (long)(n0 + row) * ldb + ch * 8;
        b1Src[it] = B1 + (long)(n0 + row) * ldb + ch * 8;
        sOff[it] = (uint32_t)(row * PADK + ch * 8) * 2u;
    }

    float acc[2][8][4];
#pragma unroll
    for (int mt = 0; mt < 2; mt++)
#pragma unroll
        for (int nt = 0; nt < 8; nt++)
#pragma unroll
            for (int r = 0; r < 4; r++) acc[mt][nt][r] = 0.f;

    const int NTILES = K / TBK;

#pragma unroll
    for (int s = 0; s < 2; s++) {
        const long kk = (long)s * TBK;
#pragma unroll
        for (int it = 0; it < 2; it++) {
            CP16(saBase  + s * ASZ * 2u + sOff[it], aSrc[it]  + kk, 16);
            CP16(sb0Base + s * BSZ * 2u + sOff[it], b0Src[it] + kk, 16);
            CP16(sb1Base + s * BSZ * 2u + sOff[it], b1Src[it] + kk, 16);
        }
        CP_COMMIT();
    }

    int cur = 0, pre = 2;
    for (int t = 0; t < NTILES; t++) {
        if (t + 1 < NTILES) CP_WAIT1(); else CP_WAIT0();
        __syncthreads();

        if (t + 2 < NTILES) {
            const long kk = (long)(t + 2) * TBK;
#pragma unroll
            for (int it = 0; it < 2; it++) {
                CP16(saBase  + pre * ASZ * 2u + sOff[it], aSrc[it]  + kk, 16);
                CP16(sb0Base + pre * BSZ * 2u + sOff[it], b0Src[it] + kk, 16);
                CP16(sb1Base + pre * BSZ * 2u + sOff[it], b1Src[it] + kk, 16);
            }
            CP_COMMIT();
        }

        const bf16* cA  = sAbuf  + cur * ASZ;
        const bf16* cB0 = sB0buf + cur * BSZ;
        const bf16* cB1 = sB1buf + cur * BSZ;

        uint32_t a[2][2][4];
#pragma unroll
        for (int ks = 0; ks < 2; ks++)
#pragma unroll
            for (int mt = 0; mt < 2; mt++)
#pragma unroll
                for (int r = 0; r < 4; r++) {
                    int row = wm + mt * 16 + gid + (r & 1) * 8;
                    int col = ks * 16 + tig * 2 + (r >> 1) * 8;
                    a[ks][mt][r] = *(const uint32_t*)&cA[row * PADK + col];
                }

#pragma unroll
        for (int nt = 0; nt < 8; nt++) {
            uint32_t b0[2][2], b1[2][2];
#pragma unroll
            for (int ks = 0; ks < 2; ks++)
#pragma unroll
                for (int r = 0; r < 2; r++) {
                    int n  = wn + nt * 8 + gid;
                    int kq = ks * 16 + tig * 2 + r * 8;
                    b0[ks][r] = *(const uint32_t*)&cB0[n * PADK + kq];
                    b1[ks][r] = *(const uint32_t*)&cB1[n * PADK + kq];
                }
#pragma unroll
            for (int mt = 0; mt < 2; mt++) {
                float* c = acc[mt][nt];
                float f[4] = {0.f, 0.f, 0.f, 0.f};
                MMA_BF16(f, a[0][mt], b0[0]);
                MMA_BF16(f, a[1][mt], b0[1]);
                c[0] += f[0]; c[1] += f[1]; c[2] += f[2]; c[3] += f[3];
                float g[4] = {0.f, 0.f, 0.f, 0.f};
                MMA_BF16(g, a[0][mt], b1[0]);
                MMA_BF16(g, a[1][mt], b1[1]);
                c[0] += g[0]; c[1] += g[1]; c[2] += g[2]; c[3] += g[3];
            }
        }

        cur = (cur == 2) ? 0 : cur + 1;
        pre = (pre == 2) ? 0 : pre + 1;
    }

#pragma unroll
    for (int mt = 0; mt < 2; mt++) {
        int row0 = m0 + wm + mt * 16 + gid;
#pragma unroll
        for (int nt = 0; nt < 8; nt++) {
            int n = n0 + wn + nt * 8 + tig * 2;
            float* c = acc[mt][nt];
            C[(long)row0 * ldc + n]         = c[0];
            C[(long)row0 * ldc + n + 1]     = c[1];
            C[(long)(row0+8) * ldc + n]     = c[2];
            C[(long)(row0+8) * ldc + n + 1] = c[3];
        }
    }
}

// ---------------- pack q/k (bf16, head-major) + RoPE (v handled elsewhere) --
__global__ void pack_k(const float* __restrict__ qu, const float* __restrict__ kvf,
                       const float* __restrict__ dwn,
                       bf16* __restrict__ q, bf16* __restrict__ k)
{
    const int s = blockIdx.x;
    const int tid = threadIdx.x;  // 256

    __shared__ float ssin[32], scos[32];
    if (tid < 32) {
        double invf_d = pow(10000.0, -((double)(2 * tid)) / 64.0);
        float invf = (float)invf_d;
        float ang = (float)s * invf;
        double a = (double)ang;
        ssin[tid] = (float)sin(a);
        scos[tid] = (float)cos(a);
    }
    __syncthreads();

    // content: H_*DV_/2 = 1024 bf162 pairs, 4 iters of 256 threads
#pragma unroll
    for (int it = 0; it < 4; it++) {
        int idx = tid + it * 256;
        int h = idx >> 6, dp = idx & 63;
        int d = dp * 2;
        float2 a = *(const float2*)&qu[(long)s * NQU + h * DV_ + d];
        *(__nv_bfloat162*)&q[((long)h * S_ + s) * DQK_ + d] = f2bf2(a.x, a.y);
        float2 b = *(const float2*)&kvf[(long)s * (H_*2*DV_) + h * DV_ + d];
        *(__nv_bfloat162*)&k[((long)h * S_ + s) * DQK_ + d] = f2bf2(b.x, b.y);
    }

    // q rope
    {
        int h = tid >> 4, jp = tid & 15;
        int j = jp * 2;
        const float* base = &qu[(long)s * NQU + 2048 + h * DR_];
        float x1a = base[j],      x1b = base[j + 1];
        float x2a = base[32 + j], x2b = base[33 + j];
        float sna = ssin[j], csa = scos[j];
        float snb = ssin[j + 1], csb = scos[j + 1];
        bf16* qd = &q[((long)h * S_ + s) * DQK_ + DV_];
        *(__nv_bfloat162*)&qd[j]      = f2bf2(x1a * csa - x2a * sna, x1b * csb - x2b * snb);
        *(__nv_bfloat162*)&qd[32 + j] = f2bf2(x2a * csa + x1a * sna, x2b * csb + x1b * snb);
    }

    // k rope (shared across heads)
    if (tid < 16) {
        int j = tid * 2;
        float x1a = dwn[(long)s * NDWN + 1024 + j];
        float x1b = dwn[(long)s * NDWN + 1024 + j + 1];
        float x2a = dwn[(long)s * NDWN + 1024 + 32 + j];
        float x2b = dwn[(long)s * NDWN + 1024 + 33 + j];
        float sna = ssin[j], csa = scos[j];
        float snb = ssin[j + 1], csb = scos[j + 1];
        __nv_bfloat162 r1 = f2bf2(x1a * csa - x2a * sna, x1b * csb - x2b * snb);
        __nv_bfloat162 r2 = f2bf2(x2a * csa + x1a * sna, x2b * csb + x1b * snb);
#pragma unroll
        for (int h = 0; h < H_; h++) {
            bf16* kd = &k[((long)h * S_ + s) * DQK_ + DV_];
            *(__nv_bfloat162*)&kd[j]      = r1;
            *(__nv_bfloat162*)&kd[32 + j] = r2;
        }
    }
}

// ---------------- vT[h][d][s] = bf16( kvf[s][H*DV + h*DV + d] ) ------------
__global__ void transpose_v(const float* __restrict__ kvf, bf16* __restrict__ vT)
{
    __shared__ bf16 t[32][33];
    const int h = blockIdx.z;
    const int s0 = blockIdx.x * 32;
    const int d0 = blockIdx.y * 32;
    const int tx = threadIdx.x, ty = threadIdx.y;  // (32, 8)
#pragma unroll
    for (int j = 0; j < 32; j += 8) {
        float val = kvf[(long)(s0 + ty + j) * (H_*2*DV_) + H_*DV_ + h * DV_ + d0 + tx];
        t[ty + j][tx] = __float2bfloat16(val);
    }
    __syncthreads();
#pragma unroll
    for (int j = 0; j < 32; j += 8)
        vT[((long)h * DV_ + d0 + ty + j) * S_ + s0 + tx] = t[tx][ty + j];
}

// ---------------- softmax: vectorized, __expf, reciprocal multiply ---------
__global__ void softmax_k(const bf16* __restrict__ L, bf16* __restrict__ P, float scale)
{
    const int s = blockIdx.x;
    const int h = blockIdx.y;
    const bf16* row = L + ((long)h * S_ + s) * S_;
    bf16* prow = P + ((long)h * S_ + s) * S_;
    const int tid = threadIdx.x;   // 256 threads, 8 contiguous elems each

    uint4 pkt = ((const uint4*)row)[tid];
    bf16 e[8];
    *(uint4*)e = pkt;

    float v[8];
    float mx = -1e30f;
#pragma unroll
    for (int i = 0; i < 8; i++) {
        v[i] = __bfloat162float(e[i]) * scale;
        mx = fmaxf(mx, v[i]);
    }
    __shared__ float red[256];
    red[tid] = mx;
    __syncthreads();
    for (int st = 128; st > 0; st >>= 1) {
        if (tid < st) red[tid] = fmaxf(red[tid], red[tid + st]);
        __syncthreads();
    }
    mx = red[0];
    __syncthreads();

    float sum = 0.f;
#pragma unroll
    for (int i = 0; i < 8; i++) {
        v[i] = __expf(v[i] - mx);
        sum += v[i];
    }
    red[tid] = sum;
    __syncthreads();
    for (int st = 128; st > 0; st >>= 1) {
        if (tid < st) red[tid] += red[tid + st];
        __syncthreads();
    }
    const float inv_tot = 1.0f / red[0];

    bf16 o[8];
#pragma unroll
    for (int i = 0; i < 8; i++) o[i] = __float2bfloat16(v[i] * inv_tot);
    ((uint4*)prow)[tid] = *(const uint4*)o;
}

// ---------------- orchestration ----------------
extern "C" void kernel_launch(void* const* d_in, const int* in_sizes, int n_in,
                              void* d_out, int out_size)
{
    (void)in_sizes; (void)n_in; (void)out_size;
    const float* x       = (const float*)d_in[0];
    const float* wq_down = (const float*)d_in[1];
    const float* wq_up   = (const float*)d_in[2];
    const float* wq_rope = (const float*)d_in[3];
    const float* wkv_down= (const float*)d_in[4];
    const float* wkv_up  = (const float*)d_in[5];
    const float* wk_rope = (const float*)d_in[6];
    const float* wo      = (const float*)d_in[7];
    float* out = (float*)d_out;

    float *wd, *wu, *dwn, *qu, *kvf;
    cudaGetSymbolAddress((void**)&wd,  g_wd);
    cudaGetSymbolAddress((void**)&wu,  g_wu);
    cudaGetSymbolAddress((void**)&dwn, g_down);
    cudaGetSymbolAddress((void**)&qu,  g_qu);
    cudaGetSymbolAddress((void**)&kvf, g_kv);

    bf16 *q, *k, *vT, *logits, *probs, *attn_bf, *wo_h, *wo_l;
    cudaGetSymbolAddress((void**)&q, g_q);
    cudaGetSymbolAddress((void**)&k, g_k);
    cudaGetSymbolAddress((void**)&vT, g_vT);
    cudaGetSymbolAddress((void**)&logits, g_logits);
    cudaGetSymbolAddress((void**)&probs, g_probs);
    cudaGetSymbolAddress((void**)&attn_bf, g_attn_bf);
    cudaGetSymbolAddress((void**)&wo_h, g_wo_h);
    cudaGetSymbolAddress((void**)&wo_l, g_wo_l);

    // dynamic smem sizes (3-stage)
    const int SM64  = 3 * (64 * FPAD + FBN * FPAD) * 4;        // 46080
    const int SM128 = 3 * (128 * FPAD + FBN * FPAD) * 4;       // 61440
    const int SMBF  = 3 * (TBM * PADK + TBN * PADK) * 2;       // 61440
    const int SMOUT = 3 * (TBM * PADK + 2 * TBN * PADK) * 2;   // 92160
    cudaFuncSetAttribute(tf32_gemm<64>,  cudaFuncAttributeMaxDynamicSharedMemorySize, SM64);
    cudaFuncSetAttribute(tf32_dual, cudaFuncAttributeMaxDynamicSharedMemorySize, SM128);
    cudaFuncSetAttribute(bf16_gemm<bf16>,  cudaFuncAttributeMaxDynamicSharedMemorySize, SMBF);
    cudaFuncSetAttribute(bf16_gemm<float>, cudaFuncAttributeMaxDynamicSharedMemorySize, SMBF);
    cudaFuncSetAttribute(outb_gemm, cudaFuncAttributeMaxDynamicSharedMemorySize, SMOUT);

    dim3 blk(256);
    auto bgrid = [](int M, int N, int batch) {
        return dim3((N + TBN - 1) / TBN, (M + TBM - 1) / TBM, batch);
    };

    // 0) concat weights (D2D) + wo bf16 split
    cudaMemcpyAsync(wd,                 wq_down,  (size_t)QR_ * E_ * 4, cudaMemcpyDeviceToDevice);
    cudaMemcpyAsync(wd + (size_t)QR_*E_, wkv_down, (size_t)KVR_ * E_ * 4, cudaMemcpyDeviceToDevice);
    cudaMemcpyAsync(wd + (size_t)(QR_+KVR_)*E_, wk_rope, (size_t)DR_ * E_ * 4, cudaMemcpyDeviceToDevice);
    cudaMemcpyAsync(wu,                  wq_up,   (size_t)H_*DV_ * QR_ * 4, cudaMemcpyDeviceToDevice);
    cudaMemcpyAsync(wu + (size_t)H_*DV_*QR_, wq_rope, (size_t)H_*DR_ * QR_ * 4, cudaMemcpyDeviceToDevice);
    split_bf_k<<<592, 256>>>(wo, wo_h, wo_l, (long)E_*H_*DV_);

    // 1) fused down projection: [cq|ckv|kr] = x @ wd^T  (BM=64: 288 CTAs)
    tf32_gemm<64><<<dim3((NDWN + FBN - 1) / FBN, S_ / 64, 1), blk, SM64>>>(
        x, wd, dwn, S_, NDWN, E_, E_, E_, NDWN);

    // 2) fused qu-up + kv-up in ONE launch (896 CTAs)
    tf32_dual<<<896, blk, SM128>>>(
        dwn, wu, qu,
        dwn + QR_, wkv_up, kvf,
        QR_, NDWN, QR_);

    // 3) pack q/k + rope ; transpose v directly from kvf
    pack_k<<<S_, 256>>>(qu, kvf, dwn, q, k);
    {
        dim3 tg(S_/32, DV_/32, H_);
        dim3 tb(32, 8);
        transpose_v<<<tg, tb>>>(kvf, vT);
    }

    // 4) logits[h] = bf16( q[h] @ k[h]^T )
    bf16_gemm<bf16><<<bgrid(S_, S_, H_), blk, SMBF>>>(
        q, q, k, k, logits, 1, S_, S_, DQK_, DQK_, DQK_, S_,
        (long)S_*DQK_, (long)S_*DQK_, (long)S_*S_);

    // 5) softmax
    {
        dim3 g(S_, H_);
        softmax_k<<<g, 256>>>(logits, probs, 1.0f / sqrtf((float)(DV_ + DR_)));
    }

    // 6) attn[h] = bf16( probs[h] @ v[h] ), stored bf16 interleaved [s][h*DV]
    bf16_gemm<bf16><<<bgrid(S_, DV_, H_), blk, SMBF>>>(
        probs, probs, vT, vT, attn_bf, 1, S_, DV_, S_, S_, S_, (long)H_*DV_,
        (long)S_*S_, (long)DV_*S_, DV_);

    // 7) out = attn @ (wo_h + wo_l)^T : shared-A dual-B single sweep
    outb_gemm<<<bgrid(S_, E_, 1), blk, SMOUT>>>(
        attn_bf, wo_h, wo_l, out, S_, E_, H_*DV_, H_*DV_, H_*DV_, E_);
}

// round 17
// speedup vs baseline: 1.3393x; 1.0247x over previous
#include <cuda_runtime.h>
#include <cuda_bf16.h>
#include <math.h>
#include <stdint.h>

#define S_  2048
#define E_  2048
#define H_  16
#define QR_ 512
#define KVR_ 512
#define DR_ 64
#define DV_ 128
#define DQK_ 192   // DV + DR
#define NDWN 1088  // QR + KVR + DR
#define NQU  3072  // H*DV + H*DR

typedef __nv_bfloat16 bf16;

// ---------------- scratch (device globals) ----------------
__device__ float g_wd [NDWN * E_];
__device__ float g_wu [NQU * QR_];
__device__ float g_down[S_ * NDWN];
__device__ float g_qu [S_ * NQU];
__device__ float g_kv [S_ * (H_*2*DV_)];
__device__ bf16 g_wo_h[E_*H_*DV_], g_wo_l[E_*H_*DV_];
__device__ bf16 g_q[(size_t)H_ * S_ * DQK_];
__device__ bf16 g_k[(size_t)H_ * S_ * DQK_];
__device__ bf16 g_vT[(size_t)H_ * DV_ * S_];
__device__ bf16 g_logits[(size_t)H_ * S_ * S_];
__device__ bf16 g_probs [(size_t)H_ * S_ * S_];
__device__ bf16 g_attn_bf[(size_t)S_ * H_ * DV_];

// ---------------- helpers ----------------
__device__ __forceinline__ uint32_t f2tf32(float x) {
    uint32_t r;
    asm("cvt.rna.tf32.f32 %0, %1;" : "=r"(r) : "f"(x));
    return r;
}

#define MMA_TF32(c, a, b) \
    asm volatile( \
        "mma.sync.aligned.m16n8k8.row.col.f32.tf32.tf32.f32 " \
        "{%0,%1,%2,%3}, {%4,%5,%6,%7}, {%8,%9}, {%0,%1,%2,%3};" \
        : "+f"((c)[0]), "+f"((c)[1]), "+f"((c)[2]), "+f"((c)[3]) \
        : "r"((a)[0]), "r"((a)[1]), "r"((a)[2]), "r"((a)[3]), \
          "r"((b)[0]), "r"((b)[1]))

#define MMA_BF16(c, a, b) \
    asm volatile( \
        "mma.sync.aligned.m16n8k16.row.col.f32.bf16.bf16.f32 " \
        "{%0,%1,%2,%3}, {%4,%5,%6,%7}, {%8,%9}, {%0,%1,%2,%3};" \
        : "+f"((c)[0]), "+f"((c)[1]), "+f"((c)[2]), "+f"((c)[3]) \
        : "r"((a)[0]), "r"((a)[1]), "r"((a)[2]), "r"((a)[3]), \
          "r"((b)[0]), "r"((b)[1]))

#define CP16(dst, src, nbytes) \
    asm volatile("cp.async.cg.shared.global [%0], [%1], 16, %2;" \
                 :: "r"(dst), "l"(src), "r"(nbytes))
#define CP_COMMIT()  asm volatile("cp.async.commit_group;")
#define CP_WAIT0()   asm volatile("cp.async.wait_group 0;")
#define CP_WAIT1()   asm volatile("cp.async.wait_group 1;")

__device__ __forceinline__ __nv_bfloat162 f2bf2(float a, float b) {
    return __nv_bfloat162(__float2bfloat16(a), __float2bfloat16(b));
}

__global__ void split_bf_k(const float* __restrict__ src, bf16* __restrict__ hi,
                           bf16* __restrict__ lo, long n)
{
    long i = (long)blockIdx.x * blockDim.x + threadIdx.x;
    long stride = (long)gridDim.x * blockDim.x;
    for (; i < n; i += stride) {
        float v = src[i];
        bf16 h = __float2bfloat16(v);
        hi[i] = h;
        lo[i] = __float2bfloat16(v - __bfloat162float(h));
    }
}

// ============================================================================
// 3xTF32 GEMM, BMv in {64,128}, 3-stage cp.async pipeline (wait_group 1).
// ============================================================================
#define FBN 128
#define FBK 16
#define FPAD 20

template <int BMv>
__global__ __launch_bounds__(256)
void tf32_gemm(const float* __restrict__ A, const float* __restrict__ B,
               float* __restrict__ C, int M, int N, int K,
               long lda, long ldb, long ldc)
{
    constexpr int MT = 2;
    constexpr int NT = (BMv == 128) ? 8 : 4;
    constexpr int ACH = BMv * 4 / 256;
    constexpr int ASZ = BMv * FPAD;
    constexpr int BSZ = FBN * FPAD;

    extern __shared__ float dsm[];
    float* sAbuf = dsm;
    float* sBbuf = dsm + 3 * ASZ;

    const int m0 = blockIdx.y * BMv;
    const int n0 = blockIdx.x * FBN;
    const int tid = threadIdx.x;
    const int warp = tid >> 5;
    const int lane = tid & 31;
    const int gid = lane >> 2;
    const int tig = lane & 3;
    const int wm = (BMv == 128) ? (warp >> 1) * 32 : (warp & 1) * 32;
    const int wn = (BMv == 128) ? (warp & 1) * 64  : (warp >> 1) * 32;

    const float* aSrc[ACH];
    uint32_t aOff[ACH];
    const float* bSrc[2];
    uint32_t bOff[2];
    int bPred[2];
    const uint32_t saBase = (uint32_t)__cvta_generic_to_shared(sAbuf);
    const uint32_t sbBase = (uint32_t)__cvta_generic_to_shared(sBbuf);
#pragma unroll
    for (int it = 0; it < ACH; it++) {
        int idx = tid + it * 256;
        int row = idx >> 2, ch = idx & 3;
        aSrc[it] = A + (long)(m0 + row) * lda + ch * 4;
        aOff[it] = (uint32_t)(row * FPAD + ch * 4) * 4u;
    }
#pragma unroll
    for (int it = 0; it < 2; it++) {
        int idx = tid + it * 256;
        int row = idx >> 2, ch = idx & 3;
        int nrow = n0 + row;
        bPred[it] = (nrow < N) ? 16 : 0;
        if (nrow >= N) nrow = N - 1;
        bSrc[it] = B + (long)nrow * ldb + ch * 4;
        bOff[it] = (uint32_t)(row * FPAD + ch * 4) * 4u;
    }

    float acc[MT][NT][4];
#pragma unroll
    for (int mt = 0; mt < MT; mt++)
#pragma unroll
        for (int nt = 0; nt < NT; nt++)
#pragma unroll
            for (int r = 0; r < 4; r++) acc[mt][nt][r] = 0.f;

    const int NTILES = K / FBK;

#pragma unroll
    for (int s = 0; s < 2; s++) {
        const long kk = (long)s * FBK;
#pragma unroll
        for (int it = 0; it < ACH; it++)
            CP16(saBase + s * ASZ * 4u + aOff[it], aSrc[it] + kk, 16);
#pragma unroll
        for (int it = 0; it < 2; it++)
            CP16(sbBase + s * BSZ * 4u + bOff[it], bSrc[it] + kk, bPred[it]);
        CP_COMMIT();
    }

    int cur = 0, pre = 2;
    for (int t = 0; t < NTILES; t++) {
        if (t + 1 < NTILES) CP_WAIT1(); else CP_WAIT0();
        __syncthreads();

        if (t + 2 < NTILES) {
            const long kk = (long)(t + 2) * FBK;
#pragma unroll
            for (int it = 0; it < ACH; it++)
                CP16(saBase + pre * ASZ * 4u + aOff[it], aSrc[it] + kk, 16);
#pragma unroll
            for (int it = 0; it < 2; it++)
                CP16(sbBase + pre * BSZ * 4u + bOff[it], bSrc[it] + kk, bPred[it]);
            CP_COMMIT();
        }

        const float* cA = sAbuf + cur * ASZ;
        const float* cB = sBbuf + cur * BSZ;

        uint32_t ah[2][MT][4], al[2][MT][4];
#pragma unroll
        for (int ks = 0; ks < 2; ks++)
#pragma unroll
            for (int mt = 0; mt < MT; mt++)
#pragma unroll
                for (int r = 0; r < 4; r++) {
                    int row = wm + mt * 16 + gid + (r & 1) * 8;
                    int col = ks * 8 + tig + (r >> 1) * 4;
                    float v = cA[row * FPAD + col];
                    uint32_t h = f2tf32(v);
                    ah[ks][mt][r] = h;
                    al[ks][mt][r] = f2tf32(v - __uint_as_float(h));
                }

#pragma unroll
        for (int nt = 0; nt < NT; nt++) {
            uint32_t bh[2][2], bl[2][2];
#pragma unroll
            for (int ks = 0; ks < 2; ks++)
#pragma unroll
                for (int r = 0; r < 2; r++) {
                    int n = wn + nt * 8 + gid;
                    int kq = ks * 8 + tig + r * 4;
                    float v = cB[n * FPAD + kq];
                    uint32_t h = f2tf32(v);
                    bh[ks][r] = h;
                    bl[ks][r] = f2tf32(v - __uint_as_float(h));
                }
#pragma unroll
            for (int mt = 0; mt < MT; mt++) {
                float f[4] = {0.f, 0.f, 0.f, 0.f};
#pragma unroll
                for (int ks = 0; ks < 2; ks++) {
                    MMA_TF32(f, ah[ks][mt], bh[ks]);
                    MMA_TF32(f, ah[ks][mt], bl[ks]);
                    MMA_TF32(f, al[ks][mt], bh[ks]);
                }
                float* c = acc[mt][nt];
                c[0] += f[0]; c[1] += f[1]; c[2] += f[2]; c[3] += f[3];
            }
        }

        cur = (cur == 2) ? 0 : cur + 1;
        pre = (pre == 2) ? 0 : pre + 1;
    }

#pragma unroll
    for (int mt = 0; mt < MT; mt++) {
        int row0 = m0 + wm + mt * 16 + gid;
#pragma unroll
        for (int nt = 0; nt < NT; nt++) {
            int n = n0 + wn + nt * 8 + tig * 2;
            if (n >= N) continue;
            float* c = acc[mt][nt];
            C[(long)row0 * ldc + n]         = c[0];
            C[(long)row0 * ldc + n + 1]     = c[1];
            C[(long)(row0+8) * ldc + n]     = c[2];
            C[(long)(row0+8) * ldc + n + 1] = c[3];
        }
    }
}

// ============================================================================
// Fused qu-up + kv-up (one flattened launch, BM=128 both).
// ============================================================================
__global__ __launch_bounds__(256)
void tf32_dual(const float* __restrict__ A0, const float* __restrict__ B0, float* __restrict__ C0,
               const float* __restrict__ A1, const float* __restrict__ B1, float* __restrict__ C1,
               int K, long lda, long ldb)
{
    constexpr int ASZ = 128 * FPAD;
    constexpr int BSZ = FBN * FPAD;

    extern __shared__ float dsm[];
    float* sAbuf = dsm;
    float* sBbuf = dsm + 3 * ASZ;

    const int bid = blockIdx.x;
    const float *A, *B;
    float* C;
    int m0, n0;
    long ldc;
    if (bid < 384) {
        A = A0; B = B0; C = C0; ldc = NQU;
        m0 = (bid / 24) * 128;  n0 = (bid % 24) * 128;
    } else {
        int b = bid - 384;
        A = A1; B = B1; C = C1; ldc = H_*2*DV_;
        m0 = (b / 32) * 128;  n0 = (b % 32) * 128;
    }

    const int tid = threadIdx.x;
    const int warp = tid >> 5;
    const int lane = tid & 31;
    const int gid = lane >> 2;
    const int tig = lane & 3;
    const int wm = (warp >> 1) * 32;
    const int wn = (warp & 1) * 64;

    const float* aSrc[2];
    const float* bSrc[2];
    uint32_t sOff[2];
    const uint32_t saBase = (uint32_t)__cvta_generic_to_shared(sAbuf);
    const uint32_t sbBase = (uint32_t)__cvta_generic_to_shared(sBbuf);
#pragma unroll
    for (int it = 0; it < 2; it++) {
        int idx = tid + it * 256;
        int row = idx >> 2, ch = idx & 3;
        aSrc[it] = A + (long)(m0 + row) * lda + ch * 4;
        bSrc[it] = B + (long)(n0 + row) * ldb + ch * 4;
        sOff[it] = (uint32_t)(row * FPAD + ch * 4) * 4u;
    }

    float acc[2][8][4];
#pragma unroll
    for (int mt = 0; mt < 2; mt++)
#pragma unroll
        for (int nt = 0; nt < 8; nt++)
#pragma unroll
            for (int r = 0; r < 4; r++) acc[mt][nt][r] = 0.f;

    const int NTILES = K / FBK;

#pragma unroll
    for (int s = 0; s < 2; s++) {
        const long kk = (long)s * FBK;
#pragma unroll
        for (int it = 0; it < 2; it++) {
            CP16(saBase + s * ASZ * 4u + sOff[it], aSrc[it] + kk, 16);
            CP16(sbBase + s * BSZ * 4u + sOff[it], bSrc[it] + kk, 16);
        }
        CP_COMMIT();
    }

    int cur = 0, pre = 2;
    for (int t = 0; t < NTILES; t++) {
        if (t + 1 < NTILES) CP_WAIT1(); else CP_WAIT0();
        __syncthreads();

        if (t + 2 < NTILES) {
            const long kk = (long)(t + 2) * FBK;
#pragma unroll
            for (int it = 0; it < 2; it++) {
                CP16(saBase + pre * ASZ * 4u + sOff[it], aSrc[it] + kk, 16);
                CP16(sbBase + pre * BSZ * 4u + sOff[it], bSrc[it] + kk, 16);
            }
            CP_COMMIT();
        }

        const float* cA = sAbuf + cur * ASZ;
        const float* cB = sBbuf + cur * BSZ;

        uint32_t ah[2][2][4], al[2][2][4];
#pragma unroll
        for (int ks = 0; ks < 2; ks++)
#pragma unroll
            for (int mt = 0; mt < 2; mt++)
#pragma unroll
                for (int r = 0; r < 4; r++) {
                    int row = wm + mt * 16 + gid + (r & 1) * 8;
                    int col = ks * 8 + tig + (r >> 1) * 4;
                    float v = cA[row * FPAD + col];
                    uint32_t h = f2tf32(v);
                    ah[ks][mt][r] = h;
                    al[ks][mt][r] = f2tf32(v - __uint_as_float(h));
                }

#pragma unroll
        for (int nt = 0; nt < 8; nt++) {
            uint32_t bh[2][2], bl[2][2];
#pragma unroll
            for (int ks = 0; ks < 2; ks++)
#pragma unroll
                for (int r = 0; r < 2; r++) {
                    int n = wn + nt * 8 + gid;
                    int kq = ks * 8 + tig + r * 4;
                    float v = cB[n * FPAD + kq];
                    uint32_t h = f2tf32(v);
                    bh[ks][r] = h;
                    bl[ks][r] = f2tf32(v - __uint_as_float(h));
                }
#pragma unroll
            for (int mt = 0; mt < 2; mt++) {
                float f[4] = {0.f, 0.f, 0.f, 0.f};
#pragma unroll
                for (int ks = 0; ks < 2; ks++) {
                    MMA_TF32(f, ah[ks][mt], bh[ks]);
                    MMA_TF32(f, ah[ks][mt], bl[ks]);
                    MMA_TF32(f, al[ks][mt], bh[ks]);
                }
                float* c = acc[mt][nt];
                c[0] += f[0]; c[1] += f[1]; c[2] += f[2]; c[3] += f[3];
            }
        }

        cur = (cur == 2) ? 0 : cur + 1;
        pre = (pre == 2) ? 0 : pre + 1;
    }

#pragma unroll
    for (int mt = 0; mt < 2; mt++) {
        int row0 = m0 + wm + mt * 16 + gid;
#pragma unroll
        for (int nt = 0; nt < 8; nt++) {
            int n = n0 + wn + nt * 8 + tig * 2;
            float* c = acc[mt][nt];
            C[(long)row0 * ldc + n]         = c[0];
            C[(long)row0 * ldc + n + 1]     = c[1];
            C[(long)(row0+8) * ldc + n]     = c[2];
            C[(long)(row0+8) * ldc + n + 1] = c[3];
        }
    }
}

// ============================================================================
// bf16 tensor-core GEMM, 3-stage cp.async pipeline per pass.
// ============================================================================
#define TBM 128
#define TBN 128
#define TBK 32
#define PADK 40

template <typename TC>
__global__ __launch_bounds__(256)
void bf16_gemm(const bf16* __restrict__ A0, const bf16* __restrict__ A1,
               const bf16* __restrict__ B0, const bf16* __restrict__ B1,
               TC* __restrict__ C, int npass, int M, int N, int K,
               long lda, long ldb, long ldc, long Abat, long Bbat, long Cbat)
{
    constexpr int ASZ = TBM * PADK;
    constexpr int BSZ = TBN * PADK;

    extern __shared__ bf16 dsmb[];
    bf16* sAbuf = dsmb;
    bf16* sBbuf = dsmb + 3 * ASZ;

    const long zo = blockIdx.z;
    C += zo * Cbat;

    const int m0 = blockIdx.y * TBM;
    const int n0 = blockIdx.x * TBN;
    const int tid = threadIdx.x;
    const int warp = tid >> 5;
    const int lane = tid & 31;
    const int gid = lane >> 2;
    const int tig = lane & 3;
    const int wm = (warp >> 1) * 32;
    const int wn = (warp & 1) * 64;

    const uint32_t saBase = (uint32_t)__cvta_generic_to_shared(sAbuf);
    const uint32_t sbBase = (uint32_t)__cvta_generic_to_shared(sBbuf);

    float acc[2][8][4];
#pragma unroll
    for (int mt = 0; mt < 2; mt++)
#pragma unroll
        for (int nt = 0; nt < 8; nt++)
#pragma unroll
            for (int r = 0; r < 4; r++) acc[mt][nt][r] = 0.f;

    const int NTILES = K / TBK;

    for (int p = 0; p < npass; p++) {
        const bf16* A = (p ? A1 : A0) + zo * Abat;
        const bf16* B = (p ? B1 : B0) + zo * Bbat;

        const bf16* aSrc[2];
        const bf16* bSrc[2];
        uint32_t aOff[2], bOff[2];
        int bPred[2];
#pragma unroll
        for (int it = 0; it < 2; it++) {
            int idx = tid + it * 256;
            int row = idx >> 2, ch = idx & 3;
            aSrc[it] = A + (long)(m0 + row) * lda + ch * 8;
            int nrow = n0 + row;
            bPred[it] = (nrow < N) ? 16 : 0;
            if (nrow >= N) nrow = N - 1;
            bSrc[it] = B + (long)nrow * ldb + ch * 8;
            aOff[it] = (uint32_t)(row * PADK + ch * 8) * 2u;
            bOff[it] = (uint32_t)(row * PADK + ch * 8) * 2u;
        }

        if (p) __syncthreads();

#pragma unroll
        for (int s = 0; s < 2; s++) {
            const long kk = (long)s * TBK;
#pragma unroll
            for (int it = 0; it < 2; it++) {
                CP16(saBase + s * ASZ * 2u + aOff[it], aSrc[it] + kk, 16);
                CP16(sbBase + s * BSZ * 2u + bOff[it], bSrc[it] + kk, bPred[it]);
            }
            CP_COMMIT();
        }

        int cur = 0, pre = 2;
        for (int t = 0; t < NTILES; t++) {
            if (t + 1 < NTILES) CP_WAIT1(); else CP_WAIT0();
            __syncthreads();

            if (t + 2 < NTILES) {
                const long kk = (long)(t + 2) * TBK;
#pragma unroll
                for (int it = 0; it < 2; it++) {
                    CP16(saBase + pre * ASZ * 2u + aOff[it], aSrc[it] + kk, 16);
                    CP16(sbBase + pre * BSZ * 2u + bOff[it], bSrc[it] + kk, bPred[it]);
                }
                CP_COMMIT();
            }

            const bf16* cA = sAbuf + cur * ASZ;
            const bf16* cB = sBbuf + cur * BSZ;

            uint32_t a[2][2][4];
#pragma unroll
            for (int ks = 0; ks < 2; ks++)
#pragma unroll
                for (int mt = 0; mt < 2; mt++)
#pragma unroll
                    for (int r = 0; r < 4; r++) {
                        int row = wm + mt * 16 + gid + (r & 1) * 8;
                        int col = ks * 16 + tig * 2 + (r >> 1) * 8;
                        a[ks][mt][r] = *(const uint32_t*)&cA[row * PADK + col];
                    }

#pragma unroll
            for (int nt = 0; nt < 8; nt++) {
                uint32_t b[2][2];
#pragma unroll
                for (int ks = 0; ks < 2; ks++)
#pragma unroll
                    for (int r = 0; r < 2; r++) {
                        int n  = wn + nt * 8 + gid;
                        int kq = ks * 16 + tig * 2 + r * 8;
                        b[ks][r] = *(const uint32_t*)&cB[n * PADK + kq];
                    }
#pragma unroll
                for (int mt = 0; mt < 2; mt++) {
                    float f[4] = {0.f, 0.f, 0.f, 0.f};
                    MMA_BF16(f, a[0][mt], b[0]);
                    MMA_BF16(f, a[1][mt], b[1]);
                    float* c = acc[mt][nt];
                    c[0] += f[0]; c[1] += f[1]; c[2] += f[2]; c[3] += f[3];
                }
            }

            cur = (cur == 2) ? 0 : cur + 1;
            pre = (pre == 2) ? 0 : pre + 1;
        }
    }

#pragma unroll
    for (int mt = 0; mt < 2; mt++) {
        int row0 = m0 + wm + mt * 16 + gid;
#pragma unroll
        for (int nt = 0; nt < 8; nt++) {
            int n = n0 + wn + nt * 8 + tig * 2;
            if (n >= N) continue;
            float* c = acc[mt][nt];
            if (sizeof(TC) == 4) {
                float* Cf = (float*)C;
                Cf[(long)row0 * ldc + n]         = c[0];
                Cf[(long)row0 * ldc + n + 1]     = c[1];
                Cf[(long)(row0+8) * ldc + n]     = c[2];
                Cf[(long)(row0+8) * ldc + n + 1] = c[3];
            } else {
                bf16* Cb = (bf16*)C;
                *(__nv_bfloat162*)&Cb[(long)row0 * ldc + n] =
                    __nv_bfloat162(__float2bfloat16(c[0]), __float2bfloat16(c[1]));
                *(__nv_bfloat162*)&Cb[(long)(row0+8) * ldc + n] =
                    __nv_bfloat162(__float2bfloat16(c[2]), __float2bfloat16(c[3]));
            }
        }
    }
}

// ============================================================================
// out GEMM: C = A @ (B0 + B1)^T, shared-A dual-B single K-sweep.
// ============================================================================
__global__ __launch_bounds__(256)
void outb_gemm(const bf16* __restrict__ A, const bf16* __restrict__ B0,
               const bf16* __restrict__ B1, float* __restrict__ C,
               int M, int N, int K, long lda, long ldb, long ldc)
{
    constexpr int ASZ = TBM * PADK;
    constexpr int BSZ = TBN * PADK;

    extern __shared__ bf16 dsmb[];
    bf16* sAbuf  = dsmb;
    bf16* sB0buf = dsmb + 3 * ASZ;
    bf16* sB1buf = dsmb + 3 * ASZ + 3 * BSZ;

    const int m0 = blockIdx.y * TBM;
    const int n0 = blockIdx.x * TBN;
    const int tid = threadIdx.x;
    const int warp = tid >> 5;
    const int lane = tid & 31;
    const int gid = lane >> 2;
    const int tig = lane & 3;
    const int wm = (warp >> 1) * 32;
    const int wn = (warp & 1) * 64;

    const uint32_t saBase  = (uint32_t)__cvta_generic_to_shared(sAbuf);
    const uint32_t sb0Base = (uint32_t)__cvta_generic_to_shared(sB0buf);
    const uint32_t sb1Base = (uint32_t)__cvta_generic_to_shared(sB1buf);

    const bf16 *aSrc[2], *b0Src[2], *b1Src[2];
    uint32_t sOff[2];
#pragma unroll
    for (int it = 0; it < 2; it++) {
        int idx = tid + it * 256;
        int row = idx >> 2, ch = idx & 3;
        aSrc[it]  = A  + (long)(m0 + row) * lda + ch * 8;
        b0Src[it] = B0 + (long)(n0 + row) * ldb + ch * 8;
        b1Src[it] = B1 + (long)(n0 + row) * ldb + ch * 8;
        sOff[it] = (uint32_t)(row * PADK + ch * 8) * 2u;
    }

    float acc[2][8][4];
#pragma unroll
    for (int mt = 0; mt < 2; mt++)
#pragma unroll
        for (int nt = 0; nt < 8; nt++)
#pragma unroll
            for (int r = 0; r < 4; r++) acc[mt][nt][r] = 0.f;

    const int NTILES = K / TBK;

#pragma unroll
    for (int s = 0; s < 2; s++) {
        const long kk = (long)s * TBK;
#pragma unroll
        for (int it = 0; it < 2; it++) {
            CP16(saBase  + s * ASZ * 2u + sOff[it], aSrc[it]  + kk, 16);
            CP16(sb0Base + s * BSZ * 2u + sOff[it], b0Src[it] + kk, 16);
            CP16(sb1Base + s * BSZ * 2u + sOff[it], b1Src[it] + kk, 16);
        }
        CP_COMMIT();
    }

    int cur = 0, pre = 2;
    for (int t = 0; t < NTILES; t++) {
        if (t + 1 < NTILES) CP_WAIT1(); else CP_WAIT0();
        __syncthreads();

        if (t + 2 < NTILES) {
            const long kk = (long)(t + 2) * TBK;
#pragma unroll
            for (int it = 0; it < 2; it++) {
                CP16(saBase  + pre * ASZ * 2u + sOff[it], aSrc[it]  + kk, 16);
                CP16(sb0Base + pre * BSZ * 2u + sOff[it], b0Src[it] + kk, 16);
                CP16(sb1Base + pre * BSZ * 2u + sOff[it], b1Src[it] + kk, 16);
            }
            CP_COMMIT();
        }

        const bf16* cA  = sAbuf  + cur * ASZ;
        const bf16* cB0 = sB0buf + cur * BSZ;
        const bf16* cB1 = sB1buf + cur * BSZ;

        uint32_t a[2][2][4];
#pragma unroll
        for (int ks = 0; ks < 2; ks++)
#pragma unroll
            for (int mt = 0; mt < 2; mt++)
#pragma unroll
                for (int r = 0; r < 4; r++) {
                    int row = wm + mt * 16 + gid + (r & 1) * 8;
                    int col = ks * 16 + tig * 2 + (r >> 1) * 8;
                    a[ks][mt][r] = *(const uint32_t*)&cA[row * PADK + col];
                }

#pragma unroll
        for (int nt = 0; nt < 8; nt++) {
            uint32_t b0[2][2], b1[2][2];
#pragma unroll
            for (int ks = 0; ks < 2; ks++)
#pragma unroll
                for (int r = 0; r < 2; r++) {
                    int n  = wn + nt * 8 + gid;
                    int kq = ks * 16 + tig * 2 + r * 8;
                    b0[ks][r] = *(const uint32_t*)&cB0[n * PADK + kq];
                    b1[ks][r] = *(const uint32_t*)&cB1[n * PADK + kq];
                }
#pragma unroll
            for (int mt = 0; mt < 2; mt++) {
                float* c = acc[mt][nt];
                float f[4] = {0.f, 0.f, 0.f, 0.f};
                MMA_BF16(f, a[0][mt], b0[0]);
                MMA_BF16(f, a[1][mt], b0[1]);
                c[0] += f[0]; c[1] += f[1]; c[2] += f[2]; c[3] += f[3];
                float g[4] = {0.f, 0.f, 0.f, 0.f};
                MMA_BF16(g, a[0][mt], b1[0]);
                MMA_BF16(g, a[1][mt], b1[1]);
                c[0] += g[0]; c[1] += g[1]; c[2] += g[2]; c[3] += g[3];
            }
        }

        cur = (cur == 2) ? 0 : cur + 1;
        pre = (pre == 2) ? 0 : pre + 1;
    }

#pragma unroll
    for (int mt = 0; mt < 2; mt++) {
        int row0 = m0 + wm + mt * 16 + gid;
#pragma unroll
        for (int nt = 0; nt < 8; nt++) {
            int n = n0 + wn + nt * 8 + tig * 2;
            float* c = acc[mt][nt];
            C[(long)row0 * ldc + n]         = c[0];
            C[(long)row0 * ldc + n + 1]     = c[1];
            C[(long)(row0+8) * ldc + n]     = c[2];
            C[(long)(row0+8) * ldc + n + 1] = c[3];
        }
    }
}

// ---------------- pack q/k + RoPE (float4 loads, uint2 stores) --------------
__global__ void pack_k(const float* __restrict__ qu, const float* __restrict__ kvf,
                       const float* __restrict__ dwn,
                       bf16* __restrict__ q, bf16* __restrict__ k)
{
    const int s = blockIdx.x;
    const int tid = threadIdx.x;  // 256

    __shared__ float ssin[32], scos[32];
    if (tid < 32) {
        double invf_d = pow(10000.0, -((double)(2 * tid)) / 64.0);
        float invf = (float)invf_d;
        float ang = (float)s * invf;
        double a = (double)ang;
        ssin[tid] = (float)sin(a);
        scos[tid] = (float)cos(a);
    }
    __syncthreads();

    // content: H_*DV_/4 = 512 quad-tasks, 2 iters of 256 threads
#pragma unroll
    for (int it = 0; it < 2; it++) {
        int idx = tid + it * 256;              // 0..511
        int h = idx >> 5, qp = idx & 31;       // 32 quads per head
        int d = qp * 4;
        float4 a = *(const float4*)&qu[(long)s * NQU + h * DV_ + d];
        __nv_bfloat162 a0 = f2bf2(a.x, a.y), a1 = f2bf2(a.z, a.w);
        uint2 pa; pa.x = *(uint32_t*)&a0; pa.y = *(uint32_t*)&a1;
        *(uint2*)&q[((long)h * S_ + s) * DQK_ + d] = pa;
        float4 b = *(const float4*)&kvf[(long)s * (H_*2*DV_) + h * DV_ + d];
        __nv_bfloat162 b0 = f2bf2(b.x, b.y), b1 = f2bf2(b.z, b.w);
        uint2 pb; pb.x = *(uint32_t*)&b0; pb.y = *(uint32_t*)&b1;
        *(uint2*)&k[((long)h * S_ + s) * DQK_ + d] = pb;
    }

    // q rope: 256 pair-tasks
    {
        int h = tid >> 4, jp = tid & 15;
        int j = jp * 2;
        const float* base = &qu[(long)s * NQU + 2048 + h * DR_];
        float x1a = base[j],      x1b = base[j + 1];
        float x2a = base[32 + j], x2b = base[33 + j];
        float sna = ssin[j], csa = scos[j];
        float snb = ssin[j + 1], csb = scos[j + 1];
        bf16* qd = &q[((long)h * S_ + s) * DQK_ + DV_];
        *(__nv_bfloat162*)&qd[j]      = f2bf2(x1a * csa - x2a * sna, x1b * csb - x2b * snb);
        *(__nv_bfloat162*)&qd[32 + j] = f2bf2(x2a * csa + x1a * sna, x2b * csb + x1b * snb);
    }

    // k rope (shared across heads)
    if (tid < 16) {
        int j = tid * 2;
        float x1a = dwn[(long)s * NDWN + 1024 + j];
        float x1b = dwn[(long)s * NDWN + 1024 + j + 1];
        float x2a = dwn[(long)s * NDWN + 1024 + 32 + j];
        float x2b = dwn[(long)s * NDWN + 1024 + 33 + j];
        float sna = ssin[j], csa = scos[j];
        float snb = ssin[j + 1], csb = scos[j + 1];
        __nv_bfloat162 r1 = f2bf2(x1a * csa - x2a * sna, x1b * csb - x2b * snb);
        __nv_bfloat162 r2 = f2bf2(x2a * csa + x1a * sna, x2b * csb + x1b * snb);
#pragma unroll
        for (int h = 0; h < H_; h++) {
            bf16* kd = &k[((long)h * S_ + s) * DQK_ + DV_];
            *(__nv_bfloat162*)&kd[j]      = r1;
            *(__nv_bfloat162*)&kd[32 + j] = r2;
        }
    }
}

// ---------------- vT[h][d][s] = bf16( kvf[s][H*DV + h*DV + d] ) ------------
__global__ void transpose_v(const float* __restrict__ kvf, bf16* __restrict__ vT)
{
    __shared__ bf16 t[32][33];
    const int h = blockIdx.z;
    const int s0 = blockIdx.x * 32;
    const int d0 = blockIdx.y * 32;
    const int tx = threadIdx.x, ty = threadIdx.y;  // (32, 8)
#pragma unroll
    for (int j = 0; j < 32; j += 8) {
        float val = kvf[(long)(s0 + ty + j) * (H_*2*DV_) + H_*DV_ + h * DV_ + d0 + tx];
        t[ty + j][tx] = __float2bfloat16(val);
    }
    __syncthreads();
#pragma unroll
    for (int j = 0; j < 32; j += 8)
        vT[((long)h * DV_ + d0 + ty + j) * S_ + s0 + tx] = t[tx][ty + j];
}

// ---------------- softmax: warp-shuffle reductions (5 barriers -> fast) ----
__global__ void softmax_k(const bf16* __restrict__ L, bf16* __restrict__ P, float scale)
{
    const int s = blockIdx.x;
    const int h = blockIdx.y;
    const bf16* row = L + ((long)h * S_ + s) * S_;
    bf16* prow = P + ((long)h * S_ + s) * S_;
    const int tid = threadIdx.x;   // 256 threads, 8 contiguous elems each
    const int warp = tid >> 5, lane = tid & 31;

    uint4 pkt = ((const uint4*)row)[tid];
    bf16 e[8];
    *(uint4*)e = pkt;

    float v[8];
    float mx = -1e30f;
#pragma unroll
    for (int i = 0; i < 8; i++) {
        v[i] = __bfloat162float(e[i]) * scale;
        mx = fmaxf(mx, v[i]);
    }
    // warp-level max
#pragma unroll
    for (int o = 16; o > 0; o >>= 1)
        mx = fmaxf(mx, __shfl_xor_sync(0xffffffffu, mx, o));

    __shared__ float wred[8];
    if (lane == 0) wred[warp] = mx;
    __syncthreads();
    if (warp == 0) {
        float m = (lane < 8) ? wred[lane] : -1e30f;
#pragma unroll
        for (int o = 4; o > 0; o >>= 1)
            m = fmaxf(m, __shfl_xor_sync(0xffffffffu, m, o));
        if (lane == 0) wred[0] = m;
    }
    __syncthreads();
    mx = wred[0];

    float sum = 0.f;
#pragma unroll
    for (int i = 0; i < 8; i++) {
        v[i] = __expf(v[i] - mx);
        sum += v[i];
    }
#pragma unroll
    for (int o = 16; o > 0; o >>= 1)
        sum += __shfl_xor_sync(0xffffffffu, sum, o);

    __syncthreads();   // protect wred reuse (all reads of wred[0] done)
    if (lane == 0) wred[warp] = sum;
    __syncthreads();
    if (warp == 0) {
        float t = (lane < 8) ? wred[lane] : 0.f;
#pragma unroll
        for (int o = 4; o > 0; o >>= 1)
            t += __shfl_xor_sync(0xffffffffu, t, o);
        if (lane == 0) wred[0] = t;
    }
    __syncthreads();
    const float inv_tot = 1.0f / wred[0];

    bf16 o[8];
#pragma unroll
    for (int i = 0; i < 8; i++) o[i] = __float2bfloat16(v[i] * inv_tot);
    ((uint4*)prow)[tid] = *(const uint4*)o;
}

// ---------------- orchestration ----------------
extern "C" void kernel_launch(void* const* d_in, const int* in_sizes, int n_in,
                              void* d_out, int out_size)
{
    (void)in_sizes; (void)n_in; (void)out_size;
    const float* x       = (const float*)d_in[0];
    const float* wq_down = (const float*)d_in[1];
    const float* wq_up   = (const float*)d_in[2];
    const float* wq_rope = (const float*)d_in[3];
    const float* wkv_down= (const float*)d_in[4];
    const float* wkv_up  = (const float*)d_in[5];
    const float* wk_rope = (const float*)d_in[6];
    const float* wo      = (const float*)d_in[7];
    float* out = (float*)d_out;

    float *wd, *wu, *dwn, *qu, *kvf;
    cudaGetSymbolAddress((void**)&wd,  g_wd);
    cudaGetSymbolAddress((void**)&wu,  g_wu);
    cudaGetSymbolAddress((void**)&dwn, g_down);
    cudaGetSymbolAddress((void**)&qu,  g_qu);
    cudaGetSymbolAddress((void**)&kvf, g_kv);

    bf16 *q, *k, *vT, *logits, *probs, *attn_bf, *wo_h, *wo_l;
    cudaGetSymbolAddress((void**)&q, g_q);
    cudaGetSymbolAddress((void**)&k, g_k);
    cudaGetSymbolAddress((void**)&vT, g_vT);
    cudaGetSymbolAddress((void**)&logits, g_logits);
    cudaGetSymbolAddress((void**)&probs, g_probs);
    cudaGetSymbolAddress((void**)&attn_bf, g_attn_bf);
    cudaGetSymbolAddress((void**)&wo_h, g_wo_h);
    cudaGetSymbolAddress((void**)&wo_l, g_wo_l);

    // dynamic smem sizes (3-stage)
    const int SM64  = 3 * (64 * FPAD + FBN * FPAD) * 4;        // 46080
    const int SM128 = 3 * (128 * FPAD + FBN * FPAD) * 4;       // 61440
    const int SMBF  = 3 * (TBM * PADK + TBN * PADK) * 2;       // 61440
    const int SMOUT = 3 * (TBM * PADK + 2 * TBN * PADK) * 2;   // 92160
    cudaFuncSetAttribute(tf32_gemm<64>,  cudaFuncAttributeMaxDynamicSharedMemorySize, SM64);
    cudaFuncSetAttribute(tf32_dual, cudaFuncAttributeMaxDynamicSharedMemorySize, SM128);
    cudaFuncSetAttribute(bf16_gemm<bf16>,  cudaFuncAttributeMaxDynamicSharedMemorySize, SMBF);
    cudaFuncSetAttribute(bf16_gemm<float>, cudaFuncAttributeMaxDynamicSharedMemorySize, SMBF);
    cudaFuncSetAttribute(outb_gemm, cudaFuncAttributeMaxDynamicSharedMemorySize, SMOUT);

    dim3 blk(256);
    auto bgrid = [](int M, int N, int batch) {
        return dim3((N + TBN - 1) / TBN, (M + TBM - 1) / TBM, batch);
    };

    // 0) concat weights (D2D) + wo bf16 split
    cudaMemcpyAsync(wd,                 wq_down,  (size_t)QR_ * E_ * 4, cudaMemcpyDeviceToDevice);
    cudaMemcpyAsync(wd + (size_t)QR_*E_, wkv_down, (size_t)KVR_ * E_ * 4, cudaMemcpyDeviceToDevice);
    cudaMemcpyAsync(wd + (size_t)(QR_+KVR_)*E_, wk_rope, (size_t)DR_ * E_ * 4, cudaMemcpyDeviceToDevice);
    cudaMemcpyAsync(wu,                  wq_up,   (size_t)H_*DV_ * QR_ * 4, cudaMemcpyDeviceToDevice);
    cudaMemcpyAsync(wu + (size_t)H_*DV_*QR_, wq_rope, (size_t)H_*DR_ * QR_ * 4, cudaMemcpyDeviceToDevice);
    split_bf_k<<<592, 256>>>(wo, wo_h, wo_l, (long)E_*H_*DV_);

    // 1) fused down projection: [cq|ckv|kr] = x @ wd^T  (BM=64: 288 CTAs)
    tf32_gemm<64><<<dim3((NDWN + FBN - 1) / FBN, S_ / 64, 1), blk, SM64>>>(
        x, wd, dwn, S_, NDWN, E_, E_, E_, NDWN);

    // 2) fused qu-up + kv-up in ONE launch (896 CTAs)
    tf32_dual<<<896, blk, SM128>>>(
        dwn, wu, qu,
        dwn + QR_, wkv_up, kvf,
        QR_, NDWN, QR_);

    // 3) pack q/k + rope ; transpose v directly from kvf
    pack_k<<<S_, 256>>>(qu, kvf, dwn, q, k);
    {
        dim3 tg(S_/32, DV_/32, H_);
        dim3 tb(32, 8);
        transpose_v<<<tg, tb>>>(kvf, vT);
    }

    // 4) logits[h] = bf16( q[h] @ k[h]^T )
    bf16_gemm<bf16><<<bgrid(S_, S_, H_), blk, SMBF>>>(
        q, q, k, k, logits, 1, S_, S_, DQK_, DQK_, DQK_, S_,
        (long)S_*DQK_, (long)S_*DQK_, (long)S_*S_);

    // 5) softmax
    {
        dim3 g(S_, H_);
        softmax_k<<<g, 256>>>(logits, probs, 1.0f / sqrtf((float)(DV_ + DR_)));
    }

    // 6) attn[h] = bf16( probs[h] @ v[h] ), stored bf16 interleaved [s][h*DV]
    bf16_gemm<bf16><<<bgrid(S_, DV_, H_), blk, SMBF>>>(
        probs, probs, vT, vT, attn_bf, 1, S_, DV_, S_, S_, S_, (long)H_*DV_,
        (long)S_*S_, (long)DV_*S_, DV_);

    // 7) out = attn @ (wo_h + wo_l)^T : shared-A dual-B single sweep
    outb_gemm<<<bgrid(S_, E_, 1), blk, SMOUT>>>(
        attn_bf, wo_h, wo_l, out, S_, E_, H_*DV_, H_*DV_, H_*DV_, E_);
}